// round 7
// baseline (speedup 1.0000x reference)
#include <cuda_runtime.h>
#include <cstdint>

#define T_ 32768
#define NTAGS 50
#define LCHUNK 32
#define WARMUP 48
#define NCHUNK (T_ / LCHUNK)

typedef unsigned long long u64;

// Scratch (static device globals; no runtime allocation)
__device__ float g_buf[(size_t)T_ * 256];   // gate projections [t][dir*128 + l*4 + p]
__device__ float h0_buf[(size_t)T_ * 64];   // layer0 output [t][dir*32 + lane]
__device__ float h1_buf[(size_t)T_ * 64];   // layer1 output
__device__ float Wt0[784 * 256];            // k-major permuted Wih0 (zero-padded 774->784)
__device__ float Wt1[64 * 256];             // k-major permuted Wih1

__device__ __forceinline__ float sigf(float x) {
    return __fdividef(1.0f, 1.0f + __expf(-x));
}
__device__ __forceinline__ float tanhfast(float x) {
    x = fminf(fmaxf(x, -15.0f), 15.0f);
    float e = __expf(2.0f * x);
    return __fdividef(e - 1.0f, e + 1.0f);
}

// packed f32x2 helpers (pairs carried in u64)
__device__ __forceinline__ u64 pack2(float x) {
    u64 d; asm("mov.b64 %0, {%1, %1};" : "=l"(d) : "f"(x)); return d;
}
__device__ __forceinline__ u64 pack2f(float lo, float hi) {
    u64 d; asm("mov.b64 %0, {%1, %2};" : "=l"(d) : "f"(lo), "f"(hi)); return d;
}
__device__ __forceinline__ void fma2(u64& acc, u64 a, u64 b) {
    asm("fma.rn.f32x2 %0, %1, %2, %0;" : "+l"(acc) : "l"(a), "l"(b));
}
__device__ __forceinline__ u64 add2(u64 a, u64 b) {
    u64 d; asm("add.rn.f32x2 %0, %1, %2;" : "=l"(d) : "l"(a), "l"(b)); return d;
}
__device__ __forceinline__ void unpack2(u64 d, float& lo, float& hi) {
    asm("mov.b64 {%0, %1}, %2;" : "=f"(lo), "=f"(hi) : "l"(d));
}

// ---------------------------------------------------------------------------
// Prep: transpose weights to k-major with the n-permutation baked in.
// n = (dir<<7)|(l<<2)|p  ->  weight row = dir*128 + p*32 + l
// ---------------------------------------------------------------------------
__global__ void prep_kernel(const float* __restrict__ Wih0, const float* __restrict__ Wih1)
{
    const int k = blockIdx.x;       // 0..783
    const int n = threadIdx.x;      // 0..255
    const int dir = n >> 7, l = (n & 127) >> 2, p = n & 3;
    const int row = dir * 128 + p * 32 + l;
    Wt0[k * 256 + n] = (k < 774) ? Wih0[(size_t)row * 774 + k] : 0.0f;
    if (k < 64) Wt1[k * 256 + n] = Wih1[(size_t)row * 64 + k];
}

// 16B-granular smem swizzle: kills 128B-aliasing bank conflicts
__device__ __forceinline__ uint32_t swz(uint32_t off) { return off ^ ((off >> 3) & 0x10); }

// ---------------------------------------------------------------------------
// Gate GEMM: 128m x 128n x 16k tiles, 256 threads, 8x8 per thread.
// A stored in smem as DUPLICATED (a,a) u64 pairs with permuted m so the
// 8-m fragment loads are 4 conflict-free ulonglong2; B rows XOR-swizzled.
// Inner loop: 6 LDS.128 + 32 FFMA2, zero MOV overhead.
// perm(m) = (m & ~31) | (((m>>1)&3)<<3) | (((m>>3)&3)<<1) | (m&1)  (involution)
// Fragment slot i = wm*32 + lm*2 + jj*8 + b holds global row perm(i)
//   = wm*32 + lm*8 + jj*2 + b  = wm*32 + lm*8 + mp  (mp = jj*2+b).
// ---------------------------------------------------------------------------
template<int CONCAT>
__global__ __launch_bounds__(256)
void gemm_gates(const float* __restrict__ A,
                const float* __restrict__ dp_table,
                const int* __restrict__ dp_in)
{
    constexpr int K = CONCAT ? 774 : 64;
    constexpr int NTILES = (K + 15) / 16;     // 49 or 4
    constexpr int AROW = CONCAT ? 770 : 64;

    __shared__ __align__(16) u64   Asd[2][16][128];   // dup pairs, permuted m (rows 1KB)
    __shared__ __align__(16) float Bs[2][16][128];    // swizzled rows (512B)

    const int tid = threadIdx.x;
    const int t0 = blockIdx.x * 128;
    const int n0 = blockIdx.y * 128;

    const int wid = tid >> 5, lane = tid & 31;
    const int wm = wid & 3, wn = wid >> 2;     // 4x2 warp grid
    const int lm = lane & 3, ln = lane >> 2;   // 4x8 lane grid

    // fragment byte offsets (row-relative)
    const uint32_t aoff = (uint32_t)(wm * 32 + lm * 2) * 8;   // + jj*64
    const uint32_t boff = (uint32_t)(wn * 256 + ln * 32);
    const uint32_t bo0 = swz(boff), bo1 = swz(boff + 16);

    // loader roles
    const int m_a = tid >> 1;         // A row 0..127
    const int ha  = (tid & 1) * 8;    // A k offset 0 or 8
    const int pm  = (m_a & ~31) | (((m_a >> 1) & 3) << 3) | (((m_a >> 3) & 3) << 1) | (m_a & 1);
    const int kb  = tid >> 4;         // B k row 0..15
    const uint32_t nbo = (uint32_t)(tid & 15) * 32;  // B byte offset in row
    const uint32_t nb0 = swz(nbo), nb1 = swz(nbo + 16);

    const float* __restrict__ Wt = CONCAT ? Wt0 : Wt1;
    const float* __restrict__ Asrc = CONCAT ? A : h0_buf;
    const float* __restrict__ Wsrc = Wt + (size_t)kb * 256 + n0 + (tid & 15) * 8;

    u64 acc[8][4];
#pragma unroll
    for (int m = 0; m < 8; m++)
#pragma unroll
        for (int j = 0; j < 4; j++) acc[m][j] = 0ull;

    float ar[8], br[8];

    auto loadA = [&](int k0) {
        if (!CONCAT || k0 < 768) {
            const float* ap = Asrc + (size_t)(t0 + m_a) * AROW + k0 + ha;
#pragma unroll
            for (int j = 0; j < 4; j++) {      // rows only 8B-aligned
                float2 v = *(const float2*)(ap + 2 * j);
                ar[2 * j] = v.x; ar[2 * j + 1] = v.y;
            }
        } else {
            int dpo = dp_in[t0 + m_a] * 4;
#pragma unroll
            for (int j = 0; j < 8; j++) {
                int k = k0 + ha + j;
                float v = 0.0f;
                if (k < 770)      v = Asrc[(size_t)(t0 + m_a) * 770 + k];
                else if (k < 774) v = dp_table[dpo + (k - 770)];
                ar[j] = v;
            }
        }
    };
    auto loadB = [&](int k0) {
        const float* bpp = Wsrc + (size_t)k0 * 256;
        float4 v0 = *(const float4*)bpp;
        float4 v1 = *(const float4*)(bpp + 4);
        br[0] = v0.x; br[1] = v0.y; br[2] = v0.z; br[3] = v0.w;
        br[4] = v1.x; br[5] = v1.y; br[6] = v1.z; br[7] = v1.w;
    };
    auto stage = [&](int buf) {
#pragma unroll
        for (int j = 0; j < 8; j++) Asd[buf][ha + j][pm] = pack2(ar[j]);
        char* row = (char*)&Bs[buf][kb][0];
        *(float4*)(row + nb0) = make_float4(br[0], br[1], br[2], br[3]);
        *(float4*)(row + nb1) = make_float4(br[4], br[5], br[6], br[7]);
    };

    loadA(0); loadB(0); stage(0);
    __syncthreads();

    for (int tile = 0; tile < NTILES; tile++) {
        const int buf = tile & 1;
        if (tile + 1 < NTILES) { loadA((tile + 1) * 16); loadB((tile + 1) * 16); }

#pragma unroll
        for (int kk = 0; kk < 16; kk++) {
            const char* arow = (const char*)&Asd[buf][kk][0];
            ulonglong2 a0 = *(const ulonglong2*)(arow + aoff);
            ulonglong2 a1 = *(const ulonglong2*)(arow + aoff + 64);
            ulonglong2 a2 = *(const ulonglong2*)(arow + aoff + 128);
            ulonglong2 a3 = *(const ulonglong2*)(arow + aoff + 192);
            const char* brow = (const char*)&Bs[buf][kk][0];
            ulonglong2 b0 = *(const ulonglong2*)(brow + bo0);
            ulonglong2 b1 = *(const ulonglong2*)(brow + bo1);
            u64 pa[8] = {a0.x, a0.y, a1.x, a1.y, a2.x, a2.y, a3.x, a3.y};
#pragma unroll
            for (int m = 0; m < 8; m++) {
                fma2(acc[m][0], pa[m], b0.x);
                fma2(acc[m][1], pa[m], b0.y);
                fma2(acc[m][2], pa[m], b1.x);
                fma2(acc[m][3], pa[m], b1.y);
            }
        }

        if (tile + 1 < NTILES) stage(buf ^ 1);
        __syncthreads();
    }

    // epilogue: acc[mp] holds global row wm*32 + lm*8 + mp (perm is involution)
#pragma unroll
    for (int mp = 0; mp < 8; mp++) {
        const int gm = t0 + wm * 32 + lm * 8 + mp;
        float v[8];
        unpack2(acc[mp][0], v[0], v[1]);
        unpack2(acc[mp][1], v[2], v[3]);
        unpack2(acc[mp][2], v[4], v[5]);
        unpack2(acc[mp][3], v[6], v[7]);
        float* orow = g_buf + (size_t)gm * 256 + n0 + wn * 64 + ln * 8;
        *(float4*)orow       = make_float4(v[0], v[1], v[2], v[3]);
        *(float4*)(orow + 4) = make_float4(v[4], v[5], v[6], v[7]);
    }
}

// ---------------------------------------------------------------------------
// Chunked LSTM recurrence, one warp per (chunk, dir). Bias seeds the second
// fma chain (2-way split). g_buf prefetch ring depth 3 hides LDG latency.
// ---------------------------------------------------------------------------
__global__ __launch_bounds__(128, 3)
void lstm_rec(const float* __restrict__ Whh, const float* __restrict__ bias, int layer)
{
    const int wglob = (blockIdx.x * blockDim.x + threadIdx.x) >> 5;
    const int lane  = threadIdx.x & 31;
    const int dir   = wglob & 1;
    const int chunk = wglob >> 1;
    if (chunk >= NCHUNK) return;

    float* hout = layer ? h1_buf : h0_buf;

    u64 w01[32], w23[32];
    const float* Wd = Whh + dir * 4096;
#pragma unroll
    for (int k = 0; k < 32; k++) {
        w01[k] = pack2f(Wd[(lane)      * 32 + k], Wd[(32 + lane) * 32 + k]);
        w23[k] = pack2f(Wd[(64 + lane) * 32 + k], Wd[(96 + lane) * 32 + k]);
    }
    const float* bd = bias + dir * 128;
    const u64 b01 = pack2f(bd[lane], bd[32 + lane]);
    const u64 b23 = pack2f(bd[64 + lane], bd[96 + lane]);

    const int lo = chunk * LCHUNK;
    const int hi = lo + LCHUNK;
    float h = 0.0f, c = 0.0f;

    if (dir == 0) {
        int tb = lo - WARMUP; if (tb < 0) tb = 0;
        const float* gbase = g_buf + lane * 4;
        ulonglong2 r0 = *(const ulonglong2*)(gbase + (size_t)tb * 256);
        int t1c = tb + 1 < hi ? tb + 1 : hi - 1;
        int t2c = tb + 2 < hi ? tb + 2 : hi - 1;
        ulonglong2 r1 = *(const ulonglong2*)(gbase + (size_t)t1c * 256);
        ulonglong2 r2 = *(const ulonglong2*)(gbase + (size_t)t2c * 256);
        for (int t = tb; t < hi; ++t) {
            ulonglong2 cur = r0; r0 = r1; r1 = r2;
            int tn = t + 3 < hi ? t + 3 : hi - 1;
            r2 = *(const ulonglong2*)(gbase + (size_t)tn * 256);
            u64 g01a = cur.x, g01b = b01;
            u64 g23a = cur.y, g23b = b23;
#pragma unroll
            for (int k = 0; k < 32; k += 2) {
                u64 p0 = pack2(__shfl_sync(0xffffffffu, h, k));
                u64 p1 = pack2(__shfl_sync(0xffffffffu, h, k + 1));
                fma2(g01a, w01[k], p0);  fma2(g01b, w01[k + 1], p1);
                fma2(g23a, w23[k], p0);  fma2(g23b, w23[k + 1], p1);
            }
            float gi, gf, gg, go;
            unpack2(add2(g01a, g01b), gi, gf);
            unpack2(add2(g23a, g23b), gg, go);
            c = sigf(gf) * c + sigf(gi) * tanhfast(gg);
            h = sigf(go) * tanhfast(c);
            if (t >= lo) hout[(size_t)t * 64 + lane] = h;
        }
    } else {
        int tb = hi - 1 + WARMUP; if (tb > T_ - 1) tb = T_ - 1;
        const float* gbase = g_buf + 128 + lane * 4;
        ulonglong2 r0 = *(const ulonglong2*)(gbase + (size_t)tb * 256);
        int t1c = tb - 1 >= lo ? tb - 1 : lo;
        int t2c = tb - 2 >= lo ? tb - 2 : lo;
        ulonglong2 r1 = *(const ulonglong2*)(gbase + (size_t)t1c * 256);
        ulonglong2 r2 = *(const ulonglong2*)(gbase + (size_t)t2c * 256);
        for (int t = tb; t >= lo; --t) {
            ulonglong2 cur = r0; r0 = r1; r1 = r2;
            int tn = t - 3 >= lo ? t - 3 : lo;
            r2 = *(const ulonglong2*)(gbase + (size_t)tn * 256);
            u64 g01a = cur.x, g01b = b01;
            u64 g23a = cur.y, g23b = b23;
#pragma unroll
            for (int k = 0; k < 32; k += 2) {
                u64 p0 = pack2(__shfl_sync(0xffffffffu, h, k));
                u64 p1 = pack2(__shfl_sync(0xffffffffu, h, k + 1));
                fma2(g01a, w01[k], p0);  fma2(g01b, w01[k + 1], p1);
                fma2(g23a, w23[k], p0);  fma2(g23b, w23[k + 1], p1);
            }
            float gi, gf, gg, go;
            unpack2(add2(g01a, g01b), gi, gf);
            unpack2(add2(g23a, g23b), gg, go);
            c = sigf(gf) * c + sigf(gi) * tanhfast(gg);
            h = sigf(go) * tanhfast(c);
            if (t < hi) hout[(size_t)t * 64 + 32 + lane] = h;
        }
    }
}

// ---------------------------------------------------------------------------
// Output head: warp per timestep, W_out staged transposed in smem.
// ---------------------------------------------------------------------------
__global__ __launch_bounds__(256)
void out_kernel(const float* __restrict__ Wout, const float* __restrict__ bout,
                const int* __restrict__ mask, float* __restrict__ out)
{
    __shared__ float Ws[64][52];
    const int tid = threadIdx.x;
    for (int i = tid; i < NTAGS * 64; i += 256) {
        int tag = i >> 6, k = i & 63;
        Ws[k][tag] = Wout[i];
    }
    __syncthreads();

    const int lane = tid & 31;
    const int t = blockIdx.x * 8 + (tid >> 5);

    float h0 = h1_buf[(size_t)t * 64 + lane];
    float h1 = h1_buf[(size_t)t * 64 + 32 + lane];

    const bool hasB = (lane < NTAGS - 32);
    float accA = bout[lane];
    float accB = hasB ? bout[lane + 32] : 0.0f;

#pragma unroll
    for (int k = 0; k < 32; k++) {
        float hk = __shfl_sync(0xffffffffu, h0, k);
        accA = fmaf(Ws[k][lane], hk, accA);
        if (hasB) accB = fmaf(Ws[k][lane + 32], hk, accB);
    }
#pragma unroll
    for (int k = 0; k < 32; k++) {
        float hk = __shfl_sync(0xffffffffu, h1, k);
        accA = fmaf(Ws[32 + k][lane], hk, accA);
        if (hasB) accB = fmaf(Ws[32 + k][lane + 32], hk, accB);
    }

    if (lane == 17) accB = (mask[t] > 0) ? fminf(accB, 1.0f) : 1.0f;
    accA = fmaxf(accA, 0.0f);
    accB = fmaxf(accB, 0.0f);

    float vB = hasB ? accB : -1.0f;
    float m = fmaxf(accA, vB);
#pragma unroll
    for (int o = 16; o; o >>= 1) m = fmaxf(m, __shfl_xor_sync(0xffffffffu, m, o));
    float s = __expf(accA - m) + (hasB ? __expf(accB - m) : 0.0f);
#pragma unroll
    for (int o = 16; o; o >>= 1) s += __shfl_xor_sync(0xffffffffu, s, o);
    float inv = __fdividef(1.0f, s);

    out[(size_t)t * NTAGS + lane] = __expf(accA - m) * inv;
    if (hasB) out[(size_t)t * NTAGS + lane + 32] = __expf(accB - m) * inv;
}

// ---------------------------------------------------------------------------

extern "C" void kernel_launch(void* const* d_in, const int* in_sizes, int n_in,
                              void* d_out, int out_size)
{
    const float* input_vecs = (const float*)d_in[0];
    const float* dp_table   = (const float*)d_in[1];
    const float* Wih0       = (const float*)d_in[2];
    const float* Whh0       = (const float*)d_in[3];
    const float* b0         = (const float*)d_in[4];
    const float* Wih1       = (const float*)d_in[5];
    const float* Whh1       = (const float*)d_in[6];
    const float* b1         = (const float*)d_in[7];
    const float* Wout       = (const float*)d_in[8];
    const float* bout       = (const float*)d_in[9];
    const int*   dp_in      = (const int*)d_in[10];
    const int*   mask       = (const int*)d_in[11];
    float* out = (float*)d_out;

    const dim3 ggrid(T_ / 128, 2);
    const int rec_blocks = (2 * NCHUNK * 32) / 128;   // 512

    prep_kernel<<<784, 256>>>(Wih0, Wih1);
    gemm_gates<1><<<ggrid, 256>>>(input_vecs, dp_table, dp_in);
    lstm_rec<<<rec_blocks, 128>>>(Whh0, b0, 0);
    gemm_gates<0><<<ggrid, 256>>>(nullptr, nullptr, nullptr);
    lstm_rec<<<rec_blocks, 128>>>(Whh1, b1, 1);
    out_kernel<<<T_ / 8, 256>>>(Wout, bout, mask, out);
}

// round 8
// speedup vs baseline: 1.0455x; 1.0455x over previous
#include <cuda_runtime.h>
#include <cstdint>

#define T_ 32768
#define NTAGS 50
#define LCHUNK 32
#define WARMUP 48
#define NCHUNK (T_ / LCHUNK)

typedef unsigned long long u64;

// Scratch (static device globals; no runtime allocation)
__device__ float g_buf[(size_t)T_ * 256];   // gate projections [t][dir*128 + l*4 + p]
__device__ float h0_buf[(size_t)T_ * 64];   // layer0 output [t][dir*32 + lane]
__device__ float h1_buf[(size_t)T_ * 64];   // layer1 output
__device__ float Wt0[784 * 256];            // k-major permuted Wih0 (zero-padded 774->784)
__device__ float Wt1[64 * 256];             // k-major permuted Wih1

__device__ __forceinline__ float sigf(float x) {
    return __fdividef(1.0f, 1.0f + __expf(-x));
}
__device__ __forceinline__ float tanhfast(float x) {
    x = fminf(fmaxf(x, -15.0f), 15.0f);
    float e = __expf(2.0f * x);
    return __fdividef(e - 1.0f, e + 1.0f);
}

// packed f32x2 helpers (pairs carried in u64)
__device__ __forceinline__ u64 pack2(float x) {
    u64 d; asm("mov.b64 %0, {%1, %1};" : "=l"(d) : "f"(x)); return d;
}
__device__ __forceinline__ u64 pack2f(float lo, float hi) {
    u64 d; asm("mov.b64 %0, {%1, %2};" : "=l"(d) : "f"(lo), "f"(hi)); return d;
}
__device__ __forceinline__ void fma2(u64& acc, u64 a, u64 b) {
    asm("fma.rn.f32x2 %0, %1, %2, %0;" : "+l"(acc) : "l"(a), "l"(b));
}
__device__ __forceinline__ u64 add2(u64 a, u64 b) {
    u64 d; asm("add.rn.f32x2 %0, %1, %2;" : "=l"(d) : "l"(a), "l"(b)); return d;
}
__device__ __forceinline__ void unpack2(u64 d, float& lo, float& hi) {
    asm("mov.b64 {%0, %1}, %2;" : "=f"(lo), "=f"(hi) : "l"(d));
}

// ---------------------------------------------------------------------------
// Prep: transpose weights to k-major with the n-permutation baked in.
// n = (dir<<7)|(l<<2)|p  ->  weight row = dir*128 + p*32 + l
// ---------------------------------------------------------------------------
__global__ void prep_kernel(const float* __restrict__ Wih0, const float* __restrict__ Wih1)
{
    const int k = blockIdx.x;       // 0..783
    const int n = threadIdx.x;      // 0..255
    const int dir = n >> 7, l = (n & 127) >> 2, p = n & 3;
    const int row = dir * 128 + p * 32 + l;
    Wt0[k * 256 + n] = (k < 774) ? Wih0[(size_t)row * 774 + k] : 0.0f;
    if (k < 64) Wt1[k * 256 + n] = Wih1[(size_t)row * 64 + k];
}

// SW128-style swizzle for 1KB rows (byte offsets)
__device__ __forceinline__ uint32_t sw1k(uint32_t off) { return off ^ ((off >> 3) & 0x70); }

// ---------------------------------------------------------------------------
// Gate GEMM: 128m x 128n x 16k tiles, 256 threads, 8x8 frag per thread.
// As[k][m] float rows (512B): the thread's 8 m-rows are naturally adjacent,
// so A pairs come straight from 2x LDS.128 (no MOV, no duplication).
// Bsd[k][n] u64 rows (1KB, SW128-swizzled): B stored PRE-DUPLICATED (b,b)
// at stage time (8 pack MOVs per tile, not per kk).
// Inner loop per kk: 6 conflict-free LDS.128 + 32 FFMA2. FMA-bound.
// acc[mp][n] accumulates m-pair (m_t+2mp, m_t+2mp+1) x col (n_t+n).
// ---------------------------------------------------------------------------
template<int CONCAT>
__global__ __launch_bounds__(256, 2)
void gemm_gates(const float* __restrict__ A,
                const float* __restrict__ dp_table,
                const int* __restrict__ dp_in)
{
    constexpr int K = CONCAT ? 774 : 64;
    constexpr int NTILES = (K + 15) / 16;     // 49 or 4
    constexpr int AROW = CONCAT ? 770 : 64;

    __shared__ __align__(16) float As[2][16][128];   // [buf][kk][m], rows 512B
    __shared__ __align__(16) u64   Bsd[2][16][128];  // [buf][kk][n] dup pairs, rows 1KB swizzled

    const int tid = threadIdx.x;
    const int t0 = blockIdx.x * 128;
    const int n0 = blockIdx.y * 128;

    const int wid = tid >> 5, lane = tid & 31;
    const int wm = wid & 3, wn = wid >> 2;     // 4x2 warp grid
    const int lm = lane & 3, ln = lane >> 2;   // 4x8 lane grid
    const int m_t = wm * 32 + lm * 8;          // 8 consecutive m rows
    const int n_t = wn * 64 + ln * 8;          // 8 consecutive n cols

    // in-row byte offsets for fragment loads
    const uint32_t a_off = (uint32_t)m_t * 4;                   // 512B row, conflict-free
    const uint32_t nt8 = (uint32_t)n_t * 8;                     // 1KB row
    const uint32_t b_o0 = sw1k(nt8),      b_o1 = sw1k(nt8 + 16);
    const uint32_t b_o2 = sw1k(nt8 + 32), b_o3 = sw1k(nt8 + 48);

    // loader roles
    const int m_a = tid >> 1;          // A row 0..127
    const int ha  = (tid & 1) * 8;     // A k offset 0 or 8
    const int kb  = tid >> 4;          // B k row 0..15
    const int nb  = (tid & 15) * 8;    // B col (8 u64 per thread)
    const uint32_t nbo = (uint32_t)nb * 8;
    const uint32_t s_o0 = sw1k(nbo),      s_o1 = sw1k(nbo + 16);
    const uint32_t s_o2 = sw1k(nbo + 32), s_o3 = sw1k(nbo + 48);

    const float* __restrict__ Wt = CONCAT ? Wt0 : Wt1;
    const float* __restrict__ Asrc = CONCAT ? A : h0_buf;
    const float* __restrict__ Wsrc = Wt + (size_t)kb * 256 + n0 + nb;

    u64 acc[4][8];
#pragma unroll
    for (int mp = 0; mp < 4; mp++)
#pragma unroll
        for (int n = 0; n < 8; n++) acc[mp][n] = 0ull;

    float ar[8], br[8];

    auto loadA = [&](int k0) {
        if (!CONCAT || k0 < 768) {
            const float* ap = Asrc + (size_t)(t0 + m_a) * AROW + k0 + ha;
#pragma unroll
            for (int j = 0; j < 4; j++) {      // rows only 8B-aligned for CONCAT
                float2 v = *(const float2*)(ap + 2 * j);
                ar[2 * j] = v.x; ar[2 * j + 1] = v.y;
            }
        } else {
            int dpo = dp_in[t0 + m_a] * 4;
#pragma unroll
            for (int j = 0; j < 8; j++) {
                int k = k0 + ha + j;
                float v = 0.0f;
                if (k < 770)      v = Asrc[(size_t)(t0 + m_a) * 770 + k];
                else if (k < 774) v = dp_table[dpo + (k - 770)];
                ar[j] = v;
            }
        }
    };
    auto loadB = [&](int k0) {
        const float* bpp = Wsrc + (size_t)k0 * 256;
        float4 v0 = *(const float4*)bpp;
        float4 v1 = *(const float4*)(bpp + 4);
        br[0] = v0.x; br[1] = v0.y; br[2] = v0.z; br[3] = v0.w;
        br[4] = v1.x; br[5] = v1.y; br[6] = v1.z; br[7] = v1.w;
    };
    auto stage = [&](int buf) {
#pragma unroll
        for (int j = 0; j < 8; j++) As[buf][ha + j][m_a] = ar[j];
        char* row = (char*)&Bsd[buf][kb][0];
        ulonglong2 d0; d0.x = pack2(br[0]); d0.y = pack2(br[1]);
        ulonglong2 d1; d1.x = pack2(br[2]); d1.y = pack2(br[3]);
        ulonglong2 d2; d2.x = pack2(br[4]); d2.y = pack2(br[5]);
        ulonglong2 d3; d3.x = pack2(br[6]); d3.y = pack2(br[7]);
        *(ulonglong2*)(row + s_o0) = d0;
        *(ulonglong2*)(row + s_o1) = d1;
        *(ulonglong2*)(row + s_o2) = d2;
        *(ulonglong2*)(row + s_o3) = d3;
    };

    loadA(0); loadB(0); stage(0);
    __syncthreads();

    for (int tile = 0; tile < NTILES; tile++) {
        const int buf = tile & 1;
        if (tile + 1 < NTILES) { loadA((tile + 1) * 16); loadB((tile + 1) * 16); }

#pragma unroll
        for (int kk = 0; kk < 16; kk++) {
            const char* arow = (const char*)&As[buf][kk][0];
            ulonglong2 a01 = *(const ulonglong2*)(arow + a_off);        // pairs (m0,m1),(m2,m3)
            ulonglong2 a23 = *(const ulonglong2*)(arow + a_off + 16);   // pairs (m4,m5),(m6,m7)
            const char* brow = (const char*)&Bsd[buf][kk][0];
            ulonglong2 b0 = *(const ulonglong2*)(brow + b_o0);
            ulonglong2 b1 = *(const ulonglong2*)(brow + b_o1);
            ulonglong2 b2 = *(const ulonglong2*)(brow + b_o2);
            ulonglong2 b3 = *(const ulonglong2*)(brow + b_o3);
            u64 pa[4] = {a01.x, a01.y, a23.x, a23.y};
            u64 bb[8] = {b0.x, b0.y, b1.x, b1.y, b2.x, b2.y, b3.x, b3.y};
#pragma unroll
            for (int mp = 0; mp < 4; mp++)
#pragma unroll
                for (int n = 0; n < 8; n++)
                    fma2(acc[mp][n], pa[mp], bb[n]);
        }

        if (tile + 1 < NTILES) stage(buf ^ 1);
        __syncthreads();
    }

    // epilogue: acc[mp][n] -> rows m_t+2mp (lo) and m_t+2mp+1 (hi), col n_t+n
#pragma unroll
    for (int mp = 0; mp < 4; mp++) {
        float vlo[8], vhi[8];
#pragma unroll
        for (int n = 0; n < 8; n++) unpack2(acc[mp][n], vlo[n], vhi[n]);
        float* r0 = g_buf + (size_t)(t0 + m_t + 2 * mp)     * 256 + n0 + n_t;
        float* r1 = g_buf + (size_t)(t0 + m_t + 2 * mp + 1) * 256 + n0 + n_t;
        *(float4*)r0       = make_float4(vlo[0], vlo[1], vlo[2], vlo[3]);
        *(float4*)(r0 + 4) = make_float4(vlo[4], vlo[5], vlo[6], vlo[7]);
        *(float4*)r1       = make_float4(vhi[0], vhi[1], vhi[2], vhi[3]);
        *(float4*)(r1 + 4) = make_float4(vhi[4], vhi[5], vhi[6], vhi[7]);
    }
}

// ---------------------------------------------------------------------------
// Chunked LSTM recurrence, one warp per (chunk, dir). Bias seeds the second
// fma chain (2-way split). g_buf prefetch ring depth 3 hides LDG latency.
// ---------------------------------------------------------------------------
__global__ __launch_bounds__(128, 3)
void lstm_rec(const float* __restrict__ Whh, const float* __restrict__ bias, int layer)
{
    const int wglob = (blockIdx.x * blockDim.x + threadIdx.x) >> 5;
    const int lane  = threadIdx.x & 31;
    const int dir   = wglob & 1;
    const int chunk = wglob >> 1;
    if (chunk >= NCHUNK) return;

    float* hout = layer ? h1_buf : h0_buf;

    u64 w01[32], w23[32];
    const float* Wd = Whh + dir * 4096;
#pragma unroll
    for (int k = 0; k < 32; k++) {
        w01[k] = pack2f(Wd[(lane)      * 32 + k], Wd[(32 + lane) * 32 + k]);
        w23[k] = pack2f(Wd[(64 + lane) * 32 + k], Wd[(96 + lane) * 32 + k]);
    }
    const float* bd = bias + dir * 128;
    const u64 b01 = pack2f(bd[lane], bd[32 + lane]);
    const u64 b23 = pack2f(bd[64 + lane], bd[96 + lane]);

    const int lo = chunk * LCHUNK;
    const int hi = lo + LCHUNK;
    float h = 0.0f, c = 0.0f;

    if (dir == 0) {
        int tb = lo - WARMUP; if (tb < 0) tb = 0;
        const float* gbase = g_buf + lane * 4;
        ulonglong2 r0 = *(const ulonglong2*)(gbase + (size_t)tb * 256);
        int t1c = tb + 1 < hi ? tb + 1 : hi - 1;
        int t2c = tb + 2 < hi ? tb + 2 : hi - 1;
        ulonglong2 r1 = *(const ulonglong2*)(gbase + (size_t)t1c * 256);
        ulonglong2 r2 = *(const ulonglong2*)(gbase + (size_t)t2c * 256);
        for (int t = tb; t < hi; ++t) {
            ulonglong2 cur = r0; r0 = r1; r1 = r2;
            int tn = t + 3 < hi ? t + 3 : hi - 1;
            r2 = *(const ulonglong2*)(gbase + (size_t)tn * 256);
            u64 g01a = cur.x, g01b = b01;
            u64 g23a = cur.y, g23b = b23;
#pragma unroll
            for (int k = 0; k < 32; k += 2) {
                u64 p0 = pack2(__shfl_sync(0xffffffffu, h, k));
                u64 p1 = pack2(__shfl_sync(0xffffffffu, h, k + 1));
                fma2(g01a, w01[k], p0);  fma2(g01b, w01[k + 1], p1);
                fma2(g23a, w23[k], p0);  fma2(g23b, w23[k + 1], p1);
            }
            float gi, gf, gg, go;
            unpack2(add2(g01a, g01b), gi, gf);
            unpack2(add2(g23a, g23b), gg, go);
            c = sigf(gf) * c + sigf(gi) * tanhfast(gg);
            h = sigf(go) * tanhfast(c);
            if (t >= lo) hout[(size_t)t * 64 + lane] = h;
        }
    } else {
        int tb = hi - 1 + WARMUP; if (tb > T_ - 1) tb = T_ - 1;
        const float* gbase = g_buf + 128 + lane * 4;
        ulonglong2 r0 = *(const ulonglong2*)(gbase + (size_t)tb * 256);
        int t1c = tb - 1 >= lo ? tb - 1 : lo;
        int t2c = tb - 2 >= lo ? tb - 2 : lo;
        ulonglong2 r1 = *(const ulonglong2*)(gbase + (size_t)t1c * 256);
        ulonglong2 r2 = *(const ulonglong2*)(gbase + (size_t)t2c * 256);
        for (int t = tb; t >= lo; --t) {
            ulonglong2 cur = r0; r0 = r1; r1 = r2;
            int tn = t - 3 >= lo ? t - 3 : lo;
            r2 = *(const ulonglong2*)(gbase + (size_t)tn * 256);
            u64 g01a = cur.x, g01b = b01;
            u64 g23a = cur.y, g23b = b23;
#pragma unroll
            for (int k = 0; k < 32; k += 2) {
                u64 p0 = pack2(__shfl_sync(0xffffffffu, h, k));
                u64 p1 = pack2(__shfl_sync(0xffffffffu, h, k + 1));
                fma2(g01a, w01[k], p0);  fma2(g01b, w01[k + 1], p1);
                fma2(g23a, w23[k], p0);  fma2(g23b, w23[k + 1], p1);
            }
            float gi, gf, gg, go;
            unpack2(add2(g01a, g01b), gi, gf);
            unpack2(add2(g23a, g23b), gg, go);
            c = sigf(gf) * c + sigf(gi) * tanhfast(gg);
            h = sigf(go) * tanhfast(c);
            if (t < hi) hout[(size_t)t * 64 + 32 + lane] = h;
        }
    }
}

// ---------------------------------------------------------------------------
// Output head: warp per timestep, W_out staged transposed in smem.
// ---------------------------------------------------------------------------
__global__ __launch_bounds__(256)
void out_kernel(const float* __restrict__ Wout, const float* __restrict__ bout,
                const int* __restrict__ mask, float* __restrict__ out)
{
    __shared__ float Ws[64][52];
    const int tid = threadIdx.x;
    for (int i = tid; i < NTAGS * 64; i += 256) {
        int tag = i >> 6, k = i & 63;
        Ws[k][tag] = Wout[i];
    }
    __syncthreads();

    const int lane = tid & 31;
    const int t = blockIdx.x * 8 + (tid >> 5);

    float h0 = h1_buf[(size_t)t * 64 + lane];
    float h1 = h1_buf[(size_t)t * 64 + 32 + lane];

    const bool hasB = (lane < NTAGS - 32);
    float accA = bout[lane];
    float accB = hasB ? bout[lane + 32] : 0.0f;

#pragma unroll
    for (int k = 0; k < 32; k++) {
        float hk = __shfl_sync(0xffffffffu, h0, k);
        accA = fmaf(Ws[k][lane], hk, accA);
        if (hasB) accB = fmaf(Ws[k][lane + 32], hk, accB);
    }
#pragma unroll
    for (int k = 0; k < 32; k++) {
        float hk = __shfl_sync(0xffffffffu, h1, k);
        accA = fmaf(Ws[32 + k][lane], hk, accA);
        if (hasB) accB = fmaf(Ws[32 + k][lane + 32], hk, accB);
    }

    if (lane == 17) accB = (mask[t] > 0) ? fminf(accB, 1.0f) : 1.0f;
    accA = fmaxf(accA, 0.0f);
    accB = fmaxf(accB, 0.0f);

    float vB = hasB ? accB : -1.0f;
    float m = fmaxf(accA, vB);
#pragma unroll
    for (int o = 16; o; o >>= 1) m = fmaxf(m, __shfl_xor_sync(0xffffffffu, m, o));
    float s = __expf(accA - m) + (hasB ? __expf(accB - m) : 0.0f);
#pragma unroll
    for (int o = 16; o; o >>= 1) s += __shfl_xor_sync(0xffffffffu, s, o);
    float inv = __fdividef(1.0f, s);

    out[(size_t)t * NTAGS + lane] = __expf(accA - m) * inv;
    if (hasB) out[(size_t)t * NTAGS + lane + 32] = __expf(accB - m) * inv;
}

// ---------------------------------------------------------------------------

extern "C" void kernel_launch(void* const* d_in, const int* in_sizes, int n_in,
                              void* d_out, int out_size)
{
    const float* input_vecs = (const float*)d_in[0];
    const float* dp_table   = (const float*)d_in[1];
    const float* Wih0       = (const float*)d_in[2];
    const float* Whh0       = (const float*)d_in[3];
    const float* b0         = (const float*)d_in[4];
    const float* Wih1       = (const float*)d_in[5];
    const float* Whh1       = (const float*)d_in[6];
    const float* b1         = (const float*)d_in[7];
    const float* Wout       = (const float*)d_in[8];
    const float* bout       = (const float*)d_in[9];
    const int*   dp_in      = (const int*)d_in[10];
    const int*   mask       = (const int*)d_in[11];
    float* out = (float*)d_out;

    const dim3 ggrid(T_ / 128, 2);
    const int rec_blocks = (2 * NCHUNK * 32) / 128;   // 512

    prep_kernel<<<784, 256>>>(Wih0, Wih1);
    gemm_gates<1><<<ggrid, 256>>>(input_vecs, dp_table, dp_in);
    lstm_rec<<<rec_blocks, 128>>>(Whh0, b0, 0);
    gemm_gates<0><<<ggrid, 256>>>(nullptr, nullptr, nullptr);
    lstm_rec<<<rec_blocks, 128>>>(Whh1, b1, 1);
    out_kernel<<<T_ / 8, 256>>>(Wout, bout, mask, out);
}

// round 9
// speedup vs baseline: 1.1309x; 1.0816x over previous
#include <cuda_runtime.h>
#include <cstdint>

#define T_ 32768
#define NTAGS 50
#define LCHUNK 32
#define WARMUP 48
#define NCHUNK (T_ / LCHUNK)

typedef unsigned long long u64;

// Scratch (static device globals; no runtime allocation)
__device__ float g_buf[(size_t)T_ * 256];   // gate projections [t][dir*128 + l*4 + p]
__device__ float h0_buf[(size_t)T_ * 64];   // layer0 output [t][dir*32 + lane]
__device__ float h1_buf[(size_t)T_ * 64];   // layer1 output
__device__ float Wt0[784 * 256];            // k-major permuted Wih0 (zero-padded 774->784)
__device__ float Wt1[64 * 256];             // k-major permuted Wih1

__device__ __forceinline__ float sigf(float x) {
    return __fdividef(1.0f, 1.0f + __expf(-x));
}
__device__ __forceinline__ float tanhfast(float x) {
    x = fminf(fmaxf(x, -15.0f), 15.0f);
    float e = __expf(2.0f * x);
    return __fdividef(e - 1.0f, e + 1.0f);
}

// packed f32x2 helpers (pairs carried in u64)
__device__ __forceinline__ u64 pack2(float x) {
    u64 d; asm("mov.b64 %0, {%1, %1};" : "=l"(d) : "f"(x)); return d;
}
__device__ __forceinline__ u64 pack2f(float lo, float hi) {
    u64 d; asm("mov.b64 %0, {%1, %2};" : "=l"(d) : "f"(lo), "f"(hi)); return d;
}
__device__ __forceinline__ void fma2(u64& acc, u64 a, u64 b) {
    asm("fma.rn.f32x2 %0, %1, %2, %0;" : "+l"(acc) : "l"(a), "l"(b));
}
__device__ __forceinline__ u64 add2(u64 a, u64 b) {
    u64 d; asm("add.rn.f32x2 %0, %1, %2;" : "=l"(d) : "l"(a), "l"(b)); return d;
}
__device__ __forceinline__ void unpack2(u64 d, float& lo, float& hi) {
    asm("mov.b64 {%0, %1}, %2;" : "=f"(lo), "=f"(hi) : "l"(d));
}

// ---------------------------------------------------------------------------
// Prep: transpose weights to k-major with the n-permutation baked in.
// n = (dir<<7)|(l<<2)|p  ->  weight row = dir*128 + p*32 + l
// ---------------------------------------------------------------------------
__global__ void prep_kernel(const float* __restrict__ Wih0, const float* __restrict__ Wih1)
{
    const int k = blockIdx.x;       // 0..783
    const int n = threadIdx.x;      // 0..255
    const int dir = n >> 7, l = (n & 127) >> 2, p = n & 3;
    const int row = dir * 128 + p * 32 + l;
    Wt0[k * 256 + n] = (k < 774) ? Wih0[(size_t)row * 774 + k] : 0.0f;
    if (k < 64) Wt1[k * 256 + n] = Wih1[(size_t)row * 64 + k];
}

// 16B-granular swizzle: maps bit7 into bit4, separating 128B-aliased offsets
__device__ __forceinline__ uint32_t swz(uint32_t off) { return off ^ ((off >> 3) & 0x10); }

// ---------------------------------------------------------------------------
// Gate GEMM: 128m x 128n x 16k tiles, 256 threads, 8x8 frag per thread.
// As[k][m], Bs[k][n]: BOTH plain float 512B rows (minimum smem traffic:
// 32B A + 32B B per thread per kk = 1.0 B/FMA, crossbar == FMA pipe).
// B fragment ulonglong2 loads give natural n-pairs (FFMA2-ready).
// A is duplicated in REGISTERS via pack2 (8 alu MOVs/kk, off the fma pipe).
// Bs rows swizzled (swz) so ln*32-stride loads are bank-conflict-free.
// acc[m][np] = row (m_t+m) x cols (n_t+2np, n_t+2np+1).
// ---------------------------------------------------------------------------
template<int CONCAT>
__global__ __launch_bounds__(256, 2)
void gemm_gates(const float* __restrict__ A,
                const float* __restrict__ dp_table,
                const int* __restrict__ dp_in)
{
    constexpr int K = CONCAT ? 774 : 64;
    constexpr int NTILES = (K + 15) / 16;     // 49 or 4
    constexpr int AROW = CONCAT ? 770 : 64;

    __shared__ __align__(16) float As[2][16][128];   // [buf][kk][m], rows 512B
    __shared__ __align__(16) float Bs[2][16][128];   // [buf][kk][n], rows 512B swizzled

    const int tid = threadIdx.x;
    const int t0 = blockIdx.x * 128;
    const int n0 = blockIdx.y * 128;

    const int wid = tid >> 5, lane = tid & 31;
    const int wm = wid & 3, wn = wid >> 2;     // 4x2 warp grid
    const int lm = lane & 3, ln = lane >> 2;   // 4x8 lane grid
    const int m_t = wm * 32 + lm * 8;          // 8 consecutive m rows
    const int n_t = wn * 64 + ln * 8;          // 8 consecutive n cols

    // in-row byte offsets for fragment loads
    const uint32_t a_off = (uint32_t)m_t * 4;             // broadcast, conflict-free
    const uint32_t nt4 = (uint32_t)n_t * 4;
    const uint32_t b_o0 = swz(nt4), b_o1 = swz(nt4 + 16);

    // loader roles
    const int m_a = tid >> 1;          // A row 0..127
    const int ha  = (tid & 1) * 8;     // A k offset 0 or 8
    const int kb  = tid >> 4;          // B k row 0..15
    const int nb  = (tid & 15) * 8;    // B col start (8 floats per thread)
    const uint32_t nbo = (uint32_t)nb * 4;
    const uint32_t s_o0 = swz(nbo), s_o1 = swz(nbo + 16);

    const float* __restrict__ Wt = CONCAT ? Wt0 : Wt1;
    const float* __restrict__ Asrc = CONCAT ? A : h0_buf;
    const float* __restrict__ Wsrc = Wt + (size_t)kb * 256 + n0 + nb;

    u64 acc[8][4];
#pragma unroll
    for (int m = 0; m < 8; m++)
#pragma unroll
        for (int np = 0; np < 4; np++) acc[m][np] = 0ull;

    float ar[8], br[8];

    auto loadA = [&](int k0) {
        if (!CONCAT || k0 < 768) {
            const float* ap = Asrc + (size_t)(t0 + m_a) * AROW + k0 + ha;
#pragma unroll
            for (int j = 0; j < 4; j++) {      // rows only 8B-aligned for CONCAT
                float2 v = *(const float2*)(ap + 2 * j);
                ar[2 * j] = v.x; ar[2 * j + 1] = v.y;
            }
        } else {
            int dpo = dp_in[t0 + m_a] * 4;
#pragma unroll
            for (int j = 0; j < 8; j++) {
                int k = k0 + ha + j;
                float v = 0.0f;
                if (k < 770)      v = Asrc[(size_t)(t0 + m_a) * 770 + k];
                else if (k < 774) v = dp_table[dpo + (k - 770)];
                ar[j] = v;
            }
        }
    };
    auto loadB = [&](int k0) {
        const float* bpp = Wsrc + (size_t)k0 * 256;
        float4 v0 = *(const float4*)bpp;
        float4 v1 = *(const float4*)(bpp + 4);
        br[0] = v0.x; br[1] = v0.y; br[2] = v0.z; br[3] = v0.w;
        br[4] = v1.x; br[5] = v1.y; br[6] = v1.z; br[7] = v1.w;
    };
    auto stage = [&](int buf) {
#pragma unroll
        for (int j = 0; j < 8; j++) As[buf][ha + j][m_a] = ar[j];
        char* row = (char*)&Bs[buf][kb][0];
        *(float4*)(row + s_o0) = make_float4(br[0], br[1], br[2], br[3]);
        *(float4*)(row + s_o1) = make_float4(br[4], br[5], br[6], br[7]);
    };

    loadA(0); loadB(0); stage(0);
    __syncthreads();

    for (int tile = 0; tile < NTILES; tile++) {
        const int buf = tile & 1;
        if (tile + 1 < NTILES) { loadA((tile + 1) * 16); loadB((tile + 1) * 16); }

#pragma unroll
        for (int kk = 0; kk < 16; kk++) {
            const char* arow = (const char*)&As[buf][kk][0];
            float4 a0 = *(const float4*)(arow + a_off);
            float4 a1 = *(const float4*)(arow + a_off + 16);
            const char* brow = (const char*)&Bs[buf][kk][0];
            ulonglong2 b01 = *(const ulonglong2*)(brow + b_o0);  // n-pairs 0,1
            ulonglong2 b23 = *(const ulonglong2*)(brow + b_o1);  // n-pairs 2,3
            u64 bb[4] = {b01.x, b01.y, b23.x, b23.y};
            u64 pa[8];
            pa[0] = pack2(a0.x); pa[1] = pack2(a0.y);
            pa[2] = pack2(a0.z); pa[3] = pack2(a0.w);
            pa[4] = pack2(a1.x); pa[5] = pack2(a1.y);
            pa[6] = pack2(a1.z); pa[7] = pack2(a1.w);
#pragma unroll
            for (int m = 0; m < 8; m++)
#pragma unroll
                for (int np = 0; np < 4; np++)
                    fma2(acc[m][np], pa[m], bb[np]);
        }

        if (tile + 1 < NTILES) stage(buf ^ 1);
        __syncthreads();
    }

    // epilogue: acc[m][np] -> row t0+m_t+m, cols n_t+2np (lo), n_t+2np+1 (hi)
#pragma unroll
    for (int m = 0; m < 8; m++) {
        float v[8];
#pragma unroll
        for (int np = 0; np < 4; np++) unpack2(acc[m][np], v[2 * np], v[2 * np + 1]);
        float* orow = g_buf + (size_t)(t0 + m_t + m) * 256 + n0 + n_t;
        *(float4*)orow       = make_float4(v[0], v[1], v[2], v[3]);
        *(float4*)(orow + 4) = make_float4(v[4], v[5], v[6], v[7]);
    }
}

// ---------------------------------------------------------------------------
// Chunked LSTM recurrence, one warp per (chunk, dir). Bias seeds the second
// fma chain (2-way split). g_buf prefetch ring depth 3 hides LDG latency.
// ---------------------------------------------------------------------------
__global__ __launch_bounds__(128, 3)
void lstm_rec(const float* __restrict__ Whh, const float* __restrict__ bias, int layer)
{
    const int wglob = (blockIdx.x * blockDim.x + threadIdx.x) >> 5;
    const int lane  = threadIdx.x & 31;
    const int dir   = wglob & 1;
    const int chunk = wglob >> 1;
    if (chunk >= NCHUNK) return;

    float* hout = layer ? h1_buf : h0_buf;

    u64 w01[32], w23[32];
    const float* Wd = Whh + dir * 4096;
#pragma unroll
    for (int k = 0; k < 32; k++) {
        w01[k] = pack2f(Wd[(lane)      * 32 + k], Wd[(32 + lane) * 32 + k]);
        w23[k] = pack2f(Wd[(64 + lane) * 32 + k], Wd[(96 + lane) * 32 + k]);
    }
    const float* bd = bias + dir * 128;
    const u64 b01 = pack2f(bd[lane], bd[32 + lane]);
    const u64 b23 = pack2f(bd[64 + lane], bd[96 + lane]);

    const int lo = chunk * LCHUNK;
    const int hi = lo + LCHUNK;
    float h = 0.0f, c = 0.0f;

    if (dir == 0) {
        int tb = lo - WARMUP; if (tb < 0) tb = 0;
        const float* gbase = g_buf + lane * 4;
        ulonglong2 r0 = *(const ulonglong2*)(gbase + (size_t)tb * 256);
        int t1c = tb + 1 < hi ? tb + 1 : hi - 1;
        int t2c = tb + 2 < hi ? tb + 2 : hi - 1;
        ulonglong2 r1 = *(const ulonglong2*)(gbase + (size_t)t1c * 256);
        ulonglong2 r2 = *(const ulonglong2*)(gbase + (size_t)t2c * 256);
        for (int t = tb; t < hi; ++t) {
            ulonglong2 cur = r0; r0 = r1; r1 = r2;
            int tn = t + 3 < hi ? t + 3 : hi - 1;
            r2 = *(const ulonglong2*)(gbase + (size_t)tn * 256);
            u64 g01a = cur.x, g01b = b01;
            u64 g23a = cur.y, g23b = b23;
#pragma unroll
            for (int k = 0; k < 32; k += 2) {
                u64 p0 = pack2(__shfl_sync(0xffffffffu, h, k));
                u64 p1 = pack2(__shfl_sync(0xffffffffu, h, k + 1));
                fma2(g01a, w01[k], p0);  fma2(g01b, w01[k + 1], p1);
                fma2(g23a, w23[k], p0);  fma2(g23b, w23[k + 1], p1);
            }
            float gi, gf, gg, go;
            unpack2(add2(g01a, g01b), gi, gf);
            unpack2(add2(g23a, g23b), gg, go);
            c = sigf(gf) * c + sigf(gi) * tanhfast(gg);
            h = sigf(go) * tanhfast(c);
            if (t >= lo) hout[(size_t)t * 64 + lane] = h;
        }
    } else {
        int tb = hi - 1 + WARMUP; if (tb > T_ - 1) tb = T_ - 1;
        const float* gbase = g_buf + 128 + lane * 4;
        ulonglong2 r0 = *(const ulonglong2*)(gbase + (size_t)tb * 256);
        int t1c = tb - 1 >= lo ? tb - 1 : lo;
        int t2c = tb - 2 >= lo ? tb - 2 : lo;
        ulonglong2 r1 = *(const ulonglong2*)(gbase + (size_t)t1c * 256);
        ulonglong2 r2 = *(const ulonglong2*)(gbase + (size_t)t2c * 256);
        for (int t = tb; t >= lo; --t) {
            ulonglong2 cur = r0; r0 = r1; r1 = r2;
            int tn = t - 3 >= lo ? t - 3 : lo;
            r2 = *(const ulonglong2*)(gbase + (size_t)tn * 256);
            u64 g01a = cur.x, g01b = b01;
            u64 g23a = cur.y, g23b = b23;
#pragma unroll
            for (int k = 0; k < 32; k += 2) {
                u64 p0 = pack2(__shfl_sync(0xffffffffu, h, k));
                u64 p1 = pack2(__shfl_sync(0xffffffffu, h, k + 1));
                fma2(g01a, w01[k], p0);  fma2(g01b, w01[k + 1], p1);
                fma2(g23a, w23[k], p0);  fma2(g23b, w23[k + 1], p1);
            }
            float gi, gf, gg, go;
            unpack2(add2(g01a, g01b), gi, gf);
            unpack2(add2(g23a, g23b), gg, go);
            c = sigf(gf) * c + sigf(gi) * tanhfast(gg);
            h = sigf(go) * tanhfast(c);
            if (t < hi) hout[(size_t)t * 64 + 32 + lane] = h;
        }
    }
}

// ---------------------------------------------------------------------------
// Output head: warp per timestep, W_out staged transposed in smem.
// ---------------------------------------------------------------------------
__global__ __launch_bounds__(256)
void out_kernel(const float* __restrict__ Wout, const float* __restrict__ bout,
                const int* __restrict__ mask, float* __restrict__ out)
{
    __shared__ float Ws[64][52];
    const int tid = threadIdx.x;
    for (int i = tid; i < NTAGS * 64; i += 256) {
        int tag = i >> 6, k = i & 63;
        Ws[k][tag] = Wout[i];
    }
    __syncthreads();

    const int lane = tid & 31;
    const int t = blockIdx.x * 8 + (tid >> 5);

    float h0 = h1_buf[(size_t)t * 64 + lane];
    float h1 = h1_buf[(size_t)t * 64 + 32 + lane];

    const bool hasB = (lane < NTAGS - 32);
    float accA = bout[lane];
    float accB = hasB ? bout[lane + 32] : 0.0f;

#pragma unroll
    for (int k = 0; k < 32; k++) {
        float hk = __shfl_sync(0xffffffffu, h0, k);
        accA = fmaf(Ws[k][lane], hk, accA);
        if (hasB) accB = fmaf(Ws[k][lane + 32], hk, accB);
    }
#pragma unroll
    for (int k = 0; k < 32; k++) {
        float hk = __shfl_sync(0xffffffffu, h1, k);
        accA = fmaf(Ws[32 + k][lane], hk, accA);
        if (hasB) accB = fmaf(Ws[32 + k][lane + 32], hk, accB);
    }

    if (lane == 17) accB = (mask[t] > 0) ? fminf(accB, 1.0f) : 1.0f;
    accA = fmaxf(accA, 0.0f);
    accB = fmaxf(accB, 0.0f);

    float vB = hasB ? accB : -1.0f;
    float m = fmaxf(accA, vB);
#pragma unroll
    for (int o = 16; o; o >>= 1) m = fmaxf(m, __shfl_xor_sync(0xffffffffu, m, o));
    float s = __expf(accA - m) + (hasB ? __expf(accB - m) : 0.0f);
#pragma unroll
    for (int o = 16; o; o >>= 1) s += __shfl_xor_sync(0xffffffffu, s, o);
    float inv = __fdividef(1.0f, s);

    out[(size_t)t * NTAGS + lane] = __expf(accA - m) * inv;
    if (hasB) out[(size_t)t * NTAGS + lane + 32] = __expf(accB - m) * inv;
}

// ---------------------------------------------------------------------------

extern "C" void kernel_launch(void* const* d_in, const int* in_sizes, int n_in,
                              void* d_out, int out_size)
{
    const float* input_vecs = (const float*)d_in[0];
    const float* dp_table   = (const float*)d_in[1];
    const float* Wih0       = (const float*)d_in[2];
    const float* Whh0       = (const float*)d_in[3];
    const float* b0         = (const float*)d_in[4];
    const float* Wih1       = (const float*)d_in[5];
    const float* Whh1       = (const float*)d_in[6];
    const float* b1         = (const float*)d_in[7];
    const float* Wout       = (const float*)d_in[8];
    const float* bout       = (const float*)d_in[9];
    const int*   dp_in      = (const int*)d_in[10];
    const int*   mask       = (const int*)d_in[11];
    float* out = (float*)d_out;

    const dim3 ggrid(T_ / 128, 2);
    const int rec_blocks = (2 * NCHUNK * 32) / 128;   // 512

    prep_kernel<<<784, 256>>>(Wih0, Wih1);
    gemm_gates<1><<<ggrid, 256>>>(input_vecs, dp_table, dp_in);
    lstm_rec<<<rec_blocks, 128>>>(Whh0, b0, 0);
    gemm_gates<0><<<ggrid, 256>>>(nullptr, nullptr, nullptr);
    lstm_rec<<<rec_blocks, 128>>>(Whh1, b1, 1);
    out_kernel<<<T_ / 8, 256>>>(Wout, bout, mask, out);
}

// round 10
// speedup vs baseline: 1.1367x; 1.0052x over previous
#include <cuda_runtime.h>
#include <cstdint>

#define T_ 32768
#define NTAGS 50
#define LCHUNK 32
#define WARMUP 48
#define NCHUNK (T_ / LCHUNK)

typedef unsigned long long u64;

// Scratch (static device globals; no runtime allocation)
__device__ float g_buf[(size_t)T_ * 256];     // gate projections [t][dir*128 + l*4 + p]
__device__ float At0[(size_t)800 * T_];       // transposed layer0 input [k][t], rows 774..799 zero
__device__ float h0T[(size_t)64 * T_];        // transposed layer0 output [k][t]
__device__ float h1_buf[(size_t)T_ * 64];     // layer1 output [t][dir*32 + lane]
__device__ float Wt0[800 * 256];              // k-major permuted Wih0 (zero-padded 774->800)
__device__ float Wt1[64 * 256];               // k-major permuted Wih1

__device__ __forceinline__ float sigf(float x) {
    return __fdividef(1.0f, 1.0f + __expf(-x));
}
__device__ __forceinline__ float tanhfast(float x) {
    x = fminf(fmaxf(x, -15.0f), 15.0f);
    float e = __expf(2.0f * x);
    return __fdividef(e - 1.0f, e + 1.0f);
}

// packed f32x2 helpers (pairs carried in u64)
__device__ __forceinline__ u64 pack2(float x) {
    u64 d; asm("mov.b64 %0, {%1, %1};" : "=l"(d) : "f"(x)); return d;
}
__device__ __forceinline__ u64 pack2f(float lo, float hi) {
    u64 d; asm("mov.b64 %0, {%1, %2};" : "=l"(d) : "f"(lo), "f"(hi)); return d;
}
__device__ __forceinline__ void fma2(u64& acc, u64 a, u64 b) {
    asm("fma.rn.f32x2 %0, %1, %2, %0;" : "+l"(acc) : "l"(a), "l"(b));
}
__device__ __forceinline__ u64 add2(u64 a, u64 b) {
    u64 d; asm("add.rn.f32x2 %0, %1, %2;" : "=l"(d) : "l"(a), "l"(b)); return d;
}
__device__ __forceinline__ void unpack2(u64 d, float& lo, float& hi) {
    asm("mov.b64 {%0, %1}, %2;" : "=f"(lo), "=f"(hi) : "l"(d));
}

// cp.async helpers
#define CP_ASYNC16(dst, src) \
    asm volatile("cp.async.cg.shared.global [%0], [%1], 16;" :: "r"(dst), "l"(src))
#define CP_COMMIT() asm volatile("cp.async.commit_group;" ::: "memory")
#define CP_WAIT1()  asm volatile("cp.async.wait_group 1;" ::: "memory")

// 16B-granular swizzle within a 512B row (bit7 -> bit4)
__device__ __forceinline__ uint32_t swz(uint32_t off) { return off ^ ((off >> 3) & 0x10); }

// ---------------------------------------------------------------------------
// Prep 1: transpose input_vecs into At0[k][t] (rows >=770 zeroed here)
// ---------------------------------------------------------------------------
__global__ void transpose_in(const float* __restrict__ inp)
{
    __shared__ float tile[32][33];
    const int kt = blockIdx.x * 32;
    const int tt = blockIdx.y * 32;
    const int x = threadIdx.x, y = threadIdx.y;   // 32 x 8
#pragma unroll
    for (int i = 0; i < 32; i += 8) {
        int t = tt + y + i, k = kt + x;
        tile[y + i][x] = (k < 770) ? inp[(size_t)t * 770 + k] : 0.0f;
    }
    __syncthreads();
#pragma unroll
    for (int i = 0; i < 32; i += 8) {
        int k = kt + y + i, t = tt + x;
        At0[(size_t)k * T_ + t] = tile[x][y + i];
    }
}

// Prep 2: dp rows 770..773 of At0
__global__ void dp_rows(const float* __restrict__ dp_table, const int* __restrict__ dp_in)
{
    const int t = blockIdx.x * 256 + threadIdx.x;
    const int dpo = dp_in[t] * 4;
#pragma unroll
    for (int j = 0; j < 4; j++)
        At0[(size_t)(770 + j) * T_ + t] = dp_table[dpo + j];
}

// Prep 3: weights to k-major with the n-permutation baked in.
// n = (dir<<7)|(l<<2)|p  ->  weight row = dir*128 + p*32 + l
__global__ void prep_w(const float* __restrict__ Wih0, const float* __restrict__ Wih1)
{
    const int k = blockIdx.x;       // 0..799
    const int n = threadIdx.x;      // 0..255
    const int dir = n >> 7, l = (n & 127) >> 2, p = n & 3;
    const int row = dir * 128 + p * 32 + l;
    Wt0[k * 256 + n] = (k < 774) ? Wih0[(size_t)row * 774 + k] : 0.0f;
    if (k < 64) Wt1[k * 256 + n] = Wih1[(size_t)row * 64 + k];
}

// ---------------------------------------------------------------------------
// Gate GEMM: 128t x 128n x 32k tiles, 256 threads, 8x8 frags, f32x2 math.
// Both operands k-major in gmem -> pure cp.async staging, 3-stage pipeline,
// one __syncthreads per 32-kk tile. Fragment layout identical to R9 (passed):
// As[kk][m] plain rows; Bs[kk][n] swz-swizzled rows (swizzle applied in the
// cp.async dst), fragment n-pair ulonglong2 loads are FFMA2-ready; A
// duplicated in registers via pack2.
// ---------------------------------------------------------------------------
template<int NT>
__global__ __launch_bounds__(256, 2)
void gemm_gates(const float* __restrict__ At, const float* __restrict__ Wt)
{
    __shared__ __align__(16) float As[3][32][128];
    __shared__ __align__(16) float Bs[3][32][128];

    const int tid = threadIdx.x;
    const int t0 = blockIdx.x * 128;
    const int n0 = blockIdx.y * 128;

    const int wid = tid >> 5, lane = tid & 31;
    const int wm = wid & 3, wn = wid >> 2;     // 4x2 warp grid
    const int lm = lane & 3, ln = lane >> 2;   // 4x8 lane grid
    const int m_t = wm * 32 + lm * 8;
    const int n_t = wn * 64 + ln * 8;

    const uint32_t a_off = (uint32_t)m_t * 4;
    const uint32_t nt4 = (uint32_t)n_t * 4;
    const uint32_t b_o0 = swz(nt4), b_o1 = swz(nt4 + 16);

    // loader roles: row lr (0..31), chunk lane lc (0..7); 4 chunks each
    const int lr = tid >> 3;
    const int lc = tid & 7;
    const float* __restrict__ a_src = At + (size_t)lr * T_ + t0 + lc * 4;
    const float* __restrict__ b_src = Wt + (size_t)lr * 256 + n0 + lc * 4;

    uint32_t a_dst[3], b_dst[3];
#pragma unroll
    for (int b = 0; b < 3; b++) {
        a_dst[b] = (uint32_t)__cvta_generic_to_shared(&As[b][lr][lc * 4]);
        b_dst[b] = (uint32_t)__cvta_generic_to_shared((char*)&Bs[b][lr][0]) ;
    }

    auto issue_stage = [&](int s) {
        if (s < NT) {
            const int buf = s % 3;
            const float* ap = a_src + (size_t)s * 32 * T_;
            const float* bp = b_src + (size_t)s * 32 * 256;
#pragma unroll
            for (int i = 0; i < 4; i++)
                CP_ASYNC16(a_dst[buf] + i * 128, ap + i * 32);
#pragma unroll
            for (int i = 0; i < 4; i++) {
                uint32_t inrow = (uint32_t)lc * 16 + i * 128;
                CP_ASYNC16(b_dst[buf] + swz(inrow), bp + i * 32);
            }
        }
        CP_COMMIT();
    };

    u64 acc[8][4];
#pragma unroll
    for (int m = 0; m < 8; m++)
#pragma unroll
        for (int np = 0; np < 4; np++) acc[m][np] = 0ull;

    issue_stage(0);
    issue_stage(1);

    for (int s = 0; s < NT; s++) {
        CP_WAIT1();            // stage s complete (<=1 pending: s+1)
        __syncthreads();       // all threads' stage-s data visible; compute(s-1) done everywhere
        issue_stage(s + 2);    // overwrites stage s-1's buffer (safe after barrier)

        const int buf = s % 3;
#pragma unroll
        for (int kk = 0; kk < 32; kk++) {
            const char* arow = (const char*)&As[buf][kk][0];
            float4 a0 = *(const float4*)(arow + a_off);
            float4 a1 = *(const float4*)(arow + a_off + 16);
            const char* brow = (const char*)&Bs[buf][kk][0];
            ulonglong2 b01 = *(const ulonglong2*)(brow + b_o0);
            ulonglong2 b23 = *(const ulonglong2*)(brow + b_o1);
            u64 bb[4] = {b01.x, b01.y, b23.x, b23.y};
            u64 pa[8];
            pa[0] = pack2(a0.x); pa[1] = pack2(a0.y);
            pa[2] = pack2(a0.z); pa[3] = pack2(a0.w);
            pa[4] = pack2(a1.x); pa[5] = pack2(a1.y);
            pa[6] = pack2(a1.z); pa[7] = pack2(a1.w);
#pragma unroll
            for (int m = 0; m < 8; m++)
#pragma unroll
                for (int np = 0; np < 4; np++)
                    fma2(acc[m][np], pa[m], bb[np]);
        }
    }

    // epilogue: acc[m][np] -> row t0+m_t+m, cols n_t+2np (lo), n_t+2np+1 (hi)
#pragma unroll
    for (int m = 0; m < 8; m++) {
        float v[8];
#pragma unroll
        for (int np = 0; np < 4; np++) unpack2(acc[m][np], v[2 * np], v[2 * np + 1]);
        float* orow = g_buf + (size_t)(t0 + m_t + m) * 256 + n0 + n_t;
        *(float4*)orow       = make_float4(v[0], v[1], v[2], v[3]);
        *(float4*)(orow + 4) = make_float4(v[4], v[5], v[6], v[7]);
    }
}

// ---------------------------------------------------------------------------
// Chunked LSTM recurrence, one warp per (chunk, dir). Bias seeds the second
// fma chain. g_buf prefetch ring depth 3. Layer0 writes h0T transposed
// (feeds the cp.async layer-1 GEMM); layer1 writes h1_buf row-major.
// ---------------------------------------------------------------------------
__global__ __launch_bounds__(128, 3)
void lstm_rec(const float* __restrict__ Whh, const float* __restrict__ bias, int layer)
{
    const int wglob = (blockIdx.x * blockDim.x + threadIdx.x) >> 5;
    const int lane  = threadIdx.x & 31;
    const int dir   = wglob & 1;
    const int chunk = wglob >> 1;
    if (chunk >= NCHUNK) return;

    // layer0: h0T[(dir*32+lane)][t]; layer1: h1_buf[t][dir*32+lane]
    float* outp  = layer ? (h1_buf + dir * 32 + lane) : (h0T + (size_t)(dir * 32 + lane) * T_);
    const int ostr = layer ? 64 : 1;

    u64 w01[32], w23[32];
    const float* Wd = Whh + dir * 4096;
#pragma unroll
    for (int k = 0; k < 32; k++) {
        w01[k] = pack2f(Wd[(lane)      * 32 + k], Wd[(32 + lane) * 32 + k]);
        w23[k] = pack2f(Wd[(64 + lane) * 32 + k], Wd[(96 + lane) * 32 + k]);
    }
    const float* bd = bias + dir * 128;
    const u64 b01 = pack2f(bd[lane], bd[32 + lane]);
    const u64 b23 = pack2f(bd[64 + lane], bd[96 + lane]);

    const int lo = chunk * LCHUNK;
    const int hi = lo + LCHUNK;
    float h = 0.0f, c = 0.0f;

    if (dir == 0) {
        int tb = lo - WARMUP; if (tb < 0) tb = 0;
        const float* gbase = g_buf + lane * 4;
        ulonglong2 r0 = *(const ulonglong2*)(gbase + (size_t)tb * 256);
        int t1c = tb + 1 < hi ? tb + 1 : hi - 1;
        int t2c = tb + 2 < hi ? tb + 2 : hi - 1;
        ulonglong2 r1 = *(const ulonglong2*)(gbase + (size_t)t1c * 256);
        ulonglong2 r2 = *(const ulonglong2*)(gbase + (size_t)t2c * 256);
        for (int t = tb; t < hi; ++t) {
            ulonglong2 cur = r0; r0 = r1; r1 = r2;
            int tn = t + 3 < hi ? t + 3 : hi - 1;
            r2 = *(const ulonglong2*)(gbase + (size_t)tn * 256);
            u64 g01a = cur.x, g01b = b01;
            u64 g23a = cur.y, g23b = b23;
#pragma unroll
            for (int k = 0; k < 32; k += 2) {
                u64 p0 = pack2(__shfl_sync(0xffffffffu, h, k));
                u64 p1 = pack2(__shfl_sync(0xffffffffu, h, k + 1));
                fma2(g01a, w01[k], p0);  fma2(g01b, w01[k + 1], p1);
                fma2(g23a, w23[k], p0);  fma2(g23b, w23[k + 1], p1);
            }
            float gi, gf, gg, go;
            unpack2(add2(g01a, g01b), gi, gf);
            unpack2(add2(g23a, g23b), gg, go);
            c = sigf(gf) * c + sigf(gi) * tanhfast(gg);
            h = sigf(go) * tanhfast(c);
            if (t >= lo) outp[(size_t)t * ostr] = h;
        }
    } else {
        int tb = hi - 1 + WARMUP; if (tb > T_ - 1) tb = T_ - 1;
        const float* gbase = g_buf + 128 + lane * 4;
        ulonglong2 r0 = *(const ulonglong2*)(gbase + (size_t)tb * 256);
        int t1c = tb - 1 >= lo ? tb - 1 : lo;
        int t2c = tb - 2 >= lo ? tb - 2 : lo;
        ulonglong2 r1 = *(const ulonglong2*)(gbase + (size_t)t1c * 256);
        ulonglong2 r2 = *(const ulonglong2*)(gbase + (size_t)t2c * 256);
        for (int t = tb; t >= lo; --t) {
            ulonglong2 cur = r0; r0 = r1; r1 = r2;
            int tn = t - 3 >= lo ? t - 3 : lo;
            r2 = *(const ulonglong2*)(gbase + (size_t)tn * 256);
            u64 g01a = cur.x, g01b = b01;
            u64 g23a = cur.y, g23b = b23;
#pragma unroll
            for (int k = 0; k < 32; k += 2) {
                u64 p0 = pack2(__shfl_sync(0xffffffffu, h, k));
                u64 p1 = pack2(__shfl_sync(0xffffffffu, h, k + 1));
                fma2(g01a, w01[k], p0);  fma2(g01b, w01[k + 1], p1);
                fma2(g23a, w23[k], p0);  fma2(g23b, w23[k + 1], p1);
            }
            float gi, gf, gg, go;
            unpack2(add2(g01a, g01b), gi, gf);
            unpack2(add2(g23a, g23b), gg, go);
            c = sigf(gf) * c + sigf(gi) * tanhfast(gg);
            h = sigf(go) * tanhfast(c);
            if (t < hi) outp[(size_t)t * ostr] = h;
        }
    }
}

// ---------------------------------------------------------------------------
// Output head: warp per timestep, W_out staged transposed in smem.
// ---------------------------------------------------------------------------
__global__ __launch_bounds__(256)
void out_kernel(const float* __restrict__ Wout, const float* __restrict__ bout,
                const int* __restrict__ mask, float* __restrict__ out)
{
    __shared__ float Ws[64][52];
    const int tid = threadIdx.x;
    for (int i = tid; i < NTAGS * 64; i += 256) {
        int tag = i >> 6, k = i & 63;
        Ws[k][tag] = Wout[i];
    }
    __syncthreads();

    const int lane = tid & 31;
    const int t = blockIdx.x * 8 + (tid >> 5);

    float h0 = h1_buf[(size_t)t * 64 + lane];
    float h1 = h1_buf[(size_t)t * 64 + 32 + lane];

    const bool hasB = (lane < NTAGS - 32);
    float accA = bout[lane];
    float accB = hasB ? bout[lane + 32] : 0.0f;

#pragma unroll
    for (int k = 0; k < 32; k++) {
        float hk = __shfl_sync(0xffffffffu, h0, k);
        accA = fmaf(Ws[k][lane], hk, accA);
        if (hasB) accB = fmaf(Ws[k][lane + 32], hk, accB);
    }
#pragma unroll
    for (int k = 0; k < 32; k++) {
        float hk = __shfl_sync(0xffffffffu, h1, k);
        accA = fmaf(Ws[32 + k][lane], hk, accA);
        if (hasB) accB = fmaf(Ws[32 + k][lane + 32], hk, accB);
    }

    if (lane == 17) accB = (mask[t] > 0) ? fminf(accB, 1.0f) : 1.0f;
    accA = fmaxf(accA, 0.0f);
    accB = fmaxf(accB, 0.0f);

    float vB = hasB ? accB : -1.0f;
    float m = fmaxf(accA, vB);
#pragma unroll
    for (int o = 16; o; o >>= 1) m = fmaxf(m, __shfl_xor_sync(0xffffffffu, m, o));
    float s = __expf(accA - m) + (hasB ? __expf(accB - m) : 0.0f);
#pragma unroll
    for (int o = 16; o; o >>= 1) s += __shfl_xor_sync(0xffffffffu, s, o);
    float inv = __fdividef(1.0f, s);

    out[(size_t)t * NTAGS + lane] = __expf(accA - m) * inv;
    if (hasB) out[(size_t)t * NTAGS + lane + 32] = __expf(accB - m) * inv;
}

// ---------------------------------------------------------------------------

extern "C" void kernel_launch(void* const* d_in, const int* in_sizes, int n_in,
                              void* d_out, int out_size)
{
    const float* input_vecs = (const float*)d_in[0];
    const float* dp_table   = (const float*)d_in[1];
    const float* Wih0       = (const float*)d_in[2];
    const float* Whh0       = (const float*)d_in[3];
    const float* b0         = (const float*)d_in[4];
    const float* Wih1       = (const float*)d_in[5];
    const float* Whh1       = (const float*)d_in[6];
    const float* b1         = (const float*)d_in[7];
    const float* Wout       = (const float*)d_in[8];
    const float* bout       = (const float*)d_in[9];
    const int*   dp_in      = (const int*)d_in[10];
    const int*   mask       = (const int*)d_in[11];
    float* out = (float*)d_out;

    const dim3 ggrid(T_ / 128, 2);
    const int rec_blocks = (2 * NCHUNK * 32) / 128;   // 512

    // device-global pointers for kernel args
    float *pAt0, *pH0T, *pWt0, *pWt1;
    cudaGetSymbolAddress((void**)&pAt0, At0);
    cudaGetSymbolAddress((void**)&pH0T, h0T);
    cudaGetSymbolAddress((void**)&pWt0, Wt0);
    cudaGetSymbolAddress((void**)&pWt1, Wt1);

    transpose_in<<<dim3(25, T_ / 32), dim3(32, 8)>>>(input_vecs);
    dp_rows<<<T_ / 256, 256>>>(dp_table, dp_in);
    prep_w<<<800, 256>>>(Wih0, Wih1);

    gemm_gates<25><<<ggrid, 256>>>(pAt0, pWt0);
    lstm_rec<<<rec_blocks, 128>>>(Whh0, b0, 0);
    gemm_gates<2><<<ggrid, 256>>>(pH0T, pWt1);
    lstm_rec<<<rec_blocks, 128>>>(Whh1, b1, 1);
    out_kernel<<<T_ / 8, 256>>>(Wout, bout, mask, out);
}

// round 11
// speedup vs baseline: 1.1988x; 1.0546x over previous
#include <cuda_runtime.h>
#include <cstdint>

#define T_ 32768
#define NTAGS 50
#define LCHUNK 32
#define WARMUP 48
#define NCHUNK (T_ / LCHUNK)

typedef unsigned long long u64;

// Scratch (static device globals; no runtime allocation)
__device__ float g_buf[(size_t)T_ * 256];   // gate projections [t][dir*128 + l*4 + p]
__device__ float h0_buf[(size_t)T_ * 64];   // layer0 output [t][dir*32 + lane]
__device__ float h1_buf[(size_t)T_ * 64];   // layer1 output
__device__ float Wt0[800 * 256];            // k-major permuted Wih0 (zero-padded 774->800)
__device__ float Wt1[64 * 256];             // k-major permuted Wih1

__device__ __forceinline__ float sigf(float x) {
    return __fdividef(1.0f, 1.0f + __expf(-x));
}
__device__ __forceinline__ float tanhfast(float x) {
    x = fminf(fmaxf(x, -15.0f), 15.0f);
    float e = __expf(2.0f * x);
    return __fdividef(e - 1.0f, e + 1.0f);
}

// packed f32x2 helpers (pairs carried in u64)
__device__ __forceinline__ u64 pack2(float x) {
    u64 d; asm("mov.b64 %0, {%1, %1};" : "=l"(d) : "f"(x)); return d;
}
__device__ __forceinline__ u64 pack2f(float lo, float hi) {
    u64 d; asm("mov.b64 %0, {%1, %2};" : "=l"(d) : "f"(lo), "f"(hi)); return d;
}
__device__ __forceinline__ void fma2(u64& acc, u64 a, u64 b) {
    asm("fma.rn.f32x2 %0, %1, %2, %0;" : "+l"(acc) : "l"(a), "l"(b));
}
__device__ __forceinline__ u64 add2(u64 a, u64 b) {
    u64 d; asm("add.rn.f32x2 %0, %1, %2;" : "=l"(d) : "l"(a), "l"(b)); return d;
}
__device__ __forceinline__ void unpack2(u64 d, float& lo, float& hi) {
    asm("mov.b64 {%0, %1}, %2;" : "=f"(lo), "=f"(hi) : "l"(d));
}

// cp.async helpers
#define CP_ASYNC16(dst, src) \
    asm volatile("cp.async.cg.shared.global [%0], [%1], 16;" :: "r"(dst), "l"(src))
#define CP_COMMIT() asm volatile("cp.async.commit_group;" ::: "memory")
#define CP_WAIT0()  asm volatile("cp.async.wait_group 0;" ::: "memory")

// ---------------------------------------------------------------------------
// Prep: weights to k-major with the n-permutation baked in.
// n = (dir<<7)|(l<<2)|p  ->  weight row = dir*128 + p*32 + l
// ---------------------------------------------------------------------------
__global__ void prep_w(const float* __restrict__ Wih0, const float* __restrict__ Wih1)
{
    const int k = blockIdx.x;       // 0..799
    const int n = threadIdx.x;      // 0..255
    const int dir = n >> 7, l = (n & 127) >> 2, p = n & 3;
    const int row = dir * 128 + p * 32 + l;
    Wt0[k * 256 + n] = (k < 774) ? Wih0[(size_t)row * 774 + k] : 0.0f;
    if (k < 64) Wt1[k * 256 + n] = Wih1[(size_t)row * 64 + k];
}

// ---------------------------------------------------------------------------
// Gate GEMM: 128t x 256n x 32k tiles, 512 threads, 8x8 frags, f32x2 math.
// B: 2-stage cp.async straight from k-major Wt (L2-resident).
// A: row-major gmem, LDG->reg->STS pipelined (LDG(s+2) under compute(s+1),
// STS(s+1) after compute(s)). One __syncthreads per 32-kk tile.
// Fragment math identical to R9/R10 (verified): A dup in regs via pack2,
// B n-pair ulonglong2 loads FFMA2-ready. All smem accesses conflict-free
// by construction (no swizzle needed with these offsets).
// ---------------------------------------------------------------------------
template<int CONCAT>
__global__ __launch_bounds__(512)
void gemm_gates(const float* __restrict__ Ain, const float* __restrict__ dp_table,
                const int* __restrict__ dp_in, const float* __restrict__ Wt)
{
    constexpr int NT = CONCAT ? 25 : 2;     // K padded: 800 or 64
    constexpr int AROW = CONCAT ? 770 : 64;

    __shared__ __align__(16) float As[2][32][128];   // 32KB
    __shared__ __align__(16) float Bs[2][32][256];   // 64KB

    const int tid = threadIdx.x;
    const int t0 = blockIdx.x * 128;

    const int wid = tid >> 5, lane = tid & 31;
    const int wm = wid & 3, wn = wid >> 2;      // 4x4 warp grid
    const int lm = lane & 3, ln = lane >> 2;    // 4x8 lane grid
    const int m_t = wm * 32 + lm * 8;
    const int n_t = wn * 64 + ln * 8;

    const uint32_t a_off = (uint32_t)m_t * 4;
    const uint32_t b_off = (uint32_t)n_t * 4;

    // A loader: row m_a (0..127), k offset ha (0,8,16,24)
    const int m_a = tid >> 2;
    const int ha  = (tid & 3) * 8;
    // B loader: k row lr (0..31), lane lc (0..15), 4 x 16B chunks
    const int lr = tid >> 4;
    const int lc = tid & 15;

    const float* __restrict__ a_base = Ain + (size_t)(t0 + m_a) * AROW + ha;
    const float* __restrict__ b_base = Wt + (size_t)lr * 256 + lc * 4;
    const int dpo = CONCAT ? (dp_in[t0 + m_a] * 4) : 0;

    uint32_t b_dst[2];
    b_dst[0] = (uint32_t)__cvta_generic_to_shared(&Bs[0][lr][lc * 4]);
    b_dst[1] = (uint32_t)__cvta_generic_to_shared(&Bs[1][lr][lc * 4]);

    float ar[8];
    auto loadA = [&](int k0) {
        if (!CONCAT || (k0 + ha + 8) <= 770) {
            const float* ap = a_base + k0;
#pragma unroll
            for (int j = 0; j < 4; j++) {          // rows only 8B-aligned
                float2 v = *(const float2*)(ap + 2 * j);
                ar[2 * j] = v.x; ar[2 * j + 1] = v.y;
            }
        } else {                                   // last CONCAT tile (k0=768)
#pragma unroll
            for (int j = 0; j < 8; j++) {
                int k = k0 + ha + j;
                float v = 0.0f;
                if (k < 770)      v = Ain[(size_t)(t0 + m_a) * 770 + k];
                else if (k < 774) v = dp_table[dpo + (k - 770)];
                ar[j] = v;
            }
        }
    };
    auto stsA = [&](int buf) {
#pragma unroll
        for (int j = 0; j < 8; j++) As[buf][ha + j][m_a] = ar[j];
    };
    auto issueB = [&](int s, int buf) {
        const float* bp = b_base + (size_t)s * 32 * 256;
#pragma unroll
        for (int i = 0; i < 4; i++)
            CP_ASYNC16(b_dst[buf] + i * 256, bp + i * 64);
        CP_COMMIT();
    };

    u64 acc[8][4];
#pragma unroll
    for (int m = 0; m < 8; m++)
#pragma unroll
        for (int np = 0; np < 4; np++) acc[m][np] = 0ull;

    // prologue: stage 0 staged; A regs preloaded for stage 1
    loadA(0);
    stsA(0);
    issueB(0, 0);
    if (NT > 1) loadA(32);
    CP_WAIT0();
    __syncthreads();

    for (int s = 0; s < NT; s++) {
        const int buf = s & 1;
        if (s + 1 < NT) issueB(s + 1, buf ^ 1);

#pragma unroll
        for (int kk = 0; kk < 32; kk++) {
            const char* arow = (const char*)&As[buf][kk][0];
            float4 a0 = *(const float4*)(arow + a_off);
            float4 a1 = *(const float4*)(arow + a_off + 16);
            const char* brow = (const char*)&Bs[buf][kk][0];
            ulonglong2 b01 = *(const ulonglong2*)(brow + b_off);
            ulonglong2 b23 = *(const ulonglong2*)(brow + b_off + 16);
            u64 bb[4] = {b01.x, b01.y, b23.x, b23.y};
            u64 pa[8];
            pa[0] = pack2(a0.x); pa[1] = pack2(a0.y);
            pa[2] = pack2(a0.z); pa[3] = pack2(a0.w);
            pa[4] = pack2(a1.x); pa[5] = pack2(a1.y);
            pa[6] = pack2(a1.z); pa[7] = pack2(a1.w);
#pragma unroll
            for (int m = 0; m < 8; m++)
#pragma unroll
                for (int np = 0; np < 4; np++)
                    fma2(acc[m][np], pa[m], bb[np]);
        }

        if (s + 1 < NT) {
            stsA(buf ^ 1);                     // stage s+1 into the free buffer
            if (s + 2 < NT) loadA((s + 2) * 32);  // LDG for s+2, lands during compute(s+1)
        }
        CP_WAIT0();
        __syncthreads();
    }

    // epilogue: acc[m][np] -> row t0+m_t+m, cols n_t+2np (lo), n_t+2np+1 (hi)
#pragma unroll
    for (int m = 0; m < 8; m++) {
        float v[8];
#pragma unroll
        for (int np = 0; np < 4; np++) unpack2(acc[m][np], v[2 * np], v[2 * np + 1]);
        float* orow = g_buf + (size_t)(t0 + m_t + m) * 256 + n_t;
        *(float4*)orow       = make_float4(v[0], v[1], v[2], v[3]);
        *(float4*)(orow + 4) = make_float4(v[4], v[5], v[6], v[7]);
    }
}

// ---------------------------------------------------------------------------
// Chunked LSTM recurrence, one warp per (chunk, dir). Bias seeds the second
// fma chain. g_buf prefetch ring depth 3 hides load latency.
// ---------------------------------------------------------------------------
__global__ __launch_bounds__(128, 3)
void lstm_rec(const float* __restrict__ Whh, const float* __restrict__ bias, int layer)
{
    const int wglob = (blockIdx.x * blockDim.x + threadIdx.x) >> 5;
    const int lane  = threadIdx.x & 31;
    const int dir   = wglob & 1;
    const int chunk = wglob >> 1;
    if (chunk >= NCHUNK) return;

    float* hout = layer ? h1_buf : h0_buf;

    u64 w01[32], w23[32];
    const float* Wd = Whh + dir * 4096;
#pragma unroll
    for (int k = 0; k < 32; k++) {
        w01[k] = pack2f(Wd[(lane)      * 32 + k], Wd[(32 + lane) * 32 + k]);
        w23[k] = pack2f(Wd[(64 + lane) * 32 + k], Wd[(96 + lane) * 32 + k]);
    }
    const float* bd = bias + dir * 128;
    const u64 b01 = pack2f(bd[lane], bd[32 + lane]);
    const u64 b23 = pack2f(bd[64 + lane], bd[96 + lane]);

    const int lo = chunk * LCHUNK;
    const int hi = lo + LCHUNK;
    float h = 0.0f, c = 0.0f;

    if (dir == 0) {
        int tb = lo - WARMUP; if (tb < 0) tb = 0;
        const float* gbase = g_buf + lane * 4;
        ulonglong2 r0 = *(const ulonglong2*)(gbase + (size_t)tb * 256);
        int t1c = tb + 1 < hi ? tb + 1 : hi - 1;
        int t2c = tb + 2 < hi ? tb + 2 : hi - 1;
        ulonglong2 r1 = *(const ulonglong2*)(gbase + (size_t)t1c * 256);
        ulonglong2 r2 = *(const ulonglong2*)(gbase + (size_t)t2c * 256);
        for (int t = tb; t < hi; ++t) {
            ulonglong2 cur = r0; r0 = r1; r1 = r2;
            int tn = t + 3 < hi ? t + 3 : hi - 1;
            r2 = *(const ulonglong2*)(gbase + (size_t)tn * 256);
            u64 g01a = cur.x, g01b = b01;
            u64 g23a = cur.y, g23b = b23;
#pragma unroll
            for (int k = 0; k < 32; k += 2) {
                u64 p0 = pack2(__shfl_sync(0xffffffffu, h, k));
                u64 p1 = pack2(__shfl_sync(0xffffffffu, h, k + 1));
                fma2(g01a, w01[k], p0);  fma2(g01b, w01[k + 1], p1);
                fma2(g23a, w23[k], p0);  fma2(g23b, w23[k + 1], p1);
            }
            float gi, gf, gg, go;
            unpack2(add2(g01a, g01b), gi, gf);
            unpack2(add2(g23a, g23b), gg, go);
            c = sigf(gf) * c + sigf(gi) * tanhfast(gg);
            h = sigf(go) * tanhfast(c);
            if (t >= lo) hout[(size_t)t * 64 + lane] = h;
        }
    } else {
        int tb = hi - 1 + WARMUP; if (tb > T_ - 1) tb = T_ - 1;
        const float* gbase = g_buf + 128 + lane * 4;
        ulonglong2 r0 = *(const ulonglong2*)(gbase + (size_t)tb * 256);
        int t1c = tb - 1 >= lo ? tb - 1 : lo;
        int t2c = tb - 2 >= lo ? tb - 2 : lo;
        ulonglong2 r1 = *(const ulonglong2*)(gbase + (size_t)t1c * 256);
        ulonglong2 r2 = *(const ulonglong2*)(gbase + (size_t)t2c * 256);
        for (int t = tb; t >= lo; --t) {
            ulonglong2 cur = r0; r0 = r1; r1 = r2;
            int tn = t - 3 >= lo ? t - 3 : lo;
            r2 = *(const ulonglong2*)(gbase + (size_t)tn * 256);
            u64 g01a = cur.x, g01b = b01;
            u64 g23a = cur.y, g23b = b23;
#pragma unroll
            for (int k = 0; k < 32; k += 2) {
                u64 p0 = pack2(__shfl_sync(0xffffffffu, h, k));
                u64 p1 = pack2(__shfl_sync(0xffffffffu, h, k + 1));
                fma2(g01a, w01[k], p0);  fma2(g01b, w01[k + 1], p1);
                fma2(g23a, w23[k], p0);  fma2(g23b, w23[k + 1], p1);
            }
            float gi, gf, gg, go;
            unpack2(add2(g01a, g01b), gi, gf);
            unpack2(add2(g23a, g23b), gg, go);
            c = sigf(gf) * c + sigf(gi) * tanhfast(gg);
            h = sigf(go) * tanhfast(c);
            if (t < hi) hout[(size_t)t * 64 + 32 + lane] = h;
        }
    }
}

// ---------------------------------------------------------------------------
// Output head: warp per timestep, W_out staged transposed in smem.
// ---------------------------------------------------------------------------
__global__ __launch_bounds__(256)
void out_kernel(const float* __restrict__ Wout, const float* __restrict__ bout,
                const int* __restrict__ mask, float* __restrict__ out)
{
    __shared__ float Ws[64][52];
    const int tid = threadIdx.x;
    for (int i = tid; i < NTAGS * 64; i += 256) {
        int tag = i >> 6, k = i & 63;
        Ws[k][tag] = Wout[i];
    }
    __syncthreads();

    const int lane = tid & 31;
    const int t = blockIdx.x * 8 + (tid >> 5);

    float h0 = h1_buf[(size_t)t * 64 + lane];
    float h1 = h1_buf[(size_t)t * 64 + 32 + lane];

    const bool hasB = (lane < NTAGS - 32);
    float accA = bout[lane];
    float accB = hasB ? bout[lane + 32] : 0.0f;

#pragma unroll
    for (int k = 0; k < 32; k++) {
        float hk = __shfl_sync(0xffffffffu, h0, k);
        accA = fmaf(Ws[k][lane], hk, accA);
        if (hasB) accB = fmaf(Ws[k][lane + 32], hk, accB);
    }
#pragma unroll
    for (int k = 0; k < 32; k++) {
        float hk = __shfl_sync(0xffffffffu, h1, k);
        accA = fmaf(Ws[32 + k][lane], hk, accA);
        if (hasB) accB = fmaf(Ws[32 + k][lane + 32], hk, accB);
    }

    if (lane == 17) accB = (mask[t] > 0) ? fminf(accB, 1.0f) : 1.0f;
    accA = fmaxf(accA, 0.0f);
    accB = fmaxf(accB, 0.0f);

    float vB = hasB ? accB : -1.0f;
    float m = fmaxf(accA, vB);
#pragma unroll
    for (int o = 16; o; o >>= 1) m = fmaxf(m, __shfl_xor_sync(0xffffffffu, m, o));
    float s = __expf(accA - m) + (hasB ? __expf(accB - m) : 0.0f);
#pragma unroll
    for (int o = 16; o; o >>= 1) s += __shfl_xor_sync(0xffffffffu, s, o);
    float inv = __fdividef(1.0f, s);

    out[(size_t)t * NTAGS + lane] = __expf(accA - m) * inv;
    if (hasB) out[(size_t)t * NTAGS + lane + 32] = __expf(accB - m) * inv;
}

// ---------------------------------------------------------------------------

extern "C" void kernel_launch(void* const* d_in, const int* in_sizes, int n_in,
                              void* d_out, int out_size)
{
    const float* input_vecs = (const float*)d_in[0];
    const float* dp_table   = (const float*)d_in[1];
    const float* Wih0       = (const float*)d_in[2];
    const float* Whh0       = (const float*)d_in[3];
    const float* b0         = (const float*)d_in[4];
    const float* Wih1       = (const float*)d_in[5];
    const float* Whh1       = (const float*)d_in[6];
    const float* b1         = (const float*)d_in[7];
    const float* Wout       = (const float*)d_in[8];
    const float* bout       = (const float*)d_in[9];
    const int*   dp_in      = (const int*)d_in[10];
    const int*   mask       = (const int*)d_in[11];
    float* out = (float*)d_out;

    float *pH0, *pWt0, *pWt1;
    cudaGetSymbolAddress((void**)&pH0, h0_buf);
    cudaGetSymbolAddress((void**)&pWt0, Wt0);
    cudaGetSymbolAddress((void**)&pWt1, Wt1);

    const int rec_blocks = (2 * NCHUNK * 32) / 128;   // 512

    prep_w<<<800, 256>>>(Wih0, Wih1);
    gemm_gates<1><<<T_ / 128, 512>>>(input_vecs, dp_table, dp_in, pWt0);
    lstm_rec<<<rec_blocks, 128>>>(Whh0, b0, 0);
    gemm_gates<0><<<T_ / 128, 512>>>(pH0, nullptr, nullptr, pWt1);
    lstm_rec<<<rec_blocks, 128>>>(Whh1, b1, 1);
    out_kernel<<<T_ / 8, 256>>>(Wout, bout, mask, out);
}

// round 12
// speedup vs baseline: 1.2180x; 1.0161x over previous
#include <cuda_runtime.h>
#include <cstdint>

#define T_ 32768
#define NTAGS 50
#define LCHUNK 64
#define WARMUP 48
#define NCHUNK (T_ / LCHUNK)

typedef unsigned long long u64;

// Scratch (static device globals; no runtime allocation)
__device__ float g_buf[(size_t)T_ * 256];   // gate projections [t][dir*128 + l*4 + p]
__device__ float h0_buf[(size_t)T_ * 64];   // layer0 output [t][dir*32 + lane]
__device__ float h1_buf[(size_t)T_ * 64];   // layer1 output
__device__ u64   Wt0p[400 * 256];           // k-PAIRED permuted Wih0: [kp][n] = (w[2kp],w[2kp+1])
__device__ u64   Wt1p[32 * 256];            // k-paired permuted Wih1

__device__ __forceinline__ float sigf(float x) {
    return __fdividef(1.0f, 1.0f + __expf(-x));
}
__device__ __forceinline__ float tanhfast(float x) {
    x = fminf(fmaxf(x, -15.0f), 15.0f);
    float e = __expf(2.0f * x);
    return __fdividef(e - 1.0f, e + 1.0f);
}

// packed f32x2 helpers (pairs carried in u64)
__device__ __forceinline__ u64 pack2(float x) {
    u64 d; asm("mov.b64 %0, {%1, %1};" : "=l"(d) : "f"(x)); return d;
}
__device__ __forceinline__ u64 pack2f(float lo, float hi) {
    u64 d; asm("mov.b64 %0, {%1, %2};" : "=l"(d) : "f"(lo), "f"(hi)); return d;
}
__device__ __forceinline__ void fma2(u64& acc, u64 a, u64 b) {
    asm("fma.rn.f32x2 %0, %1, %2, %0;" : "+l"(acc) : "l"(a), "l"(b));
}
__device__ __forceinline__ u64 add2(u64 a, u64 b) {
    u64 d; asm("add.rn.f32x2 %0, %1, %2;" : "=l"(d) : "l"(a), "l"(b)); return d;
}
__device__ __forceinline__ void unpack2(u64 d, float& lo, float& hi) {
    asm("mov.b64 {%0, %1}, %2;" : "=f"(lo), "=f"(hi) : "l"(d));
}

// cp.async helpers
#define CP_ASYNC16(dst, src) \
    asm volatile("cp.async.cg.shared.global [%0], [%1], 16;" :: "r"(dst), "l"(src))
#define CP_COMMIT() asm volatile("cp.async.commit_group;" ::: "memory")
#define CP_WAIT0()  asm volatile("cp.async.wait_group 0;" ::: "memory")

// 16B-chunk swizzle within 1KB rows: bit7 -> bit4 (involution, keeps 8B align)
__device__ __forceinline__ uint32_t swz(uint32_t off) { return off ^ ((off >> 3) & 0x10); }

// ---------------------------------------------------------------------------
// Prep: weights to k-PAIRED k-major with the n-permutation baked in.
// n = (dir<<7)|(l<<2)|p  ->  weight row = dir*128 + p*32 + l
// Wt0p[kp][n] = ( W[row][2kp], W[row][2kp+1] ), K zero-padded 774->800.
// ---------------------------------------------------------------------------
__global__ void prep_w(const float* __restrict__ Wih0, const float* __restrict__ Wih1)
{
    const int kp = blockIdx.x;      // 0..399
    const int n = threadIdx.x;      // 0..255
    const int dir = n >> 7, l = (n & 127) >> 2, p = n & 3;
    const int row = dir * 128 + p * 32 + l;
    const int k0 = 2 * kp, k1 = 2 * kp + 1;
    float w0 = (k0 < 774) ? Wih0[(size_t)row * 774 + k0] : 0.0f;
    float w1 = (k1 < 774) ? Wih0[(size_t)row * 774 + k1] : 0.0f;
    Wt0p[kp * 256 + n] = pack2f(w0, w1);
    if (kp < 32)
        Wt1p[kp * 256 + n] = pack2f(Wih1[(size_t)row * 64 + 2 * kp],
                                    Wih1[(size_t)row * 64 + 2 * kp + 1]);
}

// ---------------------------------------------------------------------------
// Gate GEMM, K-PAIRED f32x2: zero operand duplication.
// Tile 128t x 128n x 32k (16 kp), 512 threads, 8m x 4n u64 accs per thread.
// As2[kp][m], Bs2[kp][n]: u64 (k-pair) 1KB rows, swz-swizzled (conflict-free).
// acc halves hold even-k / odd-k partial sums; one add at the end.
// Inner loop per kp: 6 LDS.128 + 32 FFMA2 (84% fma mix cap).
// A: LDG->pack->STS pipelined; B: cp.async from pre-paired Wtp.
// ---------------------------------------------------------------------------
template<int CONCAT>
__global__ __launch_bounds__(512, 1)
void gemm_gates(const float* __restrict__ Ain, const float* __restrict__ dp_table,
                const int* __restrict__ dp_in, const u64* __restrict__ Wtp)
{
    constexpr int NT = CONCAT ? 25 : 2;     // stages of 32 k (K padded 800 / 64)
    constexpr int AROW = CONCAT ? 770 : 64;

    __shared__ __align__(16) u64 As2[2][16][128];   // 32KB
    __shared__ __align__(16) u64 Bs2[2][16][128];   // 32KB

    const int tid = threadIdx.x;
    const int t0 = blockIdx.x * 128;
    const int n0 = blockIdx.y * 128;

    const int wid = tid >> 5, lane = tid & 31;
    const int wm = wid & 3, wn = wid >> 2;      // 4x4 warp grid
    const int lm = lane & 3, ln = lane >> 2;    // 4x8 lane grid
    const int m_t = wm * 32 + lm * 8;           // 8 consecutive m rows
    const int n_t = wn * 32 + ln * 4;           // 4 consecutive n cols

    const uint32_t a_off = (uint32_t)m_t * 8;   // in-row byte offsets (u64 elems)
    const uint32_t b_off = (uint32_t)n_t * 8;
    const uint32_t ao[4] = { swz(a_off), swz(a_off + 16), swz(a_off + 32), swz(a_off + 48) };
    const uint32_t bo[2] = { swz(b_off), swz(b_off + 16) };

    // A loader: row m_a (0..127), k offset ha in {0,8,16,24}
    const int m_a = tid >> 2;
    const int ha  = (tid & 3) * 8;
    const uint32_t a_col = swz((uint32_t)m_a * 8);   // bit4 flip keeps 8B align
    // B loader: kp row lr (0..15), lane lc (0..31): 32B (2 chunks) per thread
    const int lr = tid >> 5;
    const int lc = tid & 31;

    const float* __restrict__ a_base = Ain + (size_t)(t0 + m_a) * AROW + ha;
    const char*  __restrict__ b_base = (const char*)(Wtp + (size_t)lr * 256 + n0) + lc * 32;
    const int dpo = CONCAT ? (dp_in[t0 + m_a] * 4) : 0;

    uint32_t b_dst[2];
    {
        uint32_t c0 = swz((uint32_t)lc * 32), c1 = swz((uint32_t)lc * 32 + 16);
        b_dst[0] = (uint32_t)__cvta_generic_to_shared((char*)&Bs2[0][lr][0]);
        b_dst[1] = (uint32_t)__cvta_generic_to_shared((char*)&Bs2[1][lr][0]);
        // store both chunk offsets by adding later; keep c0/c1 in regs via lambda capture
        b_dst[0] += 0; b_dst[1] += 0;
        // (chunk offsets applied in issueB)
    }
    const uint32_t bc0 = swz((uint32_t)lc * 32), bc1 = swz((uint32_t)lc * 32 + 16);

    float ar[8];
    auto loadA = [&](int k0) {
        if (!CONCAT || (k0 + ha + 8) <= 770) {
            const float* ap = a_base + k0;
#pragma unroll
            for (int j = 0; j < 4; j++) {          // rows only 8B-aligned
                float2 v = *(const float2*)(ap + 2 * j);
                ar[2 * j] = v.x; ar[2 * j + 1] = v.y;
            }
        } else {                                   // last CONCAT tile (k0=768)
#pragma unroll
            for (int j = 0; j < 8; j++) {
                int k = k0 + ha + j;
                float v = 0.0f;
                if (k < 770)      v = Ain[(size_t)(t0 + m_a) * 770 + k];
                else if (k < 774) v = dp_table[dpo + (k - 770)];
                ar[j] = v;
            }
        }
    };
    auto stsA = [&](int buf) {
#pragma unroll
        for (int j = 0; j < 4; j++) {
            char* row = (char*)&As2[buf][ha / 2 + j][0];
            *(u64*)(row + a_col) = pack2f(ar[2 * j], ar[2 * j + 1]);
        }
    };
    auto issueB = [&](int s, int buf) {
        const char* bp = b_base + (size_t)s * 16 * 2048;   // 16 kp rows x 2KB gmem rows
        CP_ASYNC16(b_dst[buf] + bc0, bp);
        CP_ASYNC16(b_dst[buf] + bc1, bp + 16);
        CP_COMMIT();
    };

    u64 acc[8][4];
#pragma unroll
    for (int m = 0; m < 8; m++)
#pragma unroll
        for (int n = 0; n < 4; n++) acc[m][n] = 0ull;

    // prologue
    loadA(0);
    stsA(0);
    issueB(0, 0);
    if (NT > 1) loadA(32);
    CP_WAIT0();
    __syncthreads();

    for (int s = 0; s < NT; s++) {
        const int buf = s & 1;
        if (s + 1 < NT) issueB(s + 1, buf ^ 1);

#pragma unroll
        for (int kp = 0; kp < 16; kp++) {
            const char* arow = (const char*)&As2[buf][kp][0];
            ulonglong2 a01 = *(const ulonglong2*)(arow + ao[0]);
            ulonglong2 a23 = *(const ulonglong2*)(arow + ao[1]);
            ulonglong2 a45 = *(const ulonglong2*)(arow + ao[2]);
            ulonglong2 a67 = *(const ulonglong2*)(arow + ao[3]);
            const char* brow = (const char*)&Bs2[buf][kp][0];
            ulonglong2 b01 = *(const ulonglong2*)(brow + bo[0]);
            ulonglong2 b23 = *(const ulonglong2*)(brow + bo[1]);
            u64 pa[8] = {a01.x, a01.y, a23.x, a23.y, a45.x, a45.y, a67.x, a67.y};
            u64 bb[4] = {b01.x, b01.y, b23.x, b23.y};
#pragma unroll
            for (int m = 0; m < 8; m++)
#pragma unroll
                for (int n = 0; n < 4; n++)
                    fma2(acc[m][n], pa[m], bb[n]);
        }

        if (s + 1 < NT) {
            stsA(buf ^ 1);
            if (s + 2 < NT) loadA((s + 2) * 32);
        }
        CP_WAIT0();
        __syncthreads();
    }

    // epilogue: result = lo(acc) + hi(acc); row t0+m_t+m, cols n0+n_t..+3
#pragma unroll
    for (int m = 0; m < 8; m++) {
        float v[4];
#pragma unroll
        for (int n = 0; n < 4; n++) {
            float lo, hi;
            unpack2(acc[m][n], lo, hi);
            v[n] = lo + hi;
        }
        float* orow = g_buf + (size_t)(t0 + m_t + m) * 256 + n0 + n_t;
        *(float4*)orow = make_float4(v[0], v[1], v[2], v[3]);
    }
}

// ---------------------------------------------------------------------------
// Chunked LSTM recurrence, one warp per (chunk, dir). Bias seeds the second
// fma chain. g_buf prefetch ring depth 3 hides load latency.
// ---------------------------------------------------------------------------
__global__ __launch_bounds__(128, 3)
void lstm_rec(const float* __restrict__ Whh, const float* __restrict__ bias, int layer)
{
    const int wglob = (blockIdx.x * blockDim.x + threadIdx.x) >> 5;
    const int lane  = threadIdx.x & 31;
    const int dir   = wglob & 1;
    const int chunk = wglob >> 1;
    if (chunk >= NCHUNK) return;

    float* hout = layer ? h1_buf : h0_buf;

    u64 w01[32], w23[32];
    const float* Wd = Whh + dir * 4096;
#pragma unroll
    for (int k = 0; k < 32; k++) {
        w01[k] = pack2f(Wd[(lane)      * 32 + k], Wd[(32 + lane) * 32 + k]);
        w23[k] = pack2f(Wd[(64 + lane) * 32 + k], Wd[(96 + lane) * 32 + k]);
    }
    const float* bd = bias + dir * 128;
    const u64 b01 = pack2f(bd[lane], bd[32 + lane]);
    const u64 b23 = pack2f(bd[64 + lane], bd[96 + lane]);

    const int lo = chunk * LCHUNK;
    const int hi = lo + LCHUNK;
    float h = 0.0f, c = 0.0f;

    if (dir == 0) {
        int tb = lo - WARMUP; if (tb < 0) tb = 0;
        const float* gbase = g_buf + lane * 4;
        ulonglong2 r0 = *(const ulonglong2*)(gbase + (size_t)tb * 256);
        int t1c = tb + 1 < hi ? tb + 1 : hi - 1;
        int t2c = tb + 2 < hi ? tb + 2 : hi - 1;
        ulonglong2 r1 = *(const ulonglong2*)(gbase + (size_t)t1c * 256);
        ulonglong2 r2 = *(const ulonglong2*)(gbase + (size_t)t2c * 256);
        for (int t = tb; t < hi; ++t) {
            ulonglong2 cur = r0; r0 = r1; r1 = r2;
            int tn = t + 3 < hi ? t + 3 : hi - 1;
            r2 = *(const ulonglong2*)(gbase + (size_t)tn * 256);
            u64 g01a = cur.x, g01b = b01;
            u64 g23a = cur.y, g23b = b23;
#pragma unroll
            for (int k = 0; k < 32; k += 2) {
                u64 p0 = pack2(__shfl_sync(0xffffffffu, h, k));
                u64 p1 = pack2(__shfl_sync(0xffffffffu, h, k + 1));
                fma2(g01a, w01[k], p0);  fma2(g01b, w01[k + 1], p1);
                fma2(g23a, w23[k], p0);  fma2(g23b, w23[k + 1], p1);
            }
            float gi, gf, gg, go;
            unpack2(add2(g01a, g01b), gi, gf);
            unpack2(add2(g23a, g23b), gg, go);
            c = sigf(gf) * c + sigf(gi) * tanhfast(gg);
            h = sigf(go) * tanhfast(c);
            if (t >= lo) hout[(size_t)t * 64 + lane] = h;
        }
    } else {
        int tb = hi - 1 + WARMUP; if (tb > T_ - 1) tb = T_ - 1;
        const float* gbase = g_buf + 128 + lane * 4;
        ulonglong2 r0 = *(const ulonglong2*)(gbase + (size_t)tb * 256);
        int t1c = tb - 1 >= lo ? tb - 1 : lo;
        int t2c = tb - 2 >= lo ? tb - 2 : lo;
        ulonglong2 r1 = *(const ulonglong2*)(gbase + (size_t)t1c * 256);
        ulonglong2 r2 = *(const ulonglong2*)(gbase + (size_t)t2c * 256);
        for (int t = tb; t >= lo; --t) {
            ulonglong2 cur = r0; r0 = r1; r1 = r2;
            int tn = t - 3 >= lo ? t - 3 : lo;
            r2 = *(const ulonglong2*)(gbase + (size_t)tn * 256);
            u64 g01a = cur.x, g01b = b01;
            u64 g23a = cur.y, g23b = b23;
#pragma unroll
            for (int k = 0; k < 32; k += 2) {
                u64 p0 = pack2(__shfl_sync(0xffffffffu, h, k));
                u64 p1 = pack2(__shfl_sync(0xffffffffu, h, k + 1));
                fma2(g01a, w01[k], p0);  fma2(g01b, w01[k + 1], p1);
                fma2(g23a, w23[k], p0);  fma2(g23b, w23[k + 1], p1);
            }
            float gi, gf, gg, go;
            unpack2(add2(g01a, g01b), gi, gf);
            unpack2(add2(g23a, g23b), gg, go);
            c = sigf(gf) * c + sigf(gi) * tanhfast(gg);
            h = sigf(go) * tanhfast(c);
            if (t < hi) hout[(size_t)t * 64 + 32 + lane] = h;
        }
    }
}

// ---------------------------------------------------------------------------
// Output head: warp per timestep, W_out staged transposed in smem.
// ---------------------------------------------------------------------------
__global__ __launch_bounds__(256)
void out_kernel(const float* __restrict__ Wout, const float* __restrict__ bout,
                const int* __restrict__ mask, float* __restrict__ out)
{
    __shared__ float Ws[64][52];
    const int tid = threadIdx.x;
    for (int i = tid; i < NTAGS * 64; i += 256) {
        int tag = i >> 6, k = i & 63;
        Ws[k][tag] = Wout[i];
    }
    __syncthreads();

    const int lane = tid & 31;
    const int t = blockIdx.x * 8 + (tid >> 5);

    float h0 = h1_buf[(size_t)t * 64 + lane];
    float h1 = h1_buf[(size_t)t * 64 + 32 + lane];

    const bool hasB = (lane < NTAGS - 32);
    float accA = bout[lane];
    float accB = hasB ? bout[lane + 32] : 0.0f;

#pragma unroll
    for (int k = 0; k < 32; k++) {
        float hk = __shfl_sync(0xffffffffu, h0, k);
        accA = fmaf(Ws[k][lane], hk, accA);
        if (hasB) accB = fmaf(Ws[k][lane + 32], hk, accB);
    }
#pragma unroll
    for (int k = 0; k < 32; k++) {
        float hk = __shfl_sync(0xffffffffu, h1, k);
        accA = fmaf(Ws[32 + k][lane], hk, accA);
        if (hasB) accB = fmaf(Ws[32 + k][lane + 32], hk, accB);
    }

    if (lane == 17) accB = (mask[t] > 0) ? fminf(accB, 1.0f) : 1.0f;
    accA = fmaxf(accA, 0.0f);
    accB = fmaxf(accB, 0.0f);

    float vB = hasB ? accB : -1.0f;
    float m = fmaxf(accA, vB);
#pragma unroll
    for (int o = 16; o; o >>= 1) m = fmaxf(m, __shfl_xor_sync(0xffffffffu, m, o));
    float s = __expf(accA - m) + (hasB ? __expf(accB - m) : 0.0f);
#pragma unroll
    for (int o = 16; o; o >>= 1) s += __shfl_xor_sync(0xffffffffu, s, o);
    float inv = __fdividef(1.0f, s);

    out[(size_t)t * NTAGS + lane] = __expf(accA - m) * inv;
    if (hasB) out[(size_t)t * NTAGS + lane + 32] = __expf(accB - m) * inv;
}

// ---------------------------------------------------------------------------

extern "C" void kernel_launch(void* const* d_in, const int* in_sizes, int n_in,
                              void* d_out, int out_size)
{
    const float* input_vecs = (const float*)d_in[0];
    const float* dp_table   = (const float*)d_in[1];
    const float* Wih0       = (const float*)d_in[2];
    const float* Whh0       = (const float*)d_in[3];
    const float* b0         = (const float*)d_in[4];
    const float* Wih1       = (const float*)d_in[5];
    const float* Whh1       = (const float*)d_in[6];
    const float* b1         = (const float*)d_in[7];
    const float* Wout       = (const float*)d_in[8];
    const float* bout       = (const float*)d_in[9];
    const int*   dp_in      = (const int*)d_in[10];
    const int*   mask       = (const int*)d_in[11];
    float* out = (float*)d_out;

    float* pH0;
    u64 *pWt0p, *pWt1p;
    cudaGetSymbolAddress((void**)&pH0, h0_buf);
    cudaGetSymbolAddress((void**)&pWt0p, Wt0p);
    cudaGetSymbolAddress((void**)&pWt1p, Wt1p);

    const dim3 ggrid(T_ / 128, 2);
    const int rec_blocks = (2 * NCHUNK * 32) / 128;   // 256

    prep_w<<<400, 256>>>(Wih0, Wih1);
    gemm_gates<1><<<ggrid, 512>>>(input_vecs, dp_table, dp_in, pWt0p);
    lstm_rec<<<rec_blocks, 128>>>(Whh0, b0, 0);
    gemm_gates<0><<<ggrid, 512>>>(pH0, nullptr, nullptr, pWt1p);
    lstm_rec<<<rec_blocks, 128>>>(Whh1, b1, 1);
    out_kernel<<<T_ / 8, 256>>>(Wout, bout, mask, out);
}

// round 13
// speedup vs baseline: 1.3824x; 1.1349x over previous
#include <cuda_runtime.h>
#include <cstdint>

#define T_ 32768
#define NTAGS 50
#define LCHUNK 32
#define WARMUP 48
#define NCHUNK (T_ / LCHUNK)

typedef unsigned long long u64;

// Scratch (static device globals; no runtime allocation).
// g_buf padded by 8 timesteps on both ends -> recurrence prefetch ring needs
// no bounds clamping (reads of pad garbage are never consumed).
__device__ float g_buf_raw[(size_t)(T_ + 16) * 256];
#define GBUF (g_buf_raw + 8 * 256)
__device__ float h0_buf[(size_t)T_ * 64];   // layer0 output [t][dir*32 + lane]
__device__ float h1_buf[(size_t)T_ * 64];   // layer1 output
__device__ float Wt0[800 * 256];            // k-major permuted Wih0 (zero-padded 774->800)
__device__ float Wt1[64 * 256];             // k-major permuted Wih1

__device__ __forceinline__ float sigf(float x) {
    return __fdividef(1.0f, 1.0f + __expf(-x));
}
__device__ __forceinline__ float tanhfast(float x) {
    x = fminf(fmaxf(x, -15.0f), 15.0f);
    float e = __expf(2.0f * x);
    return __fdividef(e - 1.0f, e + 1.0f);
}

// packed f32x2 helpers (pairs carried in u64)
__device__ __forceinline__ u64 pack2(float x) {
    u64 d; asm("mov.b64 %0, {%1, %1};" : "=l"(d) : "f"(x)); return d;
}
__device__ __forceinline__ u64 pack2f(float lo, float hi) {
    u64 d; asm("mov.b64 %0, {%1, %2};" : "=l"(d) : "f"(lo), "f"(hi)); return d;
}
__device__ __forceinline__ void fma2(u64& acc, u64 a, u64 b) {
    asm("fma.rn.f32x2 %0, %1, %2, %0;" : "+l"(acc) : "l"(a), "l"(b));
}
__device__ __forceinline__ u64 add2(u64 a, u64 b) {
    u64 d; asm("add.rn.f32x2 %0, %1, %2;" : "=l"(d) : "l"(a), "l"(b)); return d;
}
__device__ __forceinline__ void unpack2(u64 d, float& lo, float& hi) {
    asm("mov.b64 {%0, %1}, %2;" : "=f"(lo), "=f"(hi) : "l"(d));
}

// cp.async helpers
#define CP_ASYNC16(dst, src) \
    asm volatile("cp.async.cg.shared.global [%0], [%1], 16;" :: "r"(dst), "l"(src))
#define CP_COMMIT() asm volatile("cp.async.commit_group;" ::: "memory")
#define CP_WAIT0()  asm volatile("cp.async.wait_group 0;" ::: "memory")

// 16B-chunk swizzle: bit7 -> bit4 (involution, keeps 16B alignment)
__device__ __forceinline__ uint32_t swz(uint32_t off) { return off ^ ((off >> 3) & 0x10); }

// ---------------------------------------------------------------------------
// Prep: weights to k-major with the n-permutation baked in.
// n = (dir<<7)|(l<<2)|p  ->  weight row = dir*128 + p*32 + l
// ---------------------------------------------------------------------------
__global__ void prep_w(const float* __restrict__ Wih0, const float* __restrict__ Wih1)
{
    const int k = blockIdx.x;       // 0..799
    const int n = threadIdx.x;      // 0..255
    const int dir = n >> 7, l = (n & 127) >> 2, p = n & 3;
    const int row = dir * 128 + p * 32 + l;
    Wt0[k * 256 + n] = (k < 774) ? Wih0[(size_t)row * 774 + k] : 0.0f;
    if (k < 64) Wt1[k * 256 + n] = Wih1[(size_t)row * 64 + k];
}

// ---------------------------------------------------------------------------
// Gate GEMM (R11 config + Bs bank-conflict fix):
// 128t x 256n x 32k tiles, 512 threads, 8x8 frags, f32x2 math.
// B: 2-stage cp.async from k-major Wt, rows swz-swizzled (ln*32-stride
//    fragment loads verified conflict-free with the swizzle).
// A: row-major gmem, LDG->reg->STS pipelined. One barrier per 32-kk tile.
// A duplicated in registers via pack2; B n-pair ulonglong2 loads FFMA2-ready.
// ---------------------------------------------------------------------------
template<int CONCAT>
__global__ __launch_bounds__(512)
void gemm_gates(const float* __restrict__ Ain, const float* __restrict__ dp_table,
                const int* __restrict__ dp_in, const float* __restrict__ Wt)
{
    constexpr int NT = CONCAT ? 25 : 2;     // K padded: 800 or 64
    constexpr int AROW = CONCAT ? 770 : 64;

    __shared__ __align__(16) float As[2][32][128];   // 32KB
    __shared__ __align__(16) float Bs[2][32][256];   // 64KB (1KB rows, swizzled)

    const int tid = threadIdx.x;
    const int t0 = blockIdx.x * 128;

    const int wid = tid >> 5, lane = tid & 31;
    const int wm = wid & 3, wn = wid >> 2;      // 4x4 warp grid
    const int lm = lane & 3, ln = lane >> 2;    // 4x8 lane grid
    const int m_t = wm * 32 + lm * 8;
    const int n_t = wn * 64 + ln * 8;

    const uint32_t a_off = (uint32_t)m_t * 4;
    const uint32_t b_raw = (uint32_t)n_t * 4;
    const uint32_t b_o0 = swz(b_raw), b_o1 = swz(b_raw + 16);

    // A loader: row m_a (0..127), k offset ha (0,8,16,24)
    const int m_a = tid >> 2;
    const int ha  = (tid & 3) * 8;
    // B loader: k row lr (0..31), lane lc (0..15), 4 x 16B chunks
    const int lr = tid >> 4;
    const int lc = tid & 15;

    const float* __restrict__ a_base = Ain + (size_t)(t0 + m_a) * AROW + ha;
    const float* __restrict__ b_base = Wt + (size_t)lr * 256 + lc * 4;
    const int dpo = CONCAT ? (dp_in[t0 + m_a] * 4) : 0;

    uint32_t b_dst[2];
    b_dst[0] = (uint32_t)__cvta_generic_to_shared(&Bs[0][lr][0]);
    b_dst[1] = (uint32_t)__cvta_generic_to_shared(&Bs[1][lr][0]);
    uint32_t bco[4];
#pragma unroll
    for (int i = 0; i < 4; i++) bco[i] = swz((uint32_t)lc * 16 + i * 256);

    float ar[8];
    auto loadA = [&](int k0) {
        if (!CONCAT || (k0 + ha + 8) <= 770) {
            const float* ap = a_base + k0;
#pragma unroll
            for (int j = 0; j < 4; j++) {          // rows only 8B-aligned
                float2 v = *(const float2*)(ap + 2 * j);
                ar[2 * j] = v.x; ar[2 * j + 1] = v.y;
            }
        } else {                                   // last CONCAT tile (k0=768)
#pragma unroll
            for (int j = 0; j < 8; j++) {
                int k = k0 + ha + j;
                float v = 0.0f;
                if (k < 770)      v = Ain[(size_t)(t0 + m_a) * 770 + k];
                else if (k < 774) v = dp_table[dpo + (k - 770)];
                ar[j] = v;
            }
        }
    };
    auto stsA = [&](int buf) {
#pragma unroll
        for (int j = 0; j < 8; j++) As[buf][ha + j][m_a] = ar[j];
    };
    auto issueB = [&](int s, int buf) {
        const float* bp = b_base + (size_t)s * 32 * 256;
#pragma unroll
        for (int i = 0; i < 4; i++)
            CP_ASYNC16(b_dst[buf] + bco[i], bp + i * 64);
        CP_COMMIT();
    };

    u64 acc[8][4];
#pragma unroll
    for (int m = 0; m < 8; m++)
#pragma unroll
        for (int np = 0; np < 4; np++) acc[m][np] = 0ull;

    // prologue
    loadA(0);
    stsA(0);
    issueB(0, 0);
    if (NT > 1) loadA(32);
    CP_WAIT0();
    __syncthreads();

    for (int s = 0; s < NT; s++) {
        const int buf = s & 1;
        if (s + 1 < NT) issueB(s + 1, buf ^ 1);

#pragma unroll
        for (int kk = 0; kk < 32; kk++) {
            const char* arow = (const char*)&As[buf][kk][0];
            float4 a0 = *(const float4*)(arow + a_off);
            float4 a1 = *(const float4*)(arow + a_off + 16);
            const char* brow = (const char*)&Bs[buf][kk][0];
            ulonglong2 b01 = *(const ulonglong2*)(brow + b_o0);
            ulonglong2 b23 = *(const ulonglong2*)(brow + b_o1);
            u64 bb[4] = {b01.x, b01.y, b23.x, b23.y};
            u64 pa[8];
            pa[0] = pack2(a0.x); pa[1] = pack2(a0.y);
            pa[2] = pack2(a0.z); pa[3] = pack2(a0.w);
            pa[4] = pack2(a1.x); pa[5] = pack2(a1.y);
            pa[6] = pack2(a1.z); pa[7] = pack2(a1.w);
#pragma unroll
            for (int m = 0; m < 8; m++)
#pragma unroll
                for (int np = 0; np < 4; np++)
                    fma2(acc[m][np], pa[m], bb[np]);
        }

        if (s + 1 < NT) {
            stsA(buf ^ 1);
            if (s + 2 < NT) loadA((s + 2) * 32);
        }
        CP_WAIT0();
        __syncthreads();
    }

    // epilogue: acc[m][np] -> row t0+m_t+m, cols n_t+2np (lo), n_t+2np+1 (hi)
#pragma unroll
    for (int m = 0; m < 8; m++) {
        float v[8];
#pragma unroll
        for (int np = 0; np < 4; np++) unpack2(acc[m][np], v[2 * np], v[2 * np + 1]);
        float* orow = GBUF + (size_t)(t0 + m_t + m) * 256 + n_t;
        *(float4*)orow       = make_float4(v[0], v[1], v[2], v[3]);
        *(float4*)(orow + 4) = make_float4(v[4], v[5], v[6], v[7]);
    }
}

// ---------------------------------------------------------------------------
// Chunked LSTM recurrence, one warp per (chunk, dir).
// LCHUNK=32 (short serial chains, 2048 warps hide latency), 4-way fma chains
// (dep depth 8), unconditional depth-3 prefetch ring (g_buf padded).
// Bias seeds chain 1; chains 2,3 seed zero.
// ---------------------------------------------------------------------------
__global__ __launch_bounds__(128)
void lstm_rec(const float* __restrict__ Whh, const float* __restrict__ bias, int layer)
{
    const int wglob = (blockIdx.x * blockDim.x + threadIdx.x) >> 5;
    const int lane  = threadIdx.x & 31;
    const int dir   = wglob & 1;
    const int chunk = wglob >> 1;
    if (chunk >= NCHUNK) return;

    float* hout = layer ? h1_buf : h0_buf;

    u64 w01[32], w23[32];
    const float* Wd = Whh + dir * 4096;
#pragma unroll
    for (int k = 0; k < 32; k++) {
        w01[k] = pack2f(Wd[(lane)      * 32 + k], Wd[(32 + lane) * 32 + k]);
        w23[k] = pack2f(Wd[(64 + lane) * 32 + k], Wd[(96 + lane) * 32 + k]);
    }
    const float* bd = bias + dir * 128;
    const u64 b01 = pack2f(bd[lane], bd[32 + lane]);
    const u64 b23 = pack2f(bd[64 + lane], bd[96 + lane]);

    const int lo = chunk * LCHUNK;
    const int hi = lo + LCHUNK;
    float h = 0.0f, c = 0.0f;

    if (dir == 0) {
        int tb = lo - WARMUP; if (tb < 0) tb = 0;
        const float* gbase = GBUF + lane * 4;
        ulonglong2 r0 = *(const ulonglong2*)(gbase + (size_t)tb * 256);
        ulonglong2 r1 = *(const ulonglong2*)(gbase + (size_t)(tb + 1) * 256);
        ulonglong2 r2 = *(const ulonglong2*)(gbase + (size_t)(tb + 2) * 256);
        for (int t = tb; t < hi; ++t) {
            ulonglong2 cur = r0; r0 = r1; r1 = r2;
            r2 = *(const ulonglong2*)(gbase + (size_t)(t + 3) * 256);  // pad-safe
            u64 A01[4] = {cur.x, b01, 0ull, 0ull};
            u64 A23[4] = {cur.y, b23, 0ull, 0ull};
#pragma unroll
            for (int q = 0; q < 8; q++) {
#pragma unroll
                for (int j = 0; j < 4; j++) {
                    int k = j * 8 + q;
                    u64 p = pack2(__shfl_sync(0xffffffffu, h, k));
                    fma2(A01[j], w01[k], p);
                    fma2(A23[j], w23[k], p);
                }
            }
            float gi, gf, gg, go;
            unpack2(add2(add2(A01[0], A01[1]), add2(A01[2], A01[3])), gi, gf);
            unpack2(add2(add2(A23[0], A23[1]), add2(A23[2], A23[3])), gg, go);
            c = sigf(gf) * c + sigf(gi) * tanhfast(gg);
            h = sigf(go) * tanhfast(c);
            if (t >= lo) hout[(size_t)t * 64 + lane] = h;
        }
    } else {
        int tb = hi - 1 + WARMUP; if (tb > T_ - 1) tb = T_ - 1;
        const float* gbase = GBUF + 128 + lane * 4;
        ulonglong2 r0 = *(const ulonglong2*)(gbase + (size_t)tb * 256);
        ulonglong2 r1 = *(const ulonglong2*)(gbase + (size_t)(tb - 1) * 256);
        ulonglong2 r2 = *(const ulonglong2*)(gbase + (size_t)(tb - 2) * 256);
        for (int t = tb; t >= lo; --t) {
            ulonglong2 cur = r0; r0 = r1; r1 = r2;
            r2 = *(const ulonglong2*)(gbase + ((size_t)(t - 3) + 8) * 256 - 8 * 256); // pad-safe (t-3 >= -3)
            u64 A01[4] = {cur.x, b01, 0ull, 0ull};
            u64 A23[4] = {cur.y, b23, 0ull, 0ull};
#pragma unroll
            for (int q = 0; q < 8; q++) {
#pragma unroll
                for (int j = 0; j < 4; j++) {
                    int k = j * 8 + q;
                    u64 p = pack2(__shfl_sync(0xffffffffu, h, k));
                    fma2(A01[j], w01[k], p);
                    fma2(A23[j], w23[k], p);
                }
            }
            float gi, gf, gg, go;
            unpack2(add2(add2(A01[0], A01[1]), add2(A01[2], A01[3])), gi, gf);
            unpack2(add2(add2(A23[0], A23[1]), add2(A23[2], A23[3])), gg, go);
            c = sigf(gf) * c + sigf(gi) * tanhfast(gg);
            h = sigf(go) * tanhfast(c);
            if (t < hi) hout[(size_t)t * 64 + 32 + lane] = h;
        }
    }
}

// ---------------------------------------------------------------------------
// Output head: warp per timestep, W_out staged transposed in smem.
// ---------------------------------------------------------------------------
__global__ __launch_bounds__(256)
void out_kernel(const float* __restrict__ Wout, const float* __restrict__ bout,
                const int* __restrict__ mask, float* __restrict__ out)
{
    __shared__ float Ws[64][52];
    const int tid = threadIdx.x;
    for (int i = tid; i < NTAGS * 64; i += 256) {
        int tag = i >> 6, k = i & 63;
        Ws[k][tag] = Wout[i];
    }
    __syncthreads();

    const int lane = tid & 31;
    const int t = blockIdx.x * 8 + (tid >> 5);

    float h0 = h1_buf[(size_t)t * 64 + lane];
    float h1 = h1_buf[(size_t)t * 64 + 32 + lane];

    const bool hasB = (lane < NTAGS - 32);
    float accA = bout[lane];
    float accB = hasB ? bout[lane + 32] : 0.0f;

#pragma unroll
    for (int k = 0; k < 32; k++) {
        float hk = __shfl_sync(0xffffffffu, h0, k);
        accA = fmaf(Ws[k][lane], hk, accA);
        if (hasB) accB = fmaf(Ws[k][lane + 32], hk, accB);
    }
#pragma unroll
    for (int k = 0; k < 32; k++) {
        float hk = __shfl_sync(0xffffffffu, h1, k);
        accA = fmaf(Ws[32 + k][lane], hk, accA);
        if (hasB) accB = fmaf(Ws[32 + k][lane + 32], hk, accB);
    }

    if (lane == 17) accB = (mask[t] > 0) ? fminf(accB, 1.0f) : 1.0f;
    accA = fmaxf(accA, 0.0f);
    accB = fmaxf(accB, 0.0f);

    float vB = hasB ? accB : -1.0f;
    float m = fmaxf(accA, vB);
#pragma unroll
    for (int o = 16; o; o >>= 1) m = fmaxf(m, __shfl_xor_sync(0xffffffffu, m, o));
    float s = __expf(accA - m) + (hasB ? __expf(accB - m) : 0.0f);
#pragma unroll
    for (int o = 16; o; o >>= 1) s += __shfl_xor_sync(0xffffffffu, s, o);
    float inv = __fdividef(1.0f, s);

    out[(size_t)t * NTAGS + lane] = __expf(accA - m) * inv;
    if (hasB) out[(size_t)t * NTAGS + lane + 32] = __expf(accB - m) * inv;
}

// ---------------------------------------------------------------------------

extern "C" void kernel_launch(void* const* d_in, const int* in_sizes, int n_in,
                              void* d_out, int out_size)
{
    const float* input_vecs = (const float*)d_in[0];
    const float* dp_table   = (const float*)d_in[1];
    const float* Wih0       = (const float*)d_in[2];
    const float* Whh0       = (const float*)d_in[3];
    const float* b0         = (const float*)d_in[4];
    const float* Wih1       = (const float*)d_in[5];
    const float* Whh1       = (const float*)d_in[6];
    const float* b1         = (const float*)d_in[7];
    const float* Wout       = (const float*)d_in[8];
    const float* bout       = (const float*)d_in[9];
    const int*   dp_in      = (const int*)d_in[10];
    const int*   mask       = (const int*)d_in[11];
    float* out = (float*)d_out;

    float *pH0, *pWt0, *pWt1;
    cudaGetSymbolAddress((void**)&pH0, h0_buf);
    cudaGetSymbolAddress((void**)&pWt0, Wt0);
    cudaGetSymbolAddress((void**)&pWt1, Wt1);

    const int rec_blocks = (2 * NCHUNK * 32) / 128;   // 512

    prep_w<<<800, 256>>>(Wih0, Wih1);
    gemm_gates<1><<<T_ / 128, 512>>>(input_vecs, dp_table, dp_in, pWt0);
    lstm_rec<<<rec_blocks, 128>>>(Whh0, b0, 0);
    gemm_gates<0><<<T_ / 128, 512>>>(pH0, nullptr, nullptr, pWt1);
    lstm_rec<<<rec_blocks, 128>>>(Whh1, b1, 1);
    out_kernel<<<T_ / 8, 256>>>(Wout, bout, mask, out);
}

// round 14
// speedup vs baseline: 1.5047x; 1.0885x over previous
#include <cuda_runtime.h>
#include <cuda_bf16.h>
#include <cstdint>

#define T_ 32768
#define NTAGS 50
#define LCHUNK 32
#define WARMUP 48
#define NCHUNK (T_ / LCHUNK)

typedef unsigned long long u64;

// Scratch (static device globals; no runtime allocation).
// g_buf padded by 8 timesteps on both ends -> recurrence prefetch ring needs
// no bounds clamping.
__device__ float g_buf_raw[(size_t)(T_ + 16) * 256];
#define GBUF (g_buf_raw + 8 * 256)
__device__ float h0_buf[(size_t)T_ * 64];   // layer0 output [t][dir*32 + lane]
__device__ float h1_buf[(size_t)T_ * 64];   // layer1 output
__device__ float Wt1[64 * 256];             // k-major permuted Wih1 (layer1 FFMA2 GEMM)
// Layer0 mma weight image: 49 stages x 256 n x 48 k' bf16 (96B per n-row).
// k' = 3*k triplets: (w_hi, w_hi, w_lo) paired against A' (a_hi, a_lo, a_hi).
__device__ __nv_bfloat16 Wimg[49 * 256 * 48];

__device__ __forceinline__ float sigf(float x) {
    return __fdividef(1.0f, 1.0f + __expf(-x));
}
__device__ __forceinline__ float tanhfast(float x) {
    x = fminf(fmaxf(x, -15.0f), 15.0f);
    float e = __expf(2.0f * x);
    return __fdividef(e - 1.0f, e + 1.0f);
}

// packed f32x2 helpers (pairs carried in u64)
__device__ __forceinline__ u64 pack2(float x) {
    u64 d; asm("mov.b64 %0, {%1, %1};" : "=l"(d) : "f"(x)); return d;
}
__device__ __forceinline__ u64 pack2f(float lo, float hi) {
    u64 d; asm("mov.b64 %0, {%1, %2};" : "=l"(d) : "f"(lo), "f"(hi)); return d;
}
__device__ __forceinline__ void fma2(u64& acc, u64 a, u64 b) {
    asm("fma.rn.f32x2 %0, %1, %2, %0;" : "+l"(acc) : "l"(a), "l"(b));
}
__device__ __forceinline__ u64 add2(u64 a, u64 b) {
    u64 d; asm("add.rn.f32x2 %0, %1, %2;" : "=l"(d) : "l"(a), "l"(b)); return d;
}
__device__ __forceinline__ void unpack2(u64 d, float& lo, float& hi) {
    asm("mov.b64 {%0, %1}, %2;" : "=f"(lo), "=f"(hi) : "l"(d));
}

// cp.async helpers
#define CP_ASYNC16(dst, src) \
    asm volatile("cp.async.cg.shared.global [%0], [%1], 16;" :: "r"(dst), "l"(src))
#define CP_COMMIT() asm volatile("cp.async.commit_group;" ::: "memory")
#define CP_WAIT0()  asm volatile("cp.async.wait_group 0;" ::: "memory")

// 16B-chunk swizzle: bit7 -> bit4
__device__ __forceinline__ uint32_t swz(uint32_t off) { return off ^ ((off >> 3) & 0x10); }

// bf16 hi/lo split
__device__ __forceinline__ void bf16split(float v, uint32_t& hi, uint32_t& lo) {
    __nv_bfloat16 h = __float2bfloat16(v);
    __nv_bfloat16 l = __float2bfloat16(v - __bfloat162float(h));
    hi = __bfloat16_as_ushort(h);
    lo = __bfloat16_as_ushort(l);
}

// m16n8k16 bf16 mma, f32 accumulate in place
__device__ __forceinline__ void mma16816(float* d, const uint32_t* a, const uint32_t* b) {
    asm volatile(
        "mma.sync.aligned.m16n8k16.row.col.f32.bf16.bf16.f32 "
        "{%0,%1,%2,%3}, {%4,%5,%6,%7}, {%8,%9}, {%0,%1,%2,%3};"
        : "+f"(d[0]), "+f"(d[1]), "+f"(d[2]), "+f"(d[3])
        : "r"(a[0]), "r"(a[1]), "r"(a[2]), "r"(a[3]), "r"(b[0]), "r"(b[1]));
}
__device__ __forceinline__ void ldmatrix4(uint32_t* r, uint32_t saddr) {
    asm volatile("ldmatrix.sync.aligned.m8n8.x4.shared.b16 {%0,%1,%2,%3}, [%4];"
        : "=r"(r[0]), "=r"(r[1]), "=r"(r[2]), "=r"(r[3]) : "r"(saddr));
}

// ---------------------------------------------------------------------------
// Prep A: layer1 weights k-major permuted (for FFMA2 GEMM).
// n = (dir<<7)|(l<<2)|p  ->  weight row = dir*128 + p*32 + l
// ---------------------------------------------------------------------------
__global__ void prep_w1(const float* __restrict__ Wih1)
{
    const int k = blockIdx.x;       // 0..63
    const int n = threadIdx.x;      // 0..255
    const int dir = n >> 7, l = (n & 127) >> 2, p = n & 3;
    const int row = dir * 128 + p * 32 + l;
    Wt1[k * 256 + n] = Wih1[(size_t)row * 64 + k];
}

// ---------------------------------------------------------------------------
// Prep B: layer0 mma weight image. Stage s covers orig k [16s, 16s+16).
// Per orig k local j: k' 3j..3j+2 = (w_hi, w_hi, w_lo). K zero-padded to 784.
// ---------------------------------------------------------------------------
__global__ void prep_wimg(const float* __restrict__ Wih0)
{
    const int s = blockIdx.x;       // 0..48
    const int n = threadIdx.x;      // 0..255
    const int dir = n >> 7, l = (n & 127) >> 2, p = n & 3;
    const int row = dir * 128 + p * 32 + l;
    __nv_bfloat16* dst = Wimg + ((size_t)s * 256 + n) * 48;
#pragma unroll
    for (int j = 0; j < 16; j++) {
        int k = s * 16 + j;
        float v = (k < 774) ? Wih0[(size_t)row * 774 + k] : 0.0f;
        uint32_t hi, lo;
        bf16split(v, hi, lo);
        dst[3 * j + 0] = __ushort_as_bfloat16((unsigned short)hi);
        dst[3 * j + 1] = __ushort_as_bfloat16((unsigned short)hi);
        dst[3 * j + 2] = __ushort_as_bfloat16((unsigned short)lo);
    }
}

// ---------------------------------------------------------------------------
// Layer0 gate GEMM on tensor cores (mma.sync m16n8k16 bf16, 3-product split).
// CTA 128t x 128n, 256 threads, 8 warps (4m x 2n), warp tile 32m x 64n.
// Stage = 16 orig k = 48 k' = 3 k16 steps; NT=49; double-buffered smem:
//   As[m][48 k'] bf16 rows (96B data, 112B pitch) - built in-kernel from fp32 A
//   Bs[n][48 k'] bf16 rows (112B pitch)           - cp.async from Wimg
// A' per k: (a_hi, a_lo, a_hi) vs W' (w_hi, w_hi, w_lo).
// ---------------------------------------------------------------------------
__global__ __launch_bounds__(256, 2)
void gemm_mma(const float* __restrict__ Ain, const float* __restrict__ dp_table,
              const int* __restrict__ dp_in)
{
    constexpr int NT = 49;
    constexpr int PITCH = 112;

    __shared__ __align__(16) char As[2][128 * PITCH];   // 28KB
    __shared__ __align__(16) char Bs[2][128 * PITCH];   // 28KB

    const int tid = threadIdx.x;
    const int t0 = blockIdx.x * 128;
    const int n0g = blockIdx.y * 128;

    const int wid = tid >> 5, lane = tid & 31;
    const int wm = wid & 3, wn = wid >> 2;      // 4m x 2n warps
    const int m0 = wm * 32;                     // warp m offset (32 rows)
    const int n0w = wn * 64;                    // warp n offset (64 cols)

    // fragment load offsets
    const uint32_t aLd = (uint32_t)(m0 + (lane & 15)) * PITCH + (uint32_t)(lane & 16);
    const uint32_t bLd = (uint32_t)(n0w + (lane >> 2)) * PITCH + (uint32_t)(lane & 3) * 4;

    // A loader/converter: m = tid>>1 (0..127), half = tid&1 (8 orig k each)
    const int m_a = tid >> 1;
    const int half = tid & 1;
    const float* __restrict__ a_base = Ain + (size_t)(t0 + m_a) * 770 + half * 8;
    const int dpo = dp_in[t0 + m_a] * 4;
    const uint32_t aSt = (uint32_t)m_a * PITCH + (uint32_t)half * 48;

    // B loader: n = tid>>1, part = tid&1 -> 3 x 16B chunks
    const int n_b = tid >> 1;
    const int part = tid & 1;
    const char* __restrict__ b_base =
        (const char*)Wimg + ((size_t)(n0g + n_b) * 48) * 2 + part * 48;
    const uint32_t bSt = (uint32_t)n_b * PITCH + (uint32_t)part * 48;

    uint32_t asb[2], bsb[2];
    asb[0] = (uint32_t)__cvta_generic_to_shared(&As[0][0]);
    asb[1] = (uint32_t)__cvta_generic_to_shared(&As[1][0]);
    bsb[0] = (uint32_t)__cvta_generic_to_shared(&Bs[0][0]);
    bsb[1] = (uint32_t)__cvta_generic_to_shared(&Bs[1][0]);

    float ar[8];
    auto loadA = [&](int s) {
        const int k0 = s * 16;
        if (k0 + half * 8 + 8 <= 770) {
            const float* ap = a_base + k0;
#pragma unroll
            for (int j = 0; j < 4; j++) {          // rows 8B-aligned
                float2 v = *(const float2*)(ap + 2 * j);
                ar[2 * j] = v.x; ar[2 * j + 1] = v.y;
            }
        } else {
#pragma unroll
            for (int j = 0; j < 8; j++) {
                int k = k0 + half * 8 + j;
                float v = 0.0f;
                if (k < 770)      v = Ain[(size_t)(t0 + m_a) * 770 + k];
                else if (k < 774) v = dp_table[dpo + (k - 770)];
                ar[j] = v;
            }
        }
    };
    // convert 8 fp32 -> 24 bf16 triplets packed in 12 u32 -> 3 STS.128
    auto stsA = [&](int buf) {
        uint32_t u[12];
#pragma unroll
        for (int p = 0; p < 4; p++) {
            uint32_t h0, l0, h1, l1;
            bf16split(ar[2 * p],     h0, l0);
            bf16split(ar[2 * p + 1], h1, l1);
            u[3 * p + 0] = h0 | (l0 << 16);
            u[3 * p + 1] = h0 | (h1 << 16);
            u[3 * p + 2] = l1 | (h1 << 16);
        }
        char* row = &As[buf][0] + aSt;
        *(uint4*)(row)      = make_uint4(u[0], u[1], u[2],  u[3]);
        *(uint4*)(row + 16) = make_uint4(u[4], u[5], u[6],  u[7]);
        *(uint4*)(row + 32) = make_uint4(u[8], u[9], u[10], u[11]);
    };
    auto issueB = [&](int s, int buf) {
        const char* bp = b_base + (size_t)s * (256 * 96);
#pragma unroll
        for (int i = 0; i < 3; i++)
            CP_ASYNC16(bsb[buf] + bSt + i * 16, bp + i * 16);
        CP_COMMIT();
    };

    float acc[2][8][4];
#pragma unroll
    for (int mi = 0; mi < 2; mi++)
#pragma unroll
        for (int ni = 0; ni < 8; ni++)
#pragma unroll
            for (int r = 0; r < 4; r++) acc[mi][ni][r] = 0.0f;

    // prologue
    loadA(0);
    stsA(0);
    issueB(0, 0);
    loadA(1);
    CP_WAIT0();
    __syncthreads();

    for (int s = 0; s < NT; s++) {
        const int buf = s & 1;
        if (s + 1 < NT) issueB(s + 1, buf ^ 1);

#pragma unroll
        for (int q = 0; q < 3; q++) {               // 3 k16 per stage
            uint32_t bf[8][2];
#pragma unroll
            for (int ni = 0; ni < 8; ni++) {
                uint32_t ba = bsb[buf] + bLd + (uint32_t)ni * 8 * PITCH + q * 32;
                asm volatile("ld.shared.b32 %0, [%1];"      : "=r"(bf[ni][0]) : "r"(ba));
                asm volatile("ld.shared.b32 %0, [%1+16];"   : "=r"(bf[ni][1]) : "r"(ba));
            }
#pragma unroll
            for (int mi = 0; mi < 2; mi++) {
                uint32_t af[4];
                ldmatrix4(af, asb[buf] + aLd + (uint32_t)mi * 16 * PITCH + q * 32);
#pragma unroll
                for (int ni = 0; ni < 8; ni++)
                    mma16816(acc[mi][ni], af, bf[ni]);
            }
        }

        if (s + 1 < NT) {
            stsA(buf ^ 1);
            if (s + 2 < NT) loadA(s + 2);
        }
        CP_WAIT0();
        __syncthreads();
    }

    // epilogue: d0,d1 -> row r=lane>>2, cols 2(lane&3)+{0,1}; d2,d3 -> row r+8
    const int er = lane >> 2;
    const int ec = (lane & 3) * 2;
#pragma unroll
    for (int mi = 0; mi < 2; mi++) {
        const size_t trow = (size_t)(t0 + m0 + mi * 16 + er);
#pragma unroll
        for (int ni = 0; ni < 8; ni++) {
            float* o = GBUF + trow * 256 + n0g + n0w + ni * 8 + ec;
            *(float2*)o = make_float2(acc[mi][ni][0], acc[mi][ni][1]);
            *(float2*)(o + 8 * 256) = make_float2(acc[mi][ni][2], acc[mi][ni][3]);
        }
    }
}

// ---------------------------------------------------------------------------
// Layer1 gate GEMM (FFMA2, R13-verified): 128t x 256n x 32k, 512 threads.
// ---------------------------------------------------------------------------
__global__ __launch_bounds__(512)
void gemm_gates1(const float* __restrict__ Ain, const float* __restrict__ Wt)
{
    constexpr int NT = 2;
    constexpr int AROW = 64;

    __shared__ __align__(16) float As[2][32][128];
    __shared__ __align__(16) float Bs[2][32][256];

    const int tid = threadIdx.x;
    const int t0 = blockIdx.x * 128;

    const int wid = tid >> 5, lane = tid & 31;
    const int wm = wid & 3, wn = wid >> 2;
    const int lm = lane & 3, ln = lane >> 2;
    const int m_t = wm * 32 + lm * 8;
    const int n_t = wn * 64 + ln * 8;

    const uint32_t a_off = (uint32_t)m_t * 4;
    const uint32_t b_raw = (uint32_t)n_t * 4;
    const uint32_t b_o0 = swz(b_raw), b_o1 = swz(b_raw + 16);

    const int m_a = tid >> 2;
    const int ha  = (tid & 3) * 8;
    const int lr = tid >> 4;
    const int lc = tid & 15;

    const float* __restrict__ a_base = Ain + (size_t)(t0 + m_a) * AROW + ha;
    const float* __restrict__ b_base = Wt + (size_t)lr * 256 + lc * 4;

    uint32_t b_dst[2];
    b_dst[0] = (uint32_t)__cvta_generic_to_shared(&Bs[0][lr][0]);
    b_dst[1] = (uint32_t)__cvta_generic_to_shared(&Bs[1][lr][0]);
    uint32_t bco[4];
#pragma unroll
    for (int i = 0; i < 4; i++) bco[i] = swz((uint32_t)lc * 16 + i * 256);

    float ar[8];
    auto loadA = [&](int k0) {
        const float* ap = a_base + k0;
#pragma unroll
        for (int j = 0; j < 4; j++) {
            float2 v = *(const float2*)(ap + 2 * j);
            ar[2 * j] = v.x; ar[2 * j + 1] = v.y;
        }
    };
    auto stsA = [&](int buf) {
#pragma unroll
        for (int j = 0; j < 8; j++) As[buf][ha + j][m_a] = ar[j];
    };
    auto issueB = [&](int s, int buf) {
        const float* bp = b_base + (size_t)s * 32 * 256;
#pragma unroll
        for (int i = 0; i < 4; i++)
            CP_ASYNC16(b_dst[buf] + bco[i], bp + i * 64);
        CP_COMMIT();
    };

    u64 acc[8][4];
#pragma unroll
    for (int m = 0; m < 8; m++)
#pragma unroll
        for (int np = 0; np < 4; np++) acc[m][np] = 0ull;

    loadA(0);
    stsA(0);
    issueB(0, 0);
    loadA(32);
    CP_WAIT0();
    __syncthreads();

    for (int s = 0; s < NT; s++) {
        const int buf = s & 1;
        if (s + 1 < NT) issueB(s + 1, buf ^ 1);

#pragma unroll
        for (int kk = 0; kk < 32; kk++) {
            const char* arow = (const char*)&As[buf][kk][0];
            float4 a0 = *(const float4*)(arow + a_off);
            float4 a1 = *(const float4*)(arow + a_off + 16);
            const char* brow = (const char*)&Bs[buf][kk][0];
            ulonglong2 b01 = *(const ulonglong2*)(brow + b_o0);
            ulonglong2 b23 = *(const ulonglong2*)(brow + b_o1);
            u64 bb[4] = {b01.x, b01.y, b23.x, b23.y};
            u64 pa[8];
            pa[0] = pack2(a0.x); pa[1] = pack2(a0.y);
            pa[2] = pack2(a0.z); pa[3] = pack2(a0.w);
            pa[4] = pack2(a1.x); pa[5] = pack2(a1.y);
            pa[6] = pack2(a1.z); pa[7] = pack2(a1.w);
#pragma unroll
            for (int m = 0; m < 8; m++)
#pragma unroll
                for (int np = 0; np < 4; np++)
                    fma2(acc[m][np], pa[m], bb[np]);
        }

        if (s + 1 < NT) stsA(buf ^ 1);
        CP_WAIT0();
        __syncthreads();
    }

#pragma unroll
    for (int m = 0; m < 8; m++) {
        float v[8];
#pragma unroll
        for (int np = 0; np < 4; np++) unpack2(acc[m][np], v[2 * np], v[2 * np + 1]);
        float* orow = GBUF + (size_t)(t0 + m_t + m) * 256 + n_t;
        *(float4*)orow       = make_float4(v[0], v[1], v[2], v[3]);
        *(float4*)(orow + 4) = make_float4(v[4], v[5], v[6], v[7]);
    }
}

// ---------------------------------------------------------------------------
// Chunked LSTM recurrence (R13-verified): one warp per (chunk, dir), 4-way
// fma chains, unconditional depth-3 prefetch ring (g_buf padded).
// ---------------------------------------------------------------------------
__global__ __launch_bounds__(128)
void lstm_rec(const float* __restrict__ Whh, const float* __restrict__ bias, int layer)
{
    const int wglob = (blockIdx.x * blockDim.x + threadIdx.x) >> 5;
    const int lane  = threadIdx.x & 31;
    const int dir   = wglob & 1;
    const int chunk = wglob >> 1;
    if (chunk >= NCHUNK) return;

    float* hout = layer ? h1_buf : h0_buf;

    u64 w01[32], w23[32];
    const float* Wd = Whh + dir * 4096;
#pragma unroll
    for (int k = 0; k < 32; k++) {
        w01[k] = pack2f(Wd[(lane)      * 32 + k], Wd[(32 + lane) * 32 + k]);
        w23[k] = pack2f(Wd[(64 + lane) * 32 + k], Wd[(96 + lane) * 32 + k]);
    }
    const float* bd = bias + dir * 128;
    const u64 b01 = pack2f(bd[lane], bd[32 + lane]);
    const u64 b23 = pack2f(bd[64 + lane], bd[96 + lane]);

    const int lo = chunk * LCHUNK;
    const int hi = lo + LCHUNK;
    float h = 0.0f, c = 0.0f;

    if (dir == 0) {
        int tb = lo - WARMUP; if (tb < 0) tb = 0;
        const float* gbase = GBUF + lane * 4;
        ulonglong2 r0 = *(const ulonglong2*)(gbase + (size_t)tb * 256);
        ulonglong2 r1 = *(const ulonglong2*)(gbase + (size_t)(tb + 1) * 256);
        ulonglong2 r2 = *(const ulonglong2*)(gbase + (size_t)(tb + 2) * 256);
        for (int t = tb; t < hi; ++t) {
            ulonglong2 cur = r0; r0 = r1; r1 = r2;
            r2 = *(const ulonglong2*)(gbase + (size_t)(t + 3) * 256);
            u64 A01[4] = {cur.x, b01, 0ull, 0ull};
            u64 A23[4] = {cur.y, b23, 0ull, 0ull};
#pragma unroll
            for (int q = 0; q < 8; q++) {
#pragma unroll
                for (int j = 0; j < 4; j++) {
                    int k = j * 8 + q;
                    u64 p = pack2(__shfl_sync(0xffffffffu, h, k));
                    fma2(A01[j], w01[k], p);
                    fma2(A23[j], w23[k], p);
                }
            }
            float gi, gf, gg, go;
            unpack2(add2(add2(A01[0], A01[1]), add2(A01[2], A01[3])), gi, gf);
            unpack2(add2(add2(A23[0], A23[1]), add2(A23[2], A23[3])), gg, go);
            c = sigf(gf) * c + sigf(gi) * tanhfast(gg);
            h = sigf(go) * tanhfast(c);
            if (t >= lo) hout[(size_t)t * 64 + lane] = h;
        }
    } else {
        int tb = hi - 1 + WARMUP; if (tb > T_ - 1) tb = T_ - 1;
        const float* gbase = GBUF + 128 + lane * 4;
        ulonglong2 r0 = *(const ulonglong2*)(gbase + (size_t)tb * 256);
        ulonglong2 r1 = *(const ulonglong2*)(gbase + (size_t)(tb - 1) * 256);
        ulonglong2 r2 = *(const ulonglong2*)(gbase + (size_t)(tb - 2) * 256);
        for (int t = tb; t >= lo; --t) {
            ulonglong2 cur = r0; r0 = r1; r1 = r2;
            r2 = *(const ulonglong2*)(gbase + ((size_t)(t - 3) + 8) * 256 - 8 * 256);
            u64 A01[4] = {cur.x, b01, 0ull, 0ull};
            u64 A23[4] = {cur.y, b23, 0ull, 0ull};
#pragma unroll
            for (int q = 0; q < 8; q++) {
#pragma unroll
                for (int j = 0; j < 4; j++) {
                    int k = j * 8 + q;
                    u64 p = pack2(__shfl_sync(0xffffffffu, h, k));
                    fma2(A01[j], w01[k], p);
                    fma2(A23[j], w23[k], p);
                }
            }
            float gi, gf, gg, go;
            unpack2(add2(add2(A01[0], A01[1]), add2(A01[2], A01[3])), gi, gf);
            unpack2(add2(add2(A23[0], A23[1]), add2(A23[2], A23[3])), gg, go);
            c = sigf(gf) * c + sigf(gi) * tanhfast(gg);
            h = sigf(go) * tanhfast(c);
            if (t < hi) hout[(size_t)t * 64 + 32 + lane] = h;
        }
    }
}

// ---------------------------------------------------------------------------
// Output head (R13-verified)
// ---------------------------------------------------------------------------
__global__ __launch_bounds__(256)
void out_kernel(const float* __restrict__ Wout, const float* __restrict__ bout,
                const int* __restrict__ mask, float* __restrict__ out)
{
    __shared__ float Ws[64][52];
    const int tid = threadIdx.x;
    for (int i = tid; i < NTAGS * 64; i += 256) {
        int tag = i >> 6, k = i & 63;
        Ws[k][tag] = Wout[i];
    }
    __syncthreads();

    const int lane = tid & 31;
    const int t = blockIdx.x * 8 + (tid >> 5);

    float h0 = h1_buf[(size_t)t * 64 + lane];
    float h1 = h1_buf[(size_t)t * 64 + 32 + lane];

    const bool hasB = (lane < NTAGS - 32);
    float accA = bout[lane];
    float accB = hasB ? bout[lane + 32] : 0.0f;

#pragma unroll
    for (int k = 0; k < 32; k++) {
        float hk = __shfl_sync(0xffffffffu, h0, k);
        accA = fmaf(Ws[k][lane], hk, accA);
        if (hasB) accB = fmaf(Ws[k][lane + 32], hk, accB);
    }
#pragma unroll
    for (int k = 0; k < 32; k++) {
        float hk = __shfl_sync(0xffffffffu, h1, k);
        accA = fmaf(Ws[32 + k][lane], hk, accA);
        if (hasB) accB = fmaf(Ws[32 + k][lane + 32], hk, accB);
    }

    if (lane == 17) accB = (mask[t] > 0) ? fminf(accB, 1.0f) : 1.0f;
    accA = fmaxf(accA, 0.0f);
    accB = fmaxf(accB, 0.0f);

    float vB = hasB ? accB : -1.0f;
    float m = fmaxf(accA, vB);
#pragma unroll
    for (int o = 16; o; o >>= 1) m = fmaxf(m, __shfl_xor_sync(0xffffffffu, m, o));
    float s = __expf(accA - m) + (hasB ? __expf(accB - m) : 0.0f);
#pragma unroll
    for (int o = 16; o; o >>= 1) s += __shfl_xor_sync(0xffffffffu, s, o);
    float inv = __fdividef(1.0f, s);

    out[(size_t)t * NTAGS + lane] = __expf(accA - m) * inv;
    if (hasB) out[(size_t)t * NTAGS + lane + 32] = __expf(accB - m) * inv;
}

// ---------------------------------------------------------------------------

extern "C" void kernel_launch(void* const* d_in, const int* in_sizes, int n_in,
                              void* d_out, int out_size)
{
    const float* input_vecs = (const float*)d_in[0];
    const float* dp_table   = (const float*)d_in[1];
    const float* Wih0       = (const float*)d_in[2];
    const float* Whh0       = (const float*)d_in[3];
    const float* b0         = (const float*)d_in[4];
    const float* Wih1       = (const float*)d_in[5];
    const float* Whh1       = (const float*)d_in[6];
    const float* b1         = (const float*)d_in[7];
    const float* Wout       = (const float*)d_in[8];
    const float* bout       = (const float*)d_in[9];
    const int*   dp_in      = (const int*)d_in[10];
    const int*   mask       = (const int*)d_in[11];
    float* out = (float*)d_out;

    float *pH0, *pWt1;
    cudaGetSymbolAddress((void**)&pH0, h0_buf);
    cudaGetSymbolAddress((void**)&pWt1, Wt1);

    const int rec_blocks = (2 * NCHUNK * 32) / 128;   // 512

    prep_wimg<<<49, 256>>>(Wih0);
    prep_w1<<<64, 256>>>(Wih1);
    gemm_mma<<<dim3(T_ / 128, 2), 256>>>(input_vecs, dp_table, dp_in);
    lstm_rec<<<rec_blocks, 128>>>(Whh0, b0, 0);
    gemm_gates1<<<T_ / 128, 512>>>(pH0, pWt1);
    lstm_rec<<<rec_blocks, 128>>>(Whh1, b1, 1);
    out_kernel<<<T_ / 8, 256>>>(Wout, bout, mask, out);
}

// round 15
// speedup vs baseline: 2.0250x; 1.3458x over previous
#include <cuda_runtime.h>
#include <cuda_bf16.h>
#include <cstdint>

#define T_ 32768
#define NTAGS 50
#define LCHUNK 64
#define WARMUP 48
#define NCHUNK (T_ / LCHUNK)

typedef unsigned long long u64;

// Scratch (static device globals; no runtime allocation).
// g_buf padded by 8 timesteps on both ends -> recurrence prefetch ring needs
// no bounds clamping.
__device__ float g_buf_raw[(size_t)(T_ + 16) * 256];
#define GBUF (g_buf_raw + 8 * 256)
__device__ float h0_buf[(size_t)T_ * 64];   // layer0 output [t][dir*32 + lane]
__device__ float h1_buf[(size_t)T_ * 64];   // layer1 output
__device__ float Wt1[64 * 256];             // k-major permuted Wih1 (layer1 FFMA2 GEMM)
// Layer0 mma weight image: 49 stages x 256 n x 48 k' bf16 (96B per n-row).
// k' = 3*k triplets: (w_hi, w_hi, w_lo) paired against A' (a_hi, a_lo, a_hi).
__device__ __nv_bfloat16 Wimg[49 * 256 * 48];

__device__ __forceinline__ float sigf(float x) {
    return __fdividef(1.0f, 1.0f + __expf(-x));
}
__device__ __forceinline__ float tanhfast(float x) {
    x = fminf(fmaxf(x, -15.0f), 15.0f);
    float e = __expf(2.0f * x);
    return __fdividef(e - 1.0f, e + 1.0f);
}

// packed f32x2 helpers (pairs carried in u64)
__device__ __forceinline__ u64 pack2(float x) {
    u64 d; asm("mov.b64 %0, {%1, %1};" : "=l"(d) : "f"(x)); return d;
}
__device__ __forceinline__ u64 pack2f(float lo, float hi) {
    u64 d; asm("mov.b64 %0, {%1, %2};" : "=l"(d) : "f"(lo), "f"(hi)); return d;
}
__device__ __forceinline__ void fma2(u64& acc, u64 a, u64 b) {
    asm("fma.rn.f32x2 %0, %1, %2, %0;" : "+l"(acc) : "l"(a), "l"(b));
}
__device__ __forceinline__ u64 add2(u64 a, u64 b) {
    u64 d; asm("add.rn.f32x2 %0, %1, %2;" : "=l"(d) : "l"(a), "l"(b)); return d;
}
__device__ __forceinline__ void unpack2(u64 d, float& lo, float& hi) {
    asm("mov.b64 {%0, %1}, %2;" : "=f"(lo), "=f"(hi) : "l"(d));
}

// cp.async helpers
#define CP_ASYNC16(dst, src) \
    asm volatile("cp.async.cg.shared.global [%0], [%1], 16;" :: "r"(dst), "l"(src))
#define CP_COMMIT() asm volatile("cp.async.commit_group;" ::: "memory")
#define CP_WAIT0()  asm volatile("cp.async.wait_group 0;" ::: "memory")

// 16B-chunk swizzle: bit7 -> bit4
__device__ __forceinline__ uint32_t swz(uint32_t off) { return off ^ ((off >> 3) & 0x10); }

// bf16 hi/lo split
__device__ __forceinline__ void bf16split(float v, uint32_t& hi, uint32_t& lo) {
    __nv_bfloat16 h = __float2bfloat16(v);
    __nv_bfloat16 l = __float2bfloat16(v - __bfloat162float(h));
    hi = __bfloat16_as_ushort(h);
    lo = __bfloat16_as_ushort(l);
}

// m16n8k16 bf16 mma, f32 accumulate in place
__device__ __forceinline__ void mma16816(float* d, const uint32_t* a, const uint32_t* b) {
    asm volatile(
        "mma.sync.aligned.m16n8k16.row.col.f32.bf16.bf16.f32 "
        "{%0,%1,%2,%3}, {%4,%5,%6,%7}, {%8,%9}, {%0,%1,%2,%3};"
        : "+f"(d[0]), "+f"(d[1]), "+f"(d[2]), "+f"(d[3])
        : "r"(a[0]), "r"(a[1]), "r"(a[2]), "r"(a[3]), "r"(b[0]), "r"(b[1]));
}
__device__ __forceinline__ void ldmatrix4(uint32_t* r, uint32_t saddr) {
    asm volatile("ldmatrix.sync.aligned.m8n8.x4.shared.b16 {%0,%1,%2,%3}, [%4];"
        : "=r"(r[0]), "=r"(r[1]), "=r"(r[2]), "=r"(r[3]) : "r"(saddr));
}

// ---------------------------------------------------------------------------
// Prep A: layer1 weights k-major permuted (for FFMA2 GEMM).
// n = (dir<<7)|(l<<2)|p  ->  weight row = dir*128 + p*32 + l
// ---------------------------------------------------------------------------
__global__ void prep_w1(const float* __restrict__ Wih1)
{
    const int k = blockIdx.x;       // 0..63
    const int n = threadIdx.x;      // 0..255
    const int dir = n >> 7, l = (n & 127) >> 2, p = n & 3;
    const int row = dir * 128 + p * 32 + l;
    Wt1[k * 256 + n] = Wih1[(size_t)row * 64 + k];
}

// ---------------------------------------------------------------------------
// Prep B: layer0 mma weight image. Stage s covers orig k [16s, 16s+16).
// Per orig k local j: k' 3j..3j+2 = (w_hi, w_hi, w_lo). K zero-padded to 784.
// ---------------------------------------------------------------------------
__global__ void prep_wimg(const float* __restrict__ Wih0)
{
    const int s = blockIdx.x;       // 0..48
    const int n = threadIdx.x;      // 0..255
    const int dir = n >> 7, l = (n & 127) >> 2, p = n & 3;
    const int row = dir * 128 + p * 32 + l;
    __nv_bfloat16* dst = Wimg + ((size_t)s * 256 + n) * 48;
#pragma unroll
    for (int j = 0; j < 16; j++) {
        int k = s * 16 + j;
        float v = (k < 774) ? Wih0[(size_t)row * 774 + k] : 0.0f;
        uint32_t hi, lo;
        bf16split(v, hi, lo);
        dst[3 * j + 0] = __ushort_as_bfloat16((unsigned short)hi);
        dst[3 * j + 1] = __ushort_as_bfloat16((unsigned short)hi);
        dst[3 * j + 2] = __ushort_as_bfloat16((unsigned short)lo);
    }
}

// ---------------------------------------------------------------------------
// Layer0 gate GEMM on tensor cores (R14-verified, unchanged).
// ---------------------------------------------------------------------------
__global__ __launch_bounds__(256, 2)
void gemm_mma(const float* __restrict__ Ain, const float* __restrict__ dp_table,
              const int* __restrict__ dp_in)
{
    constexpr int NT = 49;
    constexpr int PITCH = 112;

    __shared__ __align__(16) char As[2][128 * PITCH];
    __shared__ __align__(16) char Bs[2][128 * PITCH];

    const int tid = threadIdx.x;
    const int t0 = blockIdx.x * 128;
    const int n0g = blockIdx.y * 128;

    const int wid = tid >> 5, lane = tid & 31;
    const int wm = wid & 3, wn = wid >> 2;
    const int m0 = wm * 32;
    const int n0w = wn * 64;

    const uint32_t aLd = (uint32_t)(m0 + (lane & 15)) * PITCH + (uint32_t)(lane & 16);
    const uint32_t bLd = (uint32_t)(n0w + (lane >> 2)) * PITCH + (uint32_t)(lane & 3) * 4;

    const int m_a = tid >> 1;
    const int half = tid & 1;
    const float* __restrict__ a_base = Ain + (size_t)(t0 + m_a) * 770 + half * 8;
    const int dpo = dp_in[t0 + m_a] * 4;
    const uint32_t aSt = (uint32_t)m_a * PITCH + (uint32_t)half * 48;

    const int n_b = tid >> 1;
    const int part = tid & 1;
    const char* __restrict__ b_base =
        (const char*)Wimg + ((size_t)(n0g + n_b) * 48) * 2 + part * 48;
    const uint32_t bSt = (uint32_t)n_b * PITCH + (uint32_t)part * 48;

    uint32_t asb[2], bsb[2];
    asb[0] = (uint32_t)__cvta_generic_to_shared(&As[0][0]);
    asb[1] = (uint32_t)__cvta_generic_to_shared(&As[1][0]);
    bsb[0] = (uint32_t)__cvta_generic_to_shared(&Bs[0][0]);
    bsb[1] = (uint32_t)__cvta_generic_to_shared(&Bs[1][0]);

    float ar[8];
    auto loadA = [&](int s) {
        const int k0 = s * 16;
        if (k0 + half * 8 + 8 <= 770) {
            const float* ap = a_base + k0;
#pragma unroll
            for (int j = 0; j < 4; j++) {
                float2 v = *(const float2*)(ap + 2 * j);
                ar[2 * j] = v.x; ar[2 * j + 1] = v.y;
            }
        } else {
#pragma unroll
            for (int j = 0; j < 8; j++) {
                int k = k0 + half * 8 + j;
                float v = 0.0f;
                if (k < 770)      v = Ain[(size_t)(t0 + m_a) * 770 + k];
                else if (k < 774) v = dp_table[dpo + (k - 770)];
                ar[j] = v;
            }
        }
    };
    auto stsA = [&](int buf) {
        uint32_t u[12];
#pragma unroll
        for (int p = 0; p < 4; p++) {
            uint32_t h0, l0, h1, l1;
            bf16split(ar[2 * p],     h0, l0);
            bf16split(ar[2 * p + 1], h1, l1);
            u[3 * p + 0] = h0 | (l0 << 16);
            u[3 * p + 1] = h0 | (h1 << 16);
            u[3 * p + 2] = l1 | (h1 << 16);
        }
        char* row = &As[buf][0] + aSt;
        *(uint4*)(row)      = make_uint4(u[0], u[1], u[2],  u[3]);
        *(uint4*)(row + 16) = make_uint4(u[4], u[5], u[6],  u[7]);
        *(uint4*)(row + 32) = make_uint4(u[8], u[9], u[10], u[11]);
    };
    auto issueB = [&](int s, int buf) {
        const char* bp = b_base + (size_t)s * (256 * 96);
#pragma unroll
        for (int i = 0; i < 3; i++)
            CP_ASYNC16(bsb[buf] + bSt + i * 16, bp + i * 16);
        CP_COMMIT();
    };

    float acc[2][8][4];
#pragma unroll
    for (int mi = 0; mi < 2; mi++)
#pragma unroll
        for (int ni = 0; ni < 8; ni++)
#pragma unroll
            for (int r = 0; r < 4; r++) acc[mi][ni][r] = 0.0f;

    loadA(0);
    stsA(0);
    issueB(0, 0);
    loadA(1);
    CP_WAIT0();
    __syncthreads();

    for (int s = 0; s < NT; s++) {
        const int buf = s & 1;
        if (s + 1 < NT) issueB(s + 1, buf ^ 1);

#pragma unroll
        for (int q = 0; q < 3; q++) {
            uint32_t bf[8][2];
#pragma unroll
            for (int ni = 0; ni < 8; ni++) {
                uint32_t ba = bsb[buf] + bLd + (uint32_t)ni * 8 * PITCH + q * 32;
                asm volatile("ld.shared.b32 %0, [%1];"    : "=r"(bf[ni][0]) : "r"(ba));
                asm volatile("ld.shared.b32 %0, [%1+16];" : "=r"(bf[ni][1]) : "r"(ba));
            }
#pragma unroll
            for (int mi = 0; mi < 2; mi++) {
                uint32_t af[4];
                ldmatrix4(af, asb[buf] + aLd + (uint32_t)mi * 16 * PITCH + q * 32);
#pragma unroll
                for (int ni = 0; ni < 8; ni++)
                    mma16816(acc[mi][ni], af, bf[ni]);
            }
        }

        if (s + 1 < NT) {
            stsA(buf ^ 1);
            if (s + 2 < NT) loadA(s + 2);
        }
        CP_WAIT0();
        __syncthreads();
    }

    const int er = lane >> 2;
    const int ec = (lane & 3) * 2;
#pragma unroll
    for (int mi = 0; mi < 2; mi++) {
        const size_t trow = (size_t)(t0 + m0 + mi * 16 + er);
#pragma unroll
        for (int ni = 0; ni < 8; ni++) {
            float* o = GBUF + trow * 256 + n0g + n0w + ni * 8 + ec;
            *(float2*)o = make_float2(acc[mi][ni][0], acc[mi][ni][1]);
            *(float2*)(o + 8 * 256) = make_float2(acc[mi][ni][2], acc[mi][ni][3]);
        }
    }
}

// ---------------------------------------------------------------------------
// Layer1 gate GEMM (FFMA2, R13-verified, unchanged).
// ---------------------------------------------------------------------------
__global__ __launch_bounds__(512)
void gemm_gates1(const float* __restrict__ Ain, const float* __restrict__ Wt)
{
    constexpr int NT = 2;
    constexpr int AROW = 64;

    __shared__ __align__(16) float As[2][32][128];
    __shared__ __align__(16) float Bs[2][32][256];

    const int tid = threadIdx.x;
    const int t0 = blockIdx.x * 128;

    const int wid = tid >> 5, lane = tid & 31;
    const int wm = wid & 3, wn = wid >> 2;
    const int lm = lane & 3, ln = lane >> 2;
    const int m_t = wm * 32 + lm * 8;
    const int n_t = wn * 64 + ln * 8;

    const uint32_t a_off = (uint32_t)m_t * 4;
    const uint32_t b_raw = (uint32_t)n_t * 4;
    const uint32_t b_o0 = swz(b_raw), b_o1 = swz(b_raw + 16);

    const int m_a = tid >> 2;
    const int ha  = (tid & 3) * 8;
    const int lr = tid >> 4;
    const int lc = tid & 15;

    const float* __restrict__ a_base = Ain + (size_t)(t0 + m_a) * AROW + ha;
    const float* __restrict__ b_base = Wt + (size_t)lr * 256 + lc * 4;

    uint32_t b_dst[2];
    b_dst[0] = (uint32_t)__cvta_generic_to_shared(&Bs[0][lr][0]);
    b_dst[1] = (uint32_t)__cvta_generic_to_shared(&Bs[1][lr][0]);
    uint32_t bco[4];
#pragma unroll
    for (int i = 0; i < 4; i++) bco[i] = swz((uint32_t)lc * 16 + i * 256);

    float ar[8];
    auto loadA = [&](int k0) {
        const float* ap = a_base + k0;
#pragma unroll
        for (int j = 0; j < 4; j++) {
            float2 v = *(const float2*)(ap + 2 * j);
            ar[2 * j] = v.x; ar[2 * j + 1] = v.y;
        }
    };
    auto stsA = [&](int buf) {
#pragma unroll
        for (int j = 0; j < 8; j++) As[buf][ha + j][m_a] = ar[j];
    };
    auto issueB = [&](int s, int buf) {
        const float* bp = b_base + (size_t)s * 32 * 256;
#pragma unroll
        for (int i = 0; i < 4; i++)
            CP_ASYNC16(b_dst[buf] + bco[i], bp + i * 64);
        CP_COMMIT();
    };

    u64 acc[8][4];
#pragma unroll
    for (int m = 0; m < 8; m++)
#pragma unroll
        for (int np = 0; np < 4; np++) acc[m][np] = 0ull;

    loadA(0);
    stsA(0);
    issueB(0, 0);
    loadA(32);
    CP_WAIT0();
    __syncthreads();

    for (int s = 0; s < NT; s++) {
        const int buf = s & 1;
        if (s + 1 < NT) issueB(s + 1, buf ^ 1);

#pragma unroll
        for (int kk = 0; kk < 32; kk++) {
            const char* arow = (const char*)&As[buf][kk][0];
            float4 a0 = *(const float4*)(arow + a_off);
            float4 a1 = *(const float4*)(arow + a_off + 16);
            const char* brow = (const char*)&Bs[buf][kk][0];
            ulonglong2 b01 = *(const ulonglong2*)(brow + b_o0);
            ulonglong2 b23 = *(const ulonglong2*)(brow + b_o1);
            u64 bb[4] = {b01.x, b01.y, b23.x, b23.y};
            u64 pa[8];
            pa[0] = pack2(a0.x); pa[1] = pack2(a0.y);
            pa[2] = pack2(a0.z); pa[3] = pack2(a0.w);
            pa[4] = pack2(a1.x); pa[5] = pack2(a1.y);
            pa[6] = pack2(a1.z); pa[7] = pack2(a1.w);
#pragma unroll
            for (int m = 0; m < 8; m++)
#pragma unroll
                for (int np = 0; np < 4; np++)
                    fma2(acc[m][np], pa[m], bb[np]);
        }

        if (s + 1 < NT) stsA(buf ^ 1);
        CP_WAIT0();
        __syncthreads();
    }

#pragma unroll
    for (int m = 0; m < 8; m++) {
        float v[8];
#pragma unroll
        for (int np = 0; np < 4; np++) unpack2(acc[m][np], v[2 * np], v[2 * np + 1]);
        float* orow = GBUF + (size_t)(t0 + m_t + m) * 256 + n_t;
        *(float4*)orow       = make_float4(v[0], v[1], v[2], v[3]);
        *(float4*)(orow + 4) = make_float4(v[4], v[5], v[6], v[7]);
    }
}

// ---------------------------------------------------------------------------
// Chunked LSTM recurrence v3: smem k-paired h broadcast (no shfl, no pack
// in the loop). Lane l owns h[l], c[l]; k-paired weights (w_2j, w_2j+1) in
// registers; h pairs read as broadcast LDS.64 from the warp's smem row.
// acc halves hold even/odd-k partials; horizontal add per gate at the end.
// LCHUNK=64: 1024 warps, 256 blocks -> single wave at 2 blocks/SM.
// ---------------------------------------------------------------------------
__global__ __launch_bounds__(128)
void lstm_rec(const float* __restrict__ Whh, const float* __restrict__ bias, int layer)
{
    const int wglob = (blockIdx.x * blockDim.x + threadIdx.x) >> 5;
    const int wid   = (threadIdx.x >> 5);
    const int lane  = threadIdx.x & 31;
    const int dir   = wglob & 1;
    const int chunk = wglob >> 1;
    if (chunk >= NCHUNK) return;

    float* hout = layer ? h1_buf : h0_buf;

    // k-paired weights: wX[j] = (W[row][2j], W[row][2j+1])
    u64 wi[16], wf[16], wg[16], wo[16];
    const float* Wd = Whh + dir * 4096;
#pragma unroll
    for (int j = 0; j < 16; j++) {
        wi[j] = pack2f(Wd[(lane)      * 32 + 2 * j], Wd[(lane)      * 32 + 2 * j + 1]);
        wf[j] = pack2f(Wd[(32 + lane) * 32 + 2 * j], Wd[(32 + lane) * 32 + 2 * j + 1]);
        wg[j] = pack2f(Wd[(64 + lane) * 32 + 2 * j], Wd[(64 + lane) * 32 + 2 * j + 1]);
        wo[j] = pack2f(Wd[(96 + lane) * 32 + 2 * j], Wd[(96 + lane) * 32 + 2 * j + 1]);
    }
    const float* bd = bias + dir * 128;
    const float bi  = bd[lane];
    const float bff = bd[32 + lane];
    const float bgg = bd[64 + lane];
    const float boo = bd[96 + lane];

    __shared__ __align__(8) float hs[4][32];   // per-warp h row

    const int lo = chunk * LCHUNK;
    const int hi = lo + LCHUNK;
    float h = 0.0f, c = 0.0f;

#define REC_STEP(CUR)                                                          \
    {                                                                          \
        __syncwarp();                                                          \
        hs[wid][lane] = h;                                                     \
        __syncwarp();                                                          \
        u64 ai0 = 0, ai1 = 0, af0 = 0, af1 = 0;                                \
        u64 ag0 = 0, ag1 = 0, ao0 = 0, ao1 = 0;                                \
        _Pragma("unroll")                                                      \
        for (int j = 0; j < 16; j += 2) {                                      \
            u64 hp0 = *(const u64*)&hs[wid][2 * j];                            \
            u64 hp1 = *(const u64*)&hs[wid][2 * j + 2];                        \
            fma2(ai0, wi[j], hp0); fma2(ai1, wi[j + 1], hp1);                  \
            fma2(af0, wf[j], hp0); fma2(af1, wf[j + 1], hp1);                  \
            fma2(ag0, wg[j], hp0); fma2(ag1, wg[j + 1], hp1);                  \
            fma2(ao0, wo[j], hp0); fma2(ao1, wo[j + 1], hp1);                  \
        }                                                                      \
        float gin_i, gin_f, gin_g, gin_o;                                      \
        unpack2((CUR).x, gin_i, gin_f);                                        \
        unpack2((CUR).y, gin_g, gin_o);                                        \
        float l0, h0v;                                                         \
        unpack2(add2(ai0, ai1), l0, h0v); float Gi = l0 + h0v + gin_i + bi;    \
        unpack2(add2(af0, af1), l0, h0v); float Gf = l0 + h0v + gin_f + bff;   \
        unpack2(add2(ag0, ag1), l0, h0v); float Gg = l0 + h0v + gin_g + bgg;   \
        unpack2(add2(ao0, ao1), l0, h0v); float Go = l0 + h0v + gin_o + boo;   \
        c = sigf(Gf) * c + sigf(Gi) * tanhfast(Gg);                            \
        h = sigf(Go) * tanhfast(c);                                            \
    }

    if (dir == 0) {
        int tb = lo - WARMUP; if (tb < 0) tb = 0;
        const float* gbase = GBUF + lane * 4;
        ulonglong2 r0 = *(const ulonglong2*)(gbase + (size_t)tb * 256);
        ulonglong2 r1 = *(const ulonglong2*)(gbase + (size_t)(tb + 1) * 256);
        ulonglong2 r2 = *(const ulonglong2*)(gbase + (size_t)(tb + 2) * 256);
        for (int t = tb; t < hi; ++t) {
            ulonglong2 cur = r0; r0 = r1; r1 = r2;
            r2 = *(const ulonglong2*)(gbase + (size_t)(t + 3) * 256);  // pad-safe
            REC_STEP(cur);
            if (t >= lo) hout[(size_t)t * 64 + lane] = h;
        }
    } else {
        int tb = hi - 1 + WARMUP; if (tb > T_ - 1) tb = T_ - 1;
        const float* gbase = GBUF + 128 + lane * 4;
        ulonglong2 r0 = *(const ulonglong2*)(gbase + (size_t)tb * 256);
        ulonglong2 r1 = *(const ulonglong2*)(gbase + (size_t)(tb - 1) * 256);
        ulonglong2 r2 = *(const ulonglong2*)(gbase + (size_t)(tb - 2) * 256);
        for (int t = tb; t >= lo; --t) {
            ulonglong2 cur = r0; r0 = r1; r1 = r2;
            r2 = *(const ulonglong2*)(gbase + (size_t)(t - 3 + 8) * 256 - 8 * 256); // pad-safe
            REC_STEP(cur);
            if (t < hi) hout[(size_t)t * 64 + 32 + lane] = h;
        }
    }
#undef REC_STEP
}

// ---------------------------------------------------------------------------
// Output head (verified, unchanged)
// ---------------------------------------------------------------------------
__global__ __launch_bounds__(256)
void out_kernel(const float* __restrict__ Wout, const float* __restrict__ bout,
                const int* __restrict__ mask, float* __restrict__ out)
{
    __shared__ float Ws[64][52];
    const int tid = threadIdx.x;
    for (int i = tid; i < NTAGS * 64; i += 256) {
        int tag = i >> 6, k = i & 63;
        Ws[k][tag] = Wout[i];
    }
    __syncthreads();

    const int lane = tid & 31;
    const int t = blockIdx.x * 8 + (tid >> 5);

    float h0 = h1_buf[(size_t)t * 64 + lane];
    float h1 = h1_buf[(size_t)t * 64 + 32 + lane];

    const bool hasB = (lane < NTAGS - 32);
    float accA = bout[lane];
    float accB = hasB ? bout[lane + 32] : 0.0f;

#pragma unroll
    for (int k = 0; k < 32; k++) {
        float hk = __shfl_sync(0xffffffffu, h0, k);
        accA = fmaf(Ws[k][lane], hk, accA);
        if (hasB) accB = fmaf(Ws[k][lane + 32], hk, accB);
    }
#pragma unroll
    for (int k = 0; k < 32; k++) {
        float hk = __shfl_sync(0xffffffffu, h1, k);
        accA = fmaf(Ws[32 + k][lane], hk, accA);
        if (hasB) accB = fmaf(Ws[32 + k][lane + 32], hk, accB);
    }

    if (lane == 17) accB = (mask[t] > 0) ? fminf(accB, 1.0f) : 1.0f;
    accA = fmaxf(accA, 0.0f);
    accB = fmaxf(accB, 0.0f);

    float vB = hasB ? accB : -1.0f;
    float m = fmaxf(accA, vB);
#pragma unroll
    for (int o = 16; o; o >>= 1) m = fmaxf(m, __shfl_xor_sync(0xffffffffu, m, o));
    float s = __expf(accA - m) + (hasB ? __expf(accB - m) : 0.0f);
#pragma unroll
    for (int o = 16; o; o >>= 1) s += __shfl_xor_sync(0xffffffffu, s, o);
    float inv = __fdividef(1.0f, s);

    out[(size_t)t * NTAGS + lane] = __expf(accA - m) * inv;
    if (hasB) out[(size_t)t * NTAGS + lane + 32] = __expf(accB - m) * inv;
}

// ---------------------------------------------------------------------------

extern "C" void kernel_launch(void* const* d_in, const int* in_sizes, int n_in,
                              void* d_out, int out_size)
{
    const float* input_vecs = (const float*)d_in[0];
    const float* dp_table   = (const float*)d_in[1];
    const float* Wih0       = (const float*)d_in[2];
    const float* Whh0       = (const float*)d_in[3];
    const float* b0         = (const float*)d_in[4];
    const float* Wih1       = (const float*)d_in[5];
    const float* Whh1       = (const float*)d_in[6];
    const float* b1         = (const float*)d_in[7];
    const float* Wout       = (const float*)d_in[8];
    const float* bout       = (const float*)d_in[9];
    const int*   dp_in      = (const int*)d_in[10];
    const int*   mask       = (const int*)d_in[11];
    float* out = (float*)d_out;

    float *pH0, *pWt1;
    cudaGetSymbolAddress((void**)&pH0, h0_buf);
    cudaGetSymbolAddress((void**)&pWt1, Wt1);

    const int rec_blocks = (2 * NCHUNK * 32) / 128;   // 256

    prep_wimg<<<49, 256>>>(Wih0);
    prep_w1<<<64, 256>>>(Wih1);
    gemm_mma<<<dim3(T_ / 128, 2), 256>>>(input_vecs, dp_table, dp_in);
    lstm_rec<<<rec_blocks, 128>>>(Whh0, b0, 0);
    gemm_gates1<<<T_ / 128, 512>>>(pH0, pWt1);
    lstm_rec<<<rec_blocks, 128>>>(Whh1, b1, 1);
    out_kernel<<<T_ / 8, 256>>>(Wout, bout, mask, out);
}

// round 16
// speedup vs baseline: 2.2612x; 1.1167x over previous
#include <cuda_runtime.h>
#include <cuda_bf16.h>
#include <cstdint>

#define T_ 32768
#define NTAGS 50
#define LCHUNK 64
#define WARMUP 48
#define NCHUNK (T_ / LCHUNK)

typedef unsigned long long u64;

// Scratch (static device globals; no runtime allocation).
__device__ float g_buf_raw[(size_t)(T_ + 16) * 256];
#define GBUF (g_buf_raw + 8 * 256)
__device__ float h0_buf[(size_t)T_ * 64];   // layer0 output [t][dir*32 + lane]
__device__ float h1_buf[(size_t)T_ * 64];   // layer1 output
__device__ float Wt1[64 * 256];             // k-major permuted Wih1 (layer1 FFMA2 GEMM)
// Layer0 mma weight image in FRAGMENT ORDER:
// [s (49)][g (4: 64-n group)][q (3)][np (4)][lane (32)][w (4 u32)]
// w0/w1 = b-frag regs of ni=2np, w2/w3 = of ni=2np+1.
__device__ uint32_t Wimg2[49 * 4 * 3 * 4 * 32 * 4];

__device__ __forceinline__ float sigf(float x) {
    return __fdividef(1.0f, 1.0f + __expf(-x));
}
__device__ __forceinline__ float tanhfast(float x) {
    x = fminf(fmaxf(x, -15.0f), 15.0f);
    float e = __expf(2.0f * x);
    return __fdividef(e - 1.0f, e + 1.0f);
}

// packed f32x2 helpers
__device__ __forceinline__ u64 pack2(float x) {
    u64 d; asm("mov.b64 %0, {%1, %1};" : "=l"(d) : "f"(x)); return d;
}
__device__ __forceinline__ u64 pack2f(float lo, float hi) {
    u64 d; asm("mov.b64 %0, {%1, %2};" : "=l"(d) : "f"(lo), "f"(hi)); return d;
}
__device__ __forceinline__ void fma2(u64& acc, u64 a, u64 b) {
    asm("fma.rn.f32x2 %0, %1, %2, %0;" : "+l"(acc) : "l"(a), "l"(b));
}
__device__ __forceinline__ u64 add2(u64 a, u64 b) {
    u64 d; asm("add.rn.f32x2 %0, %1, %2;" : "=l"(d) : "l"(a), "l"(b)); return d;
}
__device__ __forceinline__ void unpack2(u64 d, float& lo, float& hi) {
    asm("mov.b64 {%0, %1}, %2;" : "=f"(lo), "=f"(hi) : "l"(d));
}

// cp.async helpers
#define CP_ASYNC16(dst, src) \
    asm volatile("cp.async.cg.shared.global [%0], [%1], 16;" :: "r"(dst), "l"(src))
#define CP_COMMIT() asm volatile("cp.async.commit_group;" ::: "memory")
#define CP_WAIT0()  asm volatile("cp.async.wait_group 0;" ::: "memory")

// 16B-chunk swizzle: bit7 -> bit4
__device__ __forceinline__ uint32_t swz(uint32_t off) { return off ^ ((off >> 3) & 0x10); }

// bf16 hi/lo split
__device__ __forceinline__ void bf16split(float v, uint32_t& hi, uint32_t& lo) {
    __nv_bfloat16 h = __float2bfloat16(v);
    __nv_bfloat16 l = __float2bfloat16(v - __bfloat162float(h));
    hi = __bfloat16_as_ushort(h);
    lo = __bfloat16_as_ushort(l);
}

// m16n8k16 bf16 mma, f32 accumulate in place
__device__ __forceinline__ void mma16816(float* d, const uint32_t* a, const uint32_t* b) {
    asm volatile(
        "mma.sync.aligned.m16n8k16.row.col.f32.bf16.bf16.f32 "
        "{%0,%1,%2,%3}, {%4,%5,%6,%7}, {%8,%9}, {%0,%1,%2,%3};"
        : "+f"(d[0]), "+f"(d[1]), "+f"(d[2]), "+f"(d[3])
        : "r"(a[0]), "r"(a[1]), "r"(a[2]), "r"(a[3]), "r"(b[0]), "r"(b[1]));
}
__device__ __forceinline__ void ldmatrix4(uint32_t* r, uint32_t saddr) {
    asm volatile("ldmatrix.sync.aligned.m8n8.x4.shared.b16 {%0,%1,%2,%3}, [%4];"
        : "=r"(r[0]), "=r"(r[1]), "=r"(r[2]), "=r"(r[3]) : "r"(saddr));
}

// ---------------------------------------------------------------------------
// Prep A: layer1 weights k-major permuted (for FFMA2 GEMM).
// ---------------------------------------------------------------------------
__global__ void prep_w1(const float* __restrict__ Wih1)
{
    const int k = blockIdx.x;       // 0..63
    const int n = threadIdx.x;      // 0..255
    const int dir = n >> 7, l = (n & 127) >> 2, p = n & 3;
    const int row = dir * 128 + p * 32 + l;
    Wt1[k * 256 + n] = Wih1[(size_t)row * 64 + k];
}

// ---------------------------------------------------------------------------
// Prep B: fragment-ordered layer0 mma weight image.
// k' = 3j + r triplets (w_hi, w_hi, w_lo) vs A' (a_hi, a_lo, a_hi).
// Fragment mapping (validated R14/15): b0 = B[n][k = q*16 + (lane&3)*2 + {0,1}],
// b1 = same n, k+8. n = g*64 + ni*8 + (lane>>2), ni = 2np + (w>>1).
// ---------------------------------------------------------------------------
__global__ void prep_wimg2(const float* __restrict__ Wih0)
{
    const int s = blockIdx.x;       // 0..48
    const int g = blockIdx.y;       // 0..3
    const int tid = threadIdx.x;    // 0..383
    const int q = tid >> 7;         // 0..2
    const int np = (tid >> 5) & 3;  // 0..3
    const int lane = tid & 31;

    uint32_t* dst = Wimg2 + (size_t)((((s * 4 + g) * 3 + q) * 4 + np) * 32 + lane) * 4;

#pragma unroll
    for (int w = 0; w < 4; w++) {
        const int ni = np * 2 + (w >> 1);
        const int n = g * 64 + ni * 8 + (lane >> 2);
        const int dir = n >> 7, l = (n & 127) >> 2, p = n & 3;
        const int row = dir * 128 + p * 32 + l;
        const int kp0 = q * 16 + (lane & 3) * 2 + (w & 1) * 8;   // k' in 0..47
        uint32_t half_[2];
#pragma unroll
        for (int e = 0; e < 2; e++) {
            const int kp = kp0 + e;
            const int j = kp / 3, r = kp - 3 * j;
            const int k = s * 16 + j;
            float v = (k < 774) ? Wih0[(size_t)row * 774 + k] : 0.0f;
            uint32_t hi, lo;
            bf16split(v, hi, lo);
            half_[e] = (r == 2) ? lo : hi;
        }
        dst[w] = half_[0] | (half_[1] << 16);
    }
}

// ---------------------------------------------------------------------------
// Layer0 gate GEMM on tensor cores. B fragments pre-ordered: one LDS.128
// per (q, ni-pair). A path unchanged from R14/15 (verified).
// ---------------------------------------------------------------------------
__global__ __launch_bounds__(256, 2)
void gemm_mma(const float* __restrict__ Ain, const float* __restrict__ dp_table,
              const int* __restrict__ dp_in)
{
    constexpr int NT = 49;
    constexpr int PITCH = 112;

    __shared__ __align__(16) char As[2][128 * PITCH];        // 28KB
    __shared__ __align__(16) uint32_t Bs[2][3072];           // 24KB (12KB/buf)

    const int tid = threadIdx.x;
    const int t0 = blockIdx.x * 128;
    const int n0g = blockIdx.y * 128;
    const int gBase = (n0g >> 6);   // 0 or 2

    const int wid = tid >> 5, lane = tid & 31;
    const int wm = wid & 3, wn = wid >> 2;
    const int m0 = wm * 32;
    const int n0w = wn * 64;

    const uint32_t aLd = (uint32_t)(m0 + (lane & 15)) * PITCH + (uint32_t)(lane & 16);

    // A loader/converter (unchanged)
    const int m_a = tid >> 1;
    const int half = tid & 1;
    const float* __restrict__ a_base = Ain + (size_t)(t0 + m_a) * 770 + half * 8;
    const int dpo = dp_in[t0 + m_a] * 4;
    const uint32_t aSt = (uint32_t)m_a * PITCH + (uint32_t)half * 48;

    // B loader: linear 12KB copy; thread tid -> 48B at tid*48
    const uint32_t* __restrict__ b_base =
        Wimg2 + (size_t)(gBase) * 1536 + (size_t)tid * 12;

    uint32_t asb[2], bsb[2];
    asb[0] = (uint32_t)__cvta_generic_to_shared(&As[0][0]);
    asb[1] = (uint32_t)__cvta_generic_to_shared(&As[1][0]);
    bsb[0] = (uint32_t)__cvta_generic_to_shared(&Bs[0][0]);
    bsb[1] = (uint32_t)__cvta_generic_to_shared(&Bs[1][0]);
    const uint32_t bSt = (uint32_t)tid * 48;

    // B fragment base (u32 index): ((wn*3 + q)*4 + np)*128 + lane*4
    const uint32_t bFr = (uint32_t)lane * 16;   // byte offset within group

    float ar[8];
    auto loadA = [&](int s) {
        const int k0 = s * 16;
        if (k0 + half * 8 + 8 <= 770) {
            const float* ap = a_base + k0;
#pragma unroll
            for (int j = 0; j < 4; j++) {
                float2 v = *(const float2*)(ap + 2 * j);
                ar[2 * j] = v.x; ar[2 * j + 1] = v.y;
            }
        } else {
#pragma unroll
            for (int j = 0; j < 8; j++) {
                int k = k0 + half * 8 + j;
                float v = 0.0f;
                if (k < 770)      v = Ain[(size_t)(t0 + m_a) * 770 + k];
                else if (k < 774) v = dp_table[dpo + (k - 770)];
                ar[j] = v;
            }
        }
    };
    auto stsA = [&](int buf) {
        uint32_t u[12];
#pragma unroll
        for (int p = 0; p < 4; p++) {
            uint32_t h0, l0, h1, l1;
            bf16split(ar[2 * p],     h0, l0);
            bf16split(ar[2 * p + 1], h1, l1);
            u[3 * p + 0] = h0 | (l0 << 16);
            u[3 * p + 1] = h0 | (h1 << 16);
            u[3 * p + 2] = l1 | (h1 << 16);
        }
        char* row = &As[buf][0] + aSt;
        *(uint4*)(row)      = make_uint4(u[0], u[1], u[2],  u[3]);
        *(uint4*)(row + 16) = make_uint4(u[4], u[5], u[6],  u[7]);
        *(uint4*)(row + 32) = make_uint4(u[8], u[9], u[10], u[11]);
    };
    auto issueB = [&](int s, int buf) {
        const uint32_t* bp = b_base + (size_t)s * 6144;
#pragma unroll
        for (int i = 0; i < 3; i++)
            CP_ASYNC16(bsb[buf] + bSt + i * 16, bp + i * 4);
        CP_COMMIT();
    };

    float acc[2][8][4];
#pragma unroll
    for (int mi = 0; mi < 2; mi++)
#pragma unroll
        for (int ni = 0; ni < 8; ni++)
#pragma unroll
            for (int r = 0; r < 4; r++) acc[mi][ni][r] = 0.0f;

    loadA(0);
    stsA(0);
    issueB(0, 0);
    loadA(1);
    CP_WAIT0();
    __syncthreads();

    for (int s = 0; s < NT; s++) {
        const int buf = s & 1;
        if (s + 1 < NT) issueB(s + 1, buf ^ 1);

#pragma unroll
        for (int q = 0; q < 3; q++) {
            uint32_t bf[8][2];
#pragma unroll
            for (int np = 0; np < 4; np++) {
                uint32_t ba = bsb[buf] + (uint32_t)(((wn * 3 + q) * 4 + np) * 512) + bFr;
                uint4 bw;
                asm volatile("ld.shared.v4.b32 {%0,%1,%2,%3}, [%4];"
                    : "=r"(bw.x), "=r"(bw.y), "=r"(bw.z), "=r"(bw.w) : "r"(ba));
                bf[2 * np][0] = bw.x;     bf[2 * np][1] = bw.y;
                bf[2 * np + 1][0] = bw.z; bf[2 * np + 1][1] = bw.w;
            }
#pragma unroll
            for (int mi = 0; mi < 2; mi++) {
                uint32_t af[4];
                ldmatrix4(af, asb[buf] + aLd + (uint32_t)mi * 16 * PITCH + q * 32);
#pragma unroll
                for (int ni = 0; ni < 8; ni++)
                    mma16816(acc[mi][ni], af, bf[ni]);
            }
        }

        if (s + 1 < NT) {
            stsA(buf ^ 1);
            if (s + 2 < NT) loadA(s + 2);
        }
        CP_WAIT0();
        __syncthreads();
    }

    const int er = lane >> 2;
    const int ec = (lane & 3) * 2;
#pragma unroll
    for (int mi = 0; mi < 2; mi++) {
        const size_t trow = (size_t)(t0 + m0 + mi * 16 + er);
#pragma unroll
        for (int ni = 0; ni < 8; ni++) {
            float* o = GBUF + trow * 256 + n0g + n0w + ni * 8 + ec;
            *(float2*)o = make_float2(acc[mi][ni][0], acc[mi][ni][1]);
            *(float2*)(o + 8 * 256) = make_float2(acc[mi][ni][2], acc[mi][ni][3]);
        }
    }
}

// ---------------------------------------------------------------------------
// Layer1 gate GEMM (FFMA2, verified, unchanged).
// ---------------------------------------------------------------------------
__global__ __launch_bounds__(512)
void gemm_gates1(const float* __restrict__ Ain, const float* __restrict__ Wt)
{
    constexpr int NT = 2;
    constexpr int AROW = 64;

    __shared__ __align__(16) float As[2][32][128];
    __shared__ __align__(16) float Bs[2][32][256];

    const int tid = threadIdx.x;
    const int t0 = blockIdx.x * 128;

    const int wid = tid >> 5, lane = tid & 31;
    const int wm = wid & 3, wn = wid >> 2;
    const int lm = lane & 3, ln = lane >> 2;
    const int m_t = wm * 32 + lm * 8;
    const int n_t = wn * 64 + ln * 8;

    const uint32_t a_off = (uint32_t)m_t * 4;
    const uint32_t b_raw = (uint32_t)n_t * 4;
    const uint32_t b_o0 = swz(b_raw), b_o1 = swz(b_raw + 16);

    const int m_a = tid >> 2;
    const int ha  = (tid & 3) * 8;
    const int lr = tid >> 4;
    const int lc = tid & 15;

    const float* __restrict__ a_base = Ain + (size_t)(t0 + m_a) * AROW + ha;
    const float* __restrict__ b_base = Wt + (size_t)lr * 256 + lc * 4;

    uint32_t b_dst[2];
    b_dst[0] = (uint32_t)__cvta_generic_to_shared(&Bs[0][lr][0]);
    b_dst[1] = (uint32_t)__cvta_generic_to_shared(&Bs[1][lr][0]);
    uint32_t bco[4];
#pragma unroll
    for (int i = 0; i < 4; i++) bco[i] = swz((uint32_t)lc * 16 + i * 256);

    float ar[8];
    auto loadA = [&](int k0) {
        const float* ap = a_base + k0;
#pragma unroll
        for (int j = 0; j < 4; j++) {
            float2 v = *(const float2*)(ap + 2 * j);
            ar[2 * j] = v.x; ar[2 * j + 1] = v.y;
        }
    };
    auto stsA = [&](int buf) {
#pragma unroll
        for (int j = 0; j < 8; j++) As[buf][ha + j][m_a] = ar[j];
    };
    auto issueB = [&](int s, int buf) {
        const float* bp = b_base + (size_t)s * 32 * 256;
#pragma unroll
        for (int i = 0; i < 4; i++)
            CP_ASYNC16(b_dst[buf] + bco[i], bp + i * 64);
        CP_COMMIT();
    };

    u64 acc[8][4];
#pragma unroll
    for (int m = 0; m < 8; m++)
#pragma unroll
        for (int np = 0; np < 4; np++) acc[m][np] = 0ull;

    loadA(0);
    stsA(0);
    issueB(0, 0);
    loadA(32);
    CP_WAIT0();
    __syncthreads();

    for (int s = 0; s < NT; s++) {
        const int buf = s & 1;
        if (s + 1 < NT) issueB(s + 1, buf ^ 1);

#pragma unroll
        for (int kk = 0; kk < 32; kk++) {
            const char* arow = (const char*)&As[buf][kk][0];
            float4 a0 = *(const float4*)(arow + a_off);
            float4 a1 = *(const float4*)(arow + a_off + 16);
            const char* brow = (const char*)&Bs[buf][kk][0];
            ulonglong2 b01 = *(const ulonglong2*)(brow + b_o0);
            ulonglong2 b23 = *(const ulonglong2*)(brow + b_o1);
            u64 bb[4] = {b01.x, b01.y, b23.x, b23.y};
            u64 pa[8];
            pa[0] = pack2(a0.x); pa[1] = pack2(a0.y);
            pa[2] = pack2(a0.z); pa[3] = pack2(a0.w);
            pa[4] = pack2(a1.x); pa[5] = pack2(a1.y);
            pa[6] = pack2(a1.z); pa[7] = pack2(a1.w);
#pragma unroll
            for (int m = 0; m < 8; m++)
#pragma unroll
                for (int np = 0; np < 4; np++)
                    fma2(acc[m][np], pa[m], bb[np]);
        }

        if (s + 1 < NT) stsA(buf ^ 1);
        CP_WAIT0();
        __syncthreads();
    }

#pragma unroll
    for (int m = 0; m < 8; m++) {
        float v[8];
#pragma unroll
        for (int np = 0; np < 4; np++) unpack2(acc[m][np], v[2 * np], v[2 * np + 1]);
        float* orow = GBUF + (size_t)(t0 + m_t + m) * 256 + n_t;
        *(float4*)orow       = make_float4(v[0], v[1], v[2], v[3]);
        *(float4*)(orow + 4) = make_float4(v[4], v[5], v[6], v[7]);
    }
}

// ---------------------------------------------------------------------------
// Chunked LSTM recurrence v3 (R15-verified, unchanged).
// ---------------------------------------------------------------------------
__global__ __launch_bounds__(128)
void lstm_rec(const float* __restrict__ Whh, const float* __restrict__ bias, int layer)
{
    const int wglob = (blockIdx.x * blockDim.x + threadIdx.x) >> 5;
    const int wid   = (threadIdx.x >> 5);
    const int lane  = threadIdx.x & 31;
    const int dir   = wglob & 1;
    const int chunk = wglob >> 1;
    if (chunk >= NCHUNK) return;

    float* hout = layer ? h1_buf : h0_buf;

    u64 wi[16], wf[16], wg[16], wo[16];
    const float* Wd = Whh + dir * 4096;
#pragma unroll
    for (int j = 0; j < 16; j++) {
        wi[j] = pack2f(Wd[(lane)      * 32 + 2 * j], Wd[(lane)      * 32 + 2 * j + 1]);
        wf[j] = pack2f(Wd[(32 + lane) * 32 + 2 * j], Wd[(32 + lane) * 32 + 2 * j + 1]);
        wg[j] = pack2f(Wd[(64 + lane) * 32 + 2 * j], Wd[(64 + lane) * 32 + 2 * j + 1]);
        wo[j] = pack2f(Wd[(96 + lane) * 32 + 2 * j], Wd[(96 + lane) * 32 + 2 * j + 1]);
    }
    const float* bd = bias + dir * 128;
    const float bi  = bd[lane];
    const float bff = bd[32 + lane];
    const float bgg = bd[64 + lane];
    const float boo = bd[96 + lane];

    __shared__ __align__(8) float hs[4][32];

    const int lo = chunk * LCHUNK;
    const int hi = lo + LCHUNK;
    float h = 0.0f, c = 0.0f;

#define REC_STEP(CUR)                                                          \
    {                                                                          \
        __syncwarp();                                                          \
        hs[wid][lane] = h;                                                     \
        __syncwarp();                                                          \
        u64 ai0 = 0, ai1 = 0, af0 = 0, af1 = 0;                                \
        u64 ag0 = 0, ag1 = 0, ao0 = 0, ao1 = 0;                                \
        _Pragma("unroll")                                                      \
        for (int j = 0; j < 16; j += 2) {                                      \
            u64 hp0 = *(const u64*)&hs[wid][2 * j];                            \
            u64 hp1 = *(const u64*)&hs[wid][2 * j + 2];                        \
            fma2(ai0, wi[j], hp0); fma2(ai1, wi[j + 1], hp1);                  \
            fma2(af0, wf[j], hp0); fma2(af1, wf[j + 1], hp1);                  \
            fma2(ag0, wg[j], hp0); fma2(ag1, wg[j + 1], hp1);                  \
            fma2(ao0, wo[j], hp0); fma2(ao1, wo[j + 1], hp1);                  \
        }                                                                      \
        float gin_i, gin_f, gin_g, gin_o;                                      \
        unpack2((CUR).x, gin_i, gin_f);                                        \
        unpack2((CUR).y, gin_g, gin_o);                                        \
        float l0, h0v;                                                         \
        unpack2(add2(ai0, ai1), l0, h0v); float Gi = l0 + h0v + gin_i + bi;    \
        unpack2(add2(af0, af1), l0, h0v); float Gf = l0 + h0v + gin_f + bff;   \
        unpack2(add2(ag0, ag1), l0, h0v); float Gg = l0 + h0v + gin_g + bgg;   \
        unpack2(add2(ao0, ao1), l0, h0v); float Go = l0 + h0v + gin_o + boo;   \
        c = sigf(Gf) * c + sigf(Gi) * tanhfast(Gg);                            \
        h = sigf(Go) * tanhfast(c);                                            \
    }

    if (dir == 0) {
        int tb = lo - WARMUP; if (tb < 0) tb = 0;
        const float* gbase = GBUF + lane * 4;
        ulonglong2 r0 = *(const ulonglong2*)(gbase + (size_t)tb * 256);
        ulonglong2 r1 = *(const ulonglong2*)(gbase + (size_t)(tb + 1) * 256);
        ulonglong2 r2 = *(const ulonglong2*)(gbase + (size_t)(tb + 2) * 256);
        for (int t = tb; t < hi; ++t) {
            ulonglong2 cur = r0; r0 = r1; r1 = r2;
            r2 = *(const ulonglong2*)(gbase + (size_t)(t + 3) * 256);
            REC_STEP(cur);
            if (t >= lo) hout[(size_t)t * 64 + lane] = h;
        }
    } else {
        int tb = hi - 1 + WARMUP; if (tb > T_ - 1) tb = T_ - 1;
        const float* gbase = GBUF + 128 + lane * 4;
        ulonglong2 r0 = *(const ulonglong2*)(gbase + (size_t)tb * 256);
        ulonglong2 r1 = *(const ulonglong2*)(gbase + (size_t)(tb - 1) * 256);
        ulonglong2 r2 = *(const ulonglong2*)(gbase + (size_t)(tb - 2) * 256);
        for (int t = tb; t >= lo; --t) {
            ulonglong2 cur = r0; r0 = r1; r1 = r2;
            r2 = *(const ulonglong2*)(gbase + (size_t)(t - 3 + 8) * 256 - 8 * 256);
            REC_STEP(cur);
            if (t < hi) hout[(size_t)t * 64 + 32 + lane] = h;
        }
    }
#undef REC_STEP
}

// ---------------------------------------------------------------------------
// Output head (verified, unchanged)
// ---------------------------------------------------------------------------
__global__ __launch_bounds__(256)
void out_kernel(const float* __restrict__ Wout, const float* __restrict__ bout,
                const int* __restrict__ mask, float* __restrict__ out)
{
    __shared__ float Ws[64][52];
    const int tid = threadIdx.x;
    for (int i = tid; i < NTAGS * 64; i += 256) {
        int tag = i >> 6, k = i & 63;
        Ws[k][tag] = Wout[i];
    }
    __syncthreads();

    const int lane = tid & 31;
    const int t = blockIdx.x * 8 + (tid >> 5);

    float h0 = h1_buf[(size_t)t * 64 + lane];
    float h1 = h1_buf[(size_t)t * 64 + 32 + lane];

    const bool hasB = (lane < NTAGS - 32);
    float accA = bout[lane];
    float accB = hasB ? bout[lane + 32] : 0.0f;

#pragma unroll
    for (int k = 0; k < 32; k++) {
        float hk = __shfl_sync(0xffffffffu, h0, k);
        accA = fmaf(Ws[k][lane], hk, accA);
        if (hasB) accB = fmaf(Ws[k][lane + 32], hk, accB);
    }
#pragma unroll
    for (int k = 0; k < 32; k++) {
        float hk = __shfl_sync(0xffffffffu, h1, k);
        accA = fmaf(Ws[32 + k][lane], hk, accA);
        if (hasB) accB = fmaf(Ws[32 + k][lane + 32], hk, accB);
    }

    if (lane == 17) accB = (mask[t] > 0) ? fminf(accB, 1.0f) : 1.0f;
    accA = fmaxf(accA, 0.0f);
    accB = fmaxf(accB, 0.0f);

    float vB = hasB ? accB : -1.0f;
    float m = fmaxf(accA, vB);
#pragma unroll
    for (int o = 16; o; o >>= 1) m = fmaxf(m, __shfl_xor_sync(0xffffffffu, m, o));
    float s = __expf(accA - m) + (hasB ? __expf(accB - m) : 0.0f);
#pragma unroll
    for (int o = 16; o; o >>= 1) s += __shfl_xor_sync(0xffffffffu, s, o);
    float inv = __fdividef(1.0f, s);

    out[(size_t)t * NTAGS + lane] = __expf(accA - m) * inv;
    if (hasB) out[(size_t)t * NTAGS + lane + 32] = __expf(accB - m) * inv;
}

// ---------------------------------------------------------------------------

extern "C" void kernel_launch(void* const* d_in, const int* in_sizes, int n_in,
                              void* d_out, int out_size)
{
    const float* input_vecs = (const float*)d_in[0];
    const float* dp_table   = (const float*)d_in[1];
    const float* Wih0       = (const float*)d_in[2];
    const float* Whh0       = (const float*)d_in[3];
    const float* b0         = (const float*)d_in[4];
    const float* Wih1       = (const float*)d_in[5];
    const float* Whh1       = (const float*)d_in[6];
    const float* b1         = (const float*)d_in[7];
    const float* Wout       = (const float*)d_in[8];
    const float* bout       = (const float*)d_in[9];
    const int*   dp_in      = (const int*)d_in[10];
    const int*   mask       = (const int*)d_in[11];
    float* out = (float*)d_out;

    float *pH0, *pWt1;
    cudaGetSymbolAddress((void**)&pH0, h0_buf);
    cudaGetSymbolAddress((void**)&pWt1, Wt1);

    const int rec_blocks = (2 * NCHUNK * 32) / 128;   // 256

    prep_wimg2<<<dim3(49, 4), 384>>>(Wih0);
    prep_w1<<<64, 256>>>(Wih1);
    gemm_mma<<<dim3(T_ / 128, 2), 256>>>(input_vecs, dp_table, dp_in);
    lstm_rec<<<rec_blocks, 128>>>(Whh0, b0, 0);
    gemm_gates1<<<T_ / 128, 512>>>(pH0, pWt1);
    lstm_rec<<<rec_blocks, 128>>>(Whh1, b1, 1);
    out_kernel<<<T_ / 8, 256>>>(Wout, bout, mask, out);
}

// round 17
// speedup vs baseline: 2.2952x; 1.0150x over previous
#include <cuda_runtime.h>
#include <cuda_bf16.h>
#include <cstdint>

#define T_ 32768
#define NTAGS 50
#define LCHUNK 64
#define WARMUP 32
#define NCHUNK (T_ / LCHUNK)

typedef unsigned long long u64;

// Scratch (static device globals; no runtime allocation).
__device__ float g_buf_raw[(size_t)(T_ + 16) * 256];
#define GBUF (g_buf_raw + 8 * 256)
__device__ float h0_buf[(size_t)T_ * 64];   // layer0 output [t][dir*32 + lane]
__device__ float h1_buf[(size_t)T_ * 64];   // layer1 output
__device__ float Wt1[64 * 256];             // k-major permuted Wih1 (layer1 FFMA2 GEMM)
// Layer0 mma weight image in FRAGMENT ORDER:
// [s (49)][g (4: 64-n group)][q (3)][np (4)][lane (32)][w (4 u32)]
__device__ uint32_t Wimg2[49 * 4 * 3 * 4 * 32 * 4];

__device__ __forceinline__ float sigf(float x) {
    return __fdividef(1.0f, 1.0f + __expf(-x));
}
__device__ __forceinline__ float tanhfast(float x) {
    x = fminf(fmaxf(x, -15.0f), 15.0f);
    float e = __expf(2.0f * x);
    return __fdividef(e - 1.0f, e + 1.0f);
}

// packed f32x2 helpers
__device__ __forceinline__ u64 pack2(float x) {
    u64 d; asm("mov.b64 %0, {%1, %1};" : "=l"(d) : "f"(x)); return d;
}
__device__ __forceinline__ u64 pack2f(float lo, float hi) {
    u64 d; asm("mov.b64 %0, {%1, %2};" : "=l"(d) : "f"(lo), "f"(hi)); return d;
}
__device__ __forceinline__ void fma2(u64& acc, u64 a, u64 b) {
    asm("fma.rn.f32x2 %0, %1, %2, %0;" : "+l"(acc) : "l"(a), "l"(b));
}
__device__ __forceinline__ u64 add2(u64 a, u64 b) {
    u64 d; asm("add.rn.f32x2 %0, %1, %2;" : "=l"(d) : "l"(a), "l"(b)); return d;
}
__device__ __forceinline__ void unpack2(u64 d, float& lo, float& hi) {
    asm("mov.b64 {%0, %1}, %2;" : "=f"(lo), "=f"(hi) : "l"(d));
}

// cp.async helpers
#define CP_ASYNC16(dst, src) \
    asm volatile("cp.async.cg.shared.global [%0], [%1], 16;" :: "r"(dst), "l"(src))
#define CP_COMMIT() asm volatile("cp.async.commit_group;" ::: "memory")
#define CP_WAIT0()  asm volatile("cp.async.wait_group 0;" ::: "memory")

// 16B-chunk swizzle: bit7 -> bit4
__device__ __forceinline__ uint32_t swz(uint32_t off) { return off ^ ((off >> 3) & 0x10); }

// bf16 hi/lo split
__device__ __forceinline__ void bf16split(float v, uint32_t& hi, uint32_t& lo) {
    __nv_bfloat16 h = __float2bfloat16(v);
    __nv_bfloat16 l = __float2bfloat16(v - __bfloat162float(h));
    hi = __bfloat16_as_ushort(h);
    lo = __bfloat16_as_ushort(l);
}

// m16n8k16 bf16 mma, f32 accumulate in place
__device__ __forceinline__ void mma16816(float* d, const uint32_t* a, const uint32_t* b) {
    asm volatile(
        "mma.sync.aligned.m16n8k16.row.col.f32.bf16.bf16.f32 "
        "{%0,%1,%2,%3}, {%4,%5,%6,%7}, {%8,%9}, {%0,%1,%2,%3};"
        : "+f"(d[0]), "+f"(d[1]), "+f"(d[2]), "+f"(d[3])
        : "r"(a[0]), "r"(a[1]), "r"(a[2]), "r"(a[3]), "r"(b[0]), "r"(b[1]));
}
__device__ __forceinline__ void ldmatrix4(uint32_t* r, uint32_t saddr) {
    asm volatile("ldmatrix.sync.aligned.m8n8.x4.shared.b16 {%0,%1,%2,%3}, [%4];"
        : "=r"(r[0]), "=r"(r[1]), "=r"(r[2]), "=r"(r[3]) : "r"(saddr));
}

// ---------------------------------------------------------------------------
// Prep A: layer1 weights k-major permuted.
// ---------------------------------------------------------------------------
__global__ void prep_w1(const float* __restrict__ Wih1)
{
    const int k = blockIdx.x;
    const int n = threadIdx.x;
    const int dir = n >> 7, l = (n & 127) >> 2, p = n & 3;
    const int row = dir * 128 + p * 32 + l;
    Wt1[k * 256 + n] = Wih1[(size_t)row * 64 + k];
}

// ---------------------------------------------------------------------------
// Prep B: fragment-ordered layer0 mma weight image (R16-verified).
// ---------------------------------------------------------------------------
__global__ void prep_wimg2(const float* __restrict__ Wih0)
{
    const int s = blockIdx.x;
    const int g = blockIdx.y;
    const int tid = threadIdx.x;
    const int q = tid >> 7;
    const int np = (tid >> 5) & 3;
    const int lane = tid & 31;

    uint32_t* dst = Wimg2 + (size_t)((((s * 4 + g) * 3 + q) * 4 + np) * 32 + lane) * 4;

#pragma unroll
    for (int w = 0; w < 4; w++) {
        const int ni = np * 2 + (w >> 1);
        const int n = g * 64 + ni * 8 + (lane >> 2);
        const int dir = n >> 7, l = (n & 127) >> 2, p = n & 3;
        const int row = dir * 128 + p * 32 + l;
        const int kp0 = q * 16 + (lane & 3) * 2 + (w & 1) * 8;
        uint32_t half_[2];
#pragma unroll
        for (int e = 0; e < 2; e++) {
            const int kp = kp0 + e;
            const int j = kp / 3, r = kp - 3 * j;
            const int k = s * 16 + j;
            float v = (k < 774) ? Wih0[(size_t)row * 774 + k] : 0.0f;
            uint32_t hi, lo;
            bf16split(v, hi, lo);
            half_[e] = (r == 2) ? lo : hi;
        }
        dst[w] = half_[0] | (half_[1] << 16);
    }
}

// ---------------------------------------------------------------------------
// Layer0 gate GEMM v3: 512 threads, tile 128t x 256n (full n), dynamic smem.
// Threads 0-255: A LDG->convert->STS (verified path). Threads 256-511: B
// cp.async copy (96B each per stage, full 24KB stage image).
// Warps 4m x 4n; fragment math identical to R16.
// Dynamic smem: A 2 x 14336B at [0, 28672); B 2 x 24576B at [28672, 77824).
// ---------------------------------------------------------------------------
#define SMEM_MMA 77824
__global__ __launch_bounds__(512)
void gemm_mma(const float* __restrict__ Ain, const float* __restrict__ dp_table,
              const int* __restrict__ dp_in)
{
    constexpr int NT = 49;
    constexpr int PITCH = 112;
    extern __shared__ __align__(16) char dsm[];
    char* Asm = dsm;                       // 2 x 128*112
    uint32_t* Bsm = (uint32_t*)(dsm + 28672);  // 2 x 6144 u32

    const int tid = threadIdx.x;
    const int t0 = blockIdx.x * 128;

    const int wid = tid >> 5, lane = tid & 31;
    const int wm = wid & 3, wn = wid >> 2;     // 4m x 4n
    const int m0 = wm * 32;
    const int n0w = wn * 64;

    const uint32_t aLd = (uint32_t)(m0 + (lane & 15)) * PITCH + (uint32_t)(lane & 16);

    // A loader (tid < 256)
    const int m_a = (tid & 255) >> 1;
    const int half = tid & 1;
    const float* __restrict__ a_base = Ain + (size_t)(t0 + m_a) * 770 + half * 8;
    int dpo = 0;
    if (tid < 256) dpo = dp_in[t0 + m_a] * 4;
    const uint32_t aSt = (uint32_t)m_a * PITCH + (uint32_t)half * 48;

    // B loader (tid >= 256): 96B per thread per stage
    const int tb = tid & 255;
    const uint32_t* __restrict__ b_base = Wimg2 + (size_t)tb * 24;

    uint32_t asb[2], bsb[2];
    asb[0] = (uint32_t)__cvta_generic_to_shared(Asm);
    asb[1] = asb[0] + 14336;
    bsb[0] = (uint32_t)__cvta_generic_to_shared(Bsm);
    bsb[1] = bsb[0] + 24576;
    const uint32_t bSt = (uint32_t)tb * 96;
    const uint32_t bFr = (uint32_t)lane * 16;

    float ar[8];
    auto loadA = [&](int s) {
        const int k0 = s * 16;
        if (k0 + half * 8 + 8 <= 770) {
            const float* ap = a_base + k0;
#pragma unroll
            for (int j = 0; j < 4; j++) {
                float2 v = *(const float2*)(ap + 2 * j);
                ar[2 * j] = v.x; ar[2 * j + 1] = v.y;
            }
        } else {
#pragma unroll
            for (int j = 0; j < 8; j++) {
                int k = k0 + half * 8 + j;
                float v = 0.0f;
                if (k < 770)      v = Ain[(size_t)(t0 + m_a) * 770 + k];
                else if (k < 774) v = dp_table[dpo + (k - 770)];
                ar[j] = v;
            }
        }
    };
    auto stsA = [&](int buf) {
        uint32_t u[12];
#pragma unroll
        for (int p = 0; p < 4; p++) {
            uint32_t h0, l0, h1, l1;
            bf16split(ar[2 * p],     h0, l0);
            bf16split(ar[2 * p + 1], h1, l1);
            u[3 * p + 0] = h0 | (l0 << 16);
            u[3 * p + 1] = h0 | (h1 << 16);
            u[3 * p + 2] = l1 | (h1 << 16);
        }
        char* row = Asm + buf * 14336 + aSt;
        *(uint4*)(row)      = make_uint4(u[0], u[1], u[2],  u[3]);
        *(uint4*)(row + 16) = make_uint4(u[4], u[5], u[6],  u[7]);
        *(uint4*)(row + 32) = make_uint4(u[8], u[9], u[10], u[11]);
    };
    auto issueB = [&](int s, int buf) {
        const uint32_t* bp = b_base + (size_t)s * 6144;
#pragma unroll
        for (int i = 0; i < 6; i++)
            CP_ASYNC16(bsb[buf] + bSt + i * 16, bp + i * 4);
        CP_COMMIT();
    };

    float acc[2][8][4];
#pragma unroll
    for (int mi = 0; mi < 2; mi++)
#pragma unroll
        for (int ni = 0; ni < 8; ni++)
#pragma unroll
            for (int r = 0; r < 4; r++) acc[mi][ni][r] = 0.0f;

    // prologue
    if (tid < 256) { loadA(0); stsA(0); loadA(1); }
    else           { issueB(0, 0); }
    CP_WAIT0();
    __syncthreads();

    for (int s = 0; s < NT; s++) {
        const int buf = s & 1;
        if (tid >= 256 && s + 1 < NT) issueB(s + 1, buf ^ 1);

#pragma unroll
        for (int q = 0; q < 3; q++) {
            uint32_t bf[8][2];
#pragma unroll
            for (int np = 0; np < 4; np++) {
                uint32_t ba = bsb[buf] + (uint32_t)(((wn * 3 + q) * 4 + np) * 512) + bFr;
                uint4 bw;
                asm volatile("ld.shared.v4.b32 {%0,%1,%2,%3}, [%4];"
                    : "=r"(bw.x), "=r"(bw.y), "=r"(bw.z), "=r"(bw.w) : "r"(ba));
                bf[2 * np][0] = bw.x;     bf[2 * np][1] = bw.y;
                bf[2 * np + 1][0] = bw.z; bf[2 * np + 1][1] = bw.w;
            }
#pragma unroll
            for (int mi = 0; mi < 2; mi++) {
                uint32_t af[4];
                ldmatrix4(af, asb[buf] + aLd + (uint32_t)mi * 16 * PITCH + q * 32);
#pragma unroll
                for (int ni = 0; ni < 8; ni++)
                    mma16816(acc[mi][ni], af, bf[ni]);
            }
        }

        if (tid < 256 && s + 1 < NT) {
            stsA(buf ^ 1);
            if (s + 2 < NT) loadA(s + 2);
        }
        CP_WAIT0();
        __syncthreads();
    }

    const int er = lane >> 2;
    const int ec = (lane & 3) * 2;
#pragma unroll
    for (int mi = 0; mi < 2; mi++) {
        const size_t trow = (size_t)(t0 + m0 + mi * 16 + er);
#pragma unroll
        for (int ni = 0; ni < 8; ni++) {
            float* o = GBUF + trow * 256 + n0w + ni * 8 + ec;
            *(float2*)o = make_float2(acc[mi][ni][0], acc[mi][ni][1]);
            *(float2*)(o + 8 * 256) = make_float2(acc[mi][ni][2], acc[mi][ni][3]);
        }
    }
}

// ---------------------------------------------------------------------------
// Layer1 gate GEMM (FFMA2, verified, unchanged).
// ---------------------------------------------------------------------------
__global__ __launch_bounds__(512)
void gemm_gates1(const float* __restrict__ Ain, const float* __restrict__ Wt)
{
    constexpr int NT = 2;
    constexpr int AROW = 64;

    __shared__ __align__(16) float As[2][32][128];
    __shared__ __align__(16) float Bs[2][32][256];

    const int tid = threadIdx.x;
    const int t0 = blockIdx.x * 128;

    const int wid = tid >> 5, lane = tid & 31;
    const int wm = wid & 3, wn = wid >> 2;
    const int lm = lane & 3, ln = lane >> 2;
    const int m_t = wm * 32 + lm * 8;
    const int n_t = wn * 64 + ln * 8;

    const uint32_t a_off = (uint32_t)m_t * 4;
    const uint32_t b_raw = (uint32_t)n_t * 4;
    const uint32_t b_o0 = swz(b_raw), b_o1 = swz(b_raw + 16);

    const int m_a = tid >> 2;
    const int ha  = (tid & 3) * 8;
    const int lr = tid >> 4;
    const int lc = tid & 15;

    const float* __restrict__ a_base = Ain + (size_t)(t0 + m_a) * AROW + ha;
    const float* __restrict__ b_base = Wt + (size_t)lr * 256 + lc * 4;

    uint32_t b_dst[2];
    b_dst[0] = (uint32_t)__cvta_generic_to_shared(&Bs[0][lr][0]);
    b_dst[1] = (uint32_t)__cvta_generic_to_shared(&Bs[1][lr][0]);
    uint32_t bco[4];
#pragma unroll
    for (int i = 0; i < 4; i++) bco[i] = swz((uint32_t)lc * 16 + i * 256);

    float ar[8];
    auto loadA = [&](int k0) {
        const float* ap = a_base + k0;
#pragma unroll
        for (int j = 0; j < 4; j++) {
            float2 v = *(const float2*)(ap + 2 * j);
            ar[2 * j] = v.x; ar[2 * j + 1] = v.y;
        }
    };
    auto stsA = [&](int buf) {
#pragma unroll
        for (int j = 0; j < 8; j++) As[buf][ha + j][m_a] = ar[j];
    };
    auto issueB = [&](int s, int buf) {
        const float* bp = b_base + (size_t)s * 32 * 256;
#pragma unroll
        for (int i = 0; i < 4; i++)
            CP_ASYNC16(b_dst[buf] + bco[i], bp + i * 64);
        CP_COMMIT();
    };

    u64 acc[8][4];
#pragma unroll
    for (int m = 0; m < 8; m++)
#pragma unroll
        for (int np = 0; np < 4; np++) acc[m][np] = 0ull;

    loadA(0);
    stsA(0);
    issueB(0, 0);
    loadA(32);
    CP_WAIT0();
    __syncthreads();

    for (int s = 0; s < NT; s++) {
        const int buf = s & 1;
        if (s + 1 < NT) issueB(s + 1, buf ^ 1);

#pragma unroll
        for (int kk = 0; kk < 32; kk++) {
            const char* arow = (const char*)&As[buf][kk][0];
            float4 a0 = *(const float4*)(arow + a_off);
            float4 a1 = *(const float4*)(arow + a_off + 16);
            const char* brow = (const char*)&Bs[buf][kk][0];
            ulonglong2 b01 = *(const ulonglong2*)(brow + b_o0);
            ulonglong2 b23 = *(const ulonglong2*)(brow + b_o1);
            u64 bb[4] = {b01.x, b01.y, b23.x, b23.y};
            u64 pa[8];
            pa[0] = pack2(a0.x); pa[1] = pack2(a0.y);
            pa[2] = pack2(a0.z); pa[3] = pack2(a0.w);
            pa[4] = pack2(a1.x); pa[5] = pack2(a1.y);
            pa[6] = pack2(a1.z); pa[7] = pack2(a1.w);
#pragma unroll
            for (int m = 0; m < 8; m++)
#pragma unroll
                for (int np = 0; np < 4; np++)
                    fma2(acc[m][np], pa[m], bb[np]);
        }

        if (s + 1 < NT) stsA(buf ^ 1);
        CP_WAIT0();
        __syncthreads();
    }

#pragma unroll
    for (int m = 0; m < 8; m++) {
        float v[8];
#pragma unroll
        for (int np = 0; np < 4; np++) unpack2(acc[m][np], v[2 * np], v[2 * np + 1]);
        float* orow = GBUF + (size_t)(t0 + m_t + m) * 256 + n_t;
        *(float4*)orow       = make_float4(v[0], v[1], v[2], v[3]);
        *(float4*)(orow + 4) = make_float4(v[4], v[5], v[6], v[7]);
    }
}

// ---------------------------------------------------------------------------
// Chunked LSTM recurrence v3 (R15/16-verified; WARMUP 48->32 only change).
// ---------------------------------------------------------------------------
__global__ __launch_bounds__(128)
void lstm_rec(const float* __restrict__ Whh, const float* __restrict__ bias, int layer)
{
    const int wglob = (blockIdx.x * blockDim.x + threadIdx.x) >> 5;
    const int wid   = (threadIdx.x >> 5);
    const int lane  = threadIdx.x & 31;
    const int dir   = wglob & 1;
    const int chunk = wglob >> 1;
    if (chunk >= NCHUNK) return;

    float* hout = layer ? h1_buf : h0_buf;

    u64 wi[16], wf[16], wg[16], wo[16];
    const float* Wd = Whh + dir * 4096;
#pragma unroll
    for (int j = 0; j < 16; j++) {
        wi[j] = pack2f(Wd[(lane)      * 32 + 2 * j], Wd[(lane)      * 32 + 2 * j + 1]);
        wf[j] = pack2f(Wd[(32 + lane) * 32 + 2 * j], Wd[(32 + lane) * 32 + 2 * j + 1]);
        wg[j] = pack2f(Wd[(64 + lane) * 32 + 2 * j], Wd[(64 + lane) * 32 + 2 * j + 1]);
        wo[j] = pack2f(Wd[(96 + lane) * 32 + 2 * j], Wd[(96 + lane) * 32 + 2 * j + 1]);
    }
    const float* bd = bias + dir * 128;
    const float bi  = bd[lane];
    const float bff = bd[32 + lane];
    const float bgg = bd[64 + lane];
    const float boo = bd[96 + lane];

    __shared__ __align__(8) float hs[4][32];

    const int lo = chunk * LCHUNK;
    const int hi = lo + LCHUNK;
    float h = 0.0f, c = 0.0f;

#define REC_STEP(CUR)                                                          \
    {                                                                          \
        __syncwarp();                                                          \
        hs[wid][lane] = h;                                                     \
        __syncwarp();                                                          \
        u64 ai0 = 0, ai1 = 0, af0 = 0, af1 = 0;                                \
        u64 ag0 = 0, ag1 = 0, ao0 = 0, ao1 = 0;                                \
        _Pragma("unroll")                                                      \
        for (int j = 0; j < 16; j += 2) {                                      \
            u64 hp0 = *(const u64*)&hs[wid][2 * j];                            \
            u64 hp1 = *(const u64*)&hs[wid][2 * j + 2];                        \
            fma2(ai0, wi[j], hp0); fma2(ai1, wi[j + 1], hp1);                  \
            fma2(af0, wf[j], hp0); fma2(af1, wf[j + 1], hp1);                  \
            fma2(ag0, wg[j], hp0); fma2(ag1, wg[j + 1], hp1);                  \
            fma2(ao0, wo[j], hp0); fma2(ao1, wo[j + 1], hp1);                  \
        }                                                                      \
        float gin_i, gin_f, gin_g, gin_o;                                      \
        unpack2((CUR).x, gin_i, gin_f);                                        \
        unpack2((CUR).y, gin_g, gin_o);                                        \
        float l0, h0v;                                                         \
        unpack2(add2(ai0, ai1), l0, h0v); float Gi = l0 + h0v + gin_i + bi;    \
        unpack2(add2(af0, af1), l0, h0v); float Gf = l0 + h0v + gin_f + bff;   \
        unpack2(add2(ag0, ag1), l0, h0v); float Gg = l0 + h0v + gin_g + bgg;   \
        unpack2(add2(ao0, ao1), l0, h0v); float Go = l0 + h0v + gin_o + boo;   \
        c = sigf(Gf) * c + sigf(Gi) * tanhfast(Gg);                            \
        h = sigf(Go) * tanhfast(c);                                            \
    }

    if (dir == 0) {
        int tb = lo - WARMUP; if (tb < 0) tb = 0;
        const float* gbase = GBUF + lane * 4;
        ulonglong2 r0 = *(const ulonglong2*)(gbase + (size_t)tb * 256);
        ulonglong2 r1 = *(const ulonglong2*)(gbase + (size_t)(tb + 1) * 256);
        ulonglong2 r2 = *(const ulonglong2*)(gbase + (size_t)(tb + 2) * 256);
        for (int t = tb; t < hi; ++t) {
            ulonglong2 cur = r0; r0 = r1; r1 = r2;
            r2 = *(const ulonglong2*)(gbase + (size_t)(t + 3) * 256);
            REC_STEP(cur);
            if (t >= lo) hout[(size_t)t * 64 + lane] = h;
        }
    } else {
        int tb = hi - 1 + WARMUP; if (tb > T_ - 1) tb = T_ - 1;
        const float* gbase = GBUF + 128 + lane * 4;
        ulonglong2 r0 = *(const ulonglong2*)(gbase + (size_t)tb * 256);
        ulonglong2 r1 = *(const ulonglong2*)(gbase + (size_t)(tb - 1) * 256);
        ulonglong2 r2 = *(const ulonglong2*)(gbase + (size_t)(tb - 2) * 256);
        for (int t = tb; t >= lo; --t) {
            ulonglong2 cur = r0; r0 = r1; r1 = r2;
            r2 = *(const ulonglong2*)(gbase + (size_t)(t - 3 + 8) * 256 - 8 * 256);
            REC_STEP(cur);
            if (t < hi) hout[(size_t)t * 64 + 32 + lane] = h;
        }
    }
#undef REC_STEP
}

// ---------------------------------------------------------------------------
// Output head (verified, unchanged)
// ---------------------------------------------------------------------------
__global__ __launch_bounds__(256)
void out_kernel(const float* __restrict__ Wout, const float* __restrict__ bout,
                const int* __restrict__ mask, float* __restrict__ out)
{
    __shared__ float Ws[64][52];
    const int tid = threadIdx.x;
    for (int i = tid; i < NTAGS * 64; i += 256) {
        int tag = i >> 6, k = i & 63;
        Ws[k][tag] = Wout[i];
    }
    __syncthreads();

    const int lane = tid & 31;
    const int t = blockIdx.x * 8 + (tid >> 5);

    float h0 = h1_buf[(size_t)t * 64 + lane];
    float h1 = h1_buf[(size_t)t * 64 + 32 + lane];

    const bool hasB = (lane < NTAGS - 32);
    float accA = bout[lane];
    float accB = hasB ? bout[lane + 32] : 0.0f;

#pragma unroll
    for (int k = 0; k < 32; k++) {
        float hk = __shfl_sync(0xffffffffu, h0, k);
        accA = fmaf(Ws[k][lane], hk, accA);
        if (hasB) accB = fmaf(Ws[k][lane + 32], hk, accB);
    }
#pragma unroll
    for (int k = 0; k < 32; k++) {
        float hk = __shfl_sync(0xffffffffu, h1, k);
        accA = fmaf(Ws[32 + k][lane], hk, accA);
        if (hasB) accB = fmaf(Ws[32 + k][lane + 32], hk, accB);
    }

    if (lane == 17) accB = (mask[t] > 0) ? fminf(accB, 1.0f) : 1.0f;
    accA = fmaxf(accA, 0.0f);
    accB = fmaxf(accB, 0.0f);

    float vB = hasB ? accB : -1.0f;
    float m = fmaxf(accA, vB);
#pragma unroll
    for (int o = 16; o; o >>= 1) m = fmaxf(m, __shfl_xor_sync(0xffffffffu, m, o));
    float s = __expf(accA - m) + (hasB ? __expf(accB - m) : 0.0f);
#pragma unroll
    for (int o = 16; o; o >>= 1) s += __shfl_xor_sync(0xffffffffu, s, o);
    float inv = __fdividef(1.0f, s);

    out[(size_t)t * NTAGS + lane] = __expf(accA - m) * inv;
    if (hasB) out[(size_t)t * NTAGS + lane + 32] = __expf(accB - m) * inv;
}

// ---------------------------------------------------------------------------

extern "C" void kernel_launch(void* const* d_in, const int* in_sizes, int n_in,
                              void* d_out, int out_size)
{
    const float* input_vecs = (const float*)d_in[0];
    const float* dp_table   = (const float*)d_in[1];
    const float* Wih0       = (const float*)d_in[2];
    const float* Whh0       = (const float*)d_in[3];
    const float* b0         = (const float*)d_in[4];
    const float* Wih1       = (const float*)d_in[5];
    const float* Whh1       = (const float*)d_in[6];
    const float* b1         = (const float*)d_in[7];
    const float* Wout       = (const float*)d_in[8];
    const float* bout       = (const float*)d_in[9];
    const int*   dp_in      = (const int*)d_in[10];
    const int*   mask       = (const int*)d_in[11];
    float* out = (float*)d_out;

    float *pH0, *pWt1;
    cudaGetSymbolAddress((void**)&pH0, h0_buf);
    cudaGetSymbolAddress((void**)&pWt1, Wt1);

    static int smem_set = 0;
    if (!smem_set) {
        cudaFuncSetAttribute(gemm_mma, cudaFuncAttributeMaxDynamicSharedMemorySize, SMEM_MMA);
        smem_set = 1;
    }

    const int rec_blocks = (2 * NCHUNK * 32) / 128;   // 256

    prep_wimg2<<<dim3(49, 4), 384>>>(Wih0);
    prep_w1<<<64, 256>>>(Wih1);
    gemm_mma<<<T_ / 128, 512, SMEM_MMA>>>(input_vecs, dp_table, dp_in);
    lstm_rec<<<rec_blocks, 128>>>(Whh0, b0, 0);
    gemm_gates1<<<T_ / 128, 512>>>(pH0, pWt1);
    lstm_rec<<<rec_blocks, 128>>>(Whh1, b1, 1);
    out_kernel<<<T_ / 8, 256>>>(Wout, bout, mask, out);
}